// round 8
// baseline (speedup 1.0000x reference)
#include <cuda_runtime.h>
#include <cuda_bf16.h>
#include <math.h>

// ---------------- problem constants ----------------
constexpr int Nn  = 50000;
constexpr int Ee  = 800000;
constexpr int ET  = Ee + Nn;      // + self loops
constexpr int RNA = 645;
constexpr int SSd = 6;
constexpr int Fin = RNA + SSd;    // 651
constexpr int H   = 128;
constexpr int G   = 200;
constexpr float EPS = 1e-5f;

constexpr int BUF_STRIDE = 132;
constexpr int DYN_SMEM   = 128 * BUF_STRIDE * 4;   // 67584 B (tail only)

// ---------------- device scratch ----------------
__device__ float g_h    [Nn * H];
__device__ float g_xw   [Nn * H];
__device__ float g_y    [Nn * H];
__device__ float g_h1   [Nn * H];
__device__ float g_h2   [Nn * H];
__device__ float g_as   [Nn];
__device__ float g_ad   [Nn];
__device__ int   g_deg  [Nn];
__device__ int   g_fill [Nn];
__device__ int   g_rowptr[Nn + 1];
__device__ int   g_csrc [ET];
__device__ int   g_bsum [256];
__device__ float g_gsum [G * H];
__device__ float g_gsq  [G * H];
__device__ float g_kA   [G * H];
__device__ float g_kB   [G * H];
__device__ int   g_cnt  [G];

// ---------------- small utility kernels ----------------
__global__ void k_zero2_f(float* p1, float* p2, int n) {
    int i = blockIdx.x * blockDim.x + threadIdx.x;
    if (i < n) { p1[i] = 0.f; p2[i] = 0.f; }
}
__global__ void k_zero_all(int* deg, int* fill, int* cnt) {
    int i = blockIdx.x * blockDim.x + threadIdx.x;
    if (i < Nn) { deg[i] = 0; fill[i] = 0; }
    if (i < G) cnt[i] = 0;
}

// ---------------- CSR build ----------------
__global__ void k_hist(const int* __restrict__ ei, int* __restrict__ deg) {
    int i = blockIdx.x * blockDim.x + threadIdx.x;
    if (i >= ET) return;
    int dst = (i < Ee) ? ei[Ee + i] : (i - Ee);
    atomicAdd(&deg[dst], 1);
}

__global__ void k_scan1(const int* __restrict__ deg, int* __restrict__ rowptr,
                        int* __restrict__ bsum) {
    __shared__ int sm[256];
    int tx = threadIdx.x;
    int i = blockIdx.x * 256 + tx;
    int v = (i < Nn) ? deg[i] : 0;
    sm[tx] = v;
    __syncthreads();
    for (int off = 1; off < 256; off <<= 1) {
        int t = (tx >= off) ? sm[tx - off] : 0;
        __syncthreads();
        sm[tx] += t;
        __syncthreads();
    }
    if (i < Nn) rowptr[i] = sm[tx] - v;
    if (tx == 255) bsum[blockIdx.x] = sm[255];
}

__global__ void k_scan2(int* __restrict__ bsum, int nblk) {
    __shared__ int sm[256];
    int tx = threadIdx.x;
    int v = (tx < nblk) ? bsum[tx] : 0;
    sm[tx] = v;
    __syncthreads();
    for (int off = 1; off < 256; off <<= 1) {
        int t = (tx >= off) ? sm[tx - off] : 0;
        __syncthreads();
        sm[tx] += t;
        __syncthreads();
    }
    if (tx < nblk) bsum[tx] = sm[tx] - v;
}

__global__ void k_scan3(int* __restrict__ rowptr, const int* __restrict__ bsum) {
    int i = blockIdx.x * blockDim.x + threadIdx.x;
    if (i < Nn) rowptr[i] += bsum[i >> 8];
    if (i == 0) rowptr[Nn] = ET;
}

__global__ void k_scatter(const int* __restrict__ ei, const int* __restrict__ rowptr,
                          int* __restrict__ fill, int* __restrict__ csrc) {
    int i = blockIdx.x * blockDim.x + threadIdx.x;
    if (i >= ET) return;
    int src = (i < Ee) ? ei[i]      : (i - Ee);
    int dst = (i < Ee) ? ei[Ee + i] : (i - Ee);
    int pos = rowptr[dst] + atomicAdd(&fill[dst], 1);
    csrc[pos] = src;
}

__global__ void k_gcount(const int* __restrict__ batch, int* __restrict__ cnt) {
    int i = blockIdx.x * blockDim.x + threadIdx.x;
    if (i < Nn) atomicAdd(&cnt[batch[i]], 1);
}

// ---------------- bf16 mma helpers ----------------
__device__ __forceinline__ void mma_bf16(float* c, const unsigned* a, const unsigned* b) {
    asm volatile(
        "mma.sync.aligned.m16n8k16.row.col.f32.bf16.bf16.f32 "
        "{%0,%1,%2,%3}, {%4,%5,%6,%7}, {%8,%9}, {%0,%1,%2,%3};"
        : "+f"(c[0]), "+f"(c[1]), "+f"(c[2]), "+f"(c[3])
        : "r"(a[0]), "r"(a[1]), "r"(a[2]), "r"(a[3]), "r"(b[0]), "r"(b[1]));
}
__device__ __forceinline__ unsigned pack_bf16x2(float x0, float x1) {
    unsigned p;
    asm("cvt.rn.bf16x2.f32 %0, %1, %2;" : "=r"(p) : "f"(x1), "f"(x0));
    return p;
}
__device__ __forceinline__ void split_pair(float x0, float x1, unsigned& ph, unsigned& pl) {
    ph = pack_bf16x2(x0, x1);
    float h0 = __uint_as_float(ph << 16);
    float h1 = __uint_as_float(ph & 0xffff0000u);
    pl = pack_bf16x2(x0 - h0, x1 - h1);
}

constexpr int KW = 20;   // smem plane words per row (16 data + 4 pad)

// ---------------- tensor-core GEMM (bf16 x3 split) ----------------
// EPI 2: write C=xw, plus row dots with p1 (att_src) / p2 (att_dst) -> as_/ad_
// EPI 3: row-LN(p1=g, p2=b) + ReLU in-register -> C
template <int EPI, bool SCALAR_A>
__global__ void __launch_bounds__(256, 2)
k_mma(const float* __restrict__ A0, int K0,
      const float* __restrict__ A1,
      const float* __restrict__ B,
      const float* __restrict__ bias,
      float* __restrict__ C, int M, int Ktot, int Ncols,
      const float* __restrict__ p1, const float* __restrict__ p2,
      float* __restrict__ as_, float* __restrict__ ad_) {
    constexpr int BM = 128, BN = 128, BK = 32;
    constexpr int AELT = 16, BELT = 16;

    __shared__ unsigned AsH[BM * KW], AsL[BM * KW];
    __shared__ unsigned BsH[BN * KW], BsL[BN * KW];
    __shared__ float rb1[128 * 4], rb2[128 * 4];

    const int tid  = threadIdx.x;
    const int wid  = tid >> 5;
    const int lane = tid & 31;
    const int wr   = wid >> 2;
    const int wc   = wid & 3;
    const int rowBase = blockIdx.x * BM;
    const int K1 = Ktot - K0;

    const int ar = tid >> 1, ac = (tid & 1) * 16;
    const int am = rowBase + ar;
    const int bn  = tid & 127;
    const int bk0 = (tid >> 7) * 16;

    float aReg[AELT], bReg[BELT];
    float acc[4][4][4];
#pragma unroll
    for (int a = 0; a < 4; ++a)
#pragma unroll
        for (int b = 0; b < 4; ++b)
#pragma unroll
            for (int cc = 0; cc < 4; ++cc) acc[a][b][cc] = 0.f;

    const int T = (Ktot + BK - 1) / BK;

    auto gload = [&](int t) {
        const int k0 = t * BK;
        if (SCALAR_A) {
#pragma unroll
            for (int j = 0; j < AELT; ++j) {
                int k = k0 + ac + j;
                float v = 0.f;
                if (am < M && k < Ktot)
                    v = (k < K0) ? A0[(size_t)am * K0 + k]
                                 : A1[(size_t)am * K1 + (k - K0)];
                aReg[j] = v;
            }
        } else {
#pragma unroll
            for (int j4 = 0; j4 < AELT / 4; ++j4) {
                int k = k0 + ac + j4 * 4;
                float4 v = make_float4(0.f, 0.f, 0.f, 0.f);
                if (am < M) {
                    const float* p = (k < K0) ? (A0 + (size_t)am * K0 + k)
                                              : (A1 + (size_t)am * K1 + (k - K0));
                    v = *reinterpret_cast<const float4*>(p);
                }
                aReg[j4 * 4 + 0] = v.x; aReg[j4 * 4 + 1] = v.y;
                aReg[j4 * 4 + 2] = v.z; aReg[j4 * 4 + 3] = v.w;
            }
        }
#pragma unroll
        for (int j = 0; j < BELT; ++j) {
            int k = k0 + bk0 + j;
            bReg[j] = (k < Ktot) ? B[(size_t)k * Ncols + bn] : 0.f;
        }
    };

    auto convert = [&]() {
#pragma unroll
        for (int j = 0; j < AELT; j += 2) {
            unsigned ph, pl;
            split_pair(aReg[j], aReg[j + 1], ph, pl);
            int wi = ar * KW + ((ac + j) >> 1);
            AsH[wi] = ph; AsL[wi] = pl;
        }
#pragma unroll
        for (int j = 0; j < BELT; j += 2) {
            unsigned ph, pl;
            split_pair(bReg[j], bReg[j + 1], ph, pl);
            int wi = bn * KW + ((bk0 + j) >> 1);
            BsH[wi] = ph; BsL[wi] = pl;
        }
    };

    // pipeline: regs not live across the mma phase
    gload(0);
    for (int t = 0; t < T; ++t) {
        __syncthreads();      // planes free (prev mma done)
        convert();
        __syncthreads();      // planes ready

#pragma unroll
        for (int ks = 0; ks < 2; ++ks) {
            unsigned bh[4][2], bl[4][2];
#pragma unroll
            for (int nt = 0; nt < 4; ++nt) {
                int n  = wc * 32 + nt * 8 + (lane >> 2);
                int kw = ks * 8 + (lane & 3);
                bh[nt][0] = BsH[n * KW + kw];     bl[nt][0] = BsL[n * KW + kw];
                bh[nt][1] = BsH[n * KW + kw + 4]; bl[nt][1] = BsL[n * KW + kw + 4];
            }
#pragma unroll
            for (int mt = 0; mt < 4; ++mt) {
                int r  = wr * 64 + mt * 16 + (lane >> 2);
                int kw = ks * 8 + (lane & 3);
                unsigned ah[4], al[4];
                ah[0] = AsH[r * KW + kw];           al[0] = AsL[r * KW + kw];
                ah[1] = AsH[(r + 8) * KW + kw];     al[1] = AsL[(r + 8) * KW + kw];
                ah[2] = AsH[r * KW + kw + 4];       al[2] = AsL[r * KW + kw + 4];
                ah[3] = AsH[(r + 8) * KW + kw + 4]; al[3] = AsL[(r + 8) * KW + kw + 4];
#pragma unroll
                for (int nt = 0; nt < 4; ++nt) {
                    mma_bf16(acc[mt][nt], ah, bh[nt]);
                    mma_bf16(acc[mt][nt], ah, bl[nt]);
                    mma_bf16(acc[mt][nt], al, bh[nt]);
                }
            }
        }
        if (t + 1 < T) gload(t + 1);
    }

    if (EPI == 2) {
        // preload att values for this thread's columns
        float aS[4][2], aD[4][2];
#pragma unroll
        for (int nt = 0; nt < 4; ++nt) {
            int c = wc * 32 + nt * 8 + (lane & 3) * 2;
            aS[nt][0] = p1[c]; aS[nt][1] = p1[c + 1];
            aD[nt][0] = p2[c]; aD[nt][1] = p2[c + 1];
        }
#pragma unroll
        for (int mt = 0; mt < 4; ++mt) {
#pragma unroll
            for (int hrow = 0; hrow < 2; ++hrow) {
                float s1 = 0.f, s2 = 0.f;
                int r = wr * 64 + mt * 16 + (lane >> 2) + hrow * 8;
                int gr = rowBase + r;
#pragma unroll
                for (int nt = 0; nt < 4; ++nt) {
                    int c = wc * 32 + nt * 8 + (lane & 3) * 2;
                    float v0 = acc[mt][nt][hrow * 2 + 0];
                    float v1 = acc[mt][nt][hrow * 2 + 1];
                    s1 += v0 * aS[nt][0] + v1 * aS[nt][1];
                    s2 += v0 * aD[nt][0] + v1 * aD[nt][1];
                    if (gr < M)
                        *reinterpret_cast<float2*>(&C[(size_t)gr * 128 + c]) =
                            make_float2(v0, v1);
                }
                s1 += __shfl_xor_sync(0xffffffffu, s1, 1);
                s1 += __shfl_xor_sync(0xffffffffu, s1, 2);
                s2 += __shfl_xor_sync(0xffffffffu, s2, 1);
                s2 += __shfl_xor_sync(0xffffffffu, s2, 2);
                if ((lane & 3) == 0) { rb1[r * 4 + wc] = s1; rb2[r * 4 + wc] = s2; }
            }
        }
        __syncthreads();
        if (tid < 128) {
            int gr = rowBase + tid;
            if (gr < M) {
                as_[gr] = rb1[tid * 4] + rb1[tid * 4 + 1] + rb1[tid * 4 + 2] + rb1[tid * 4 + 3];
                ad_[gr] = rb2[tid * 4] + rb2[tid * 4 + 1] + rb2[tid * 4 + 2] + rb2[tid * 4 + 3];
            }
        }
    } else {
        // EPI == 3: in-register LayerNorm + ReLU
#pragma unroll
        for (int mt = 0; mt < 4; ++mt) {
#pragma unroll
            for (int hrow = 0; hrow < 2; ++hrow) {
                float s = 0.f, q = 0.f;
                int r = wr * 64 + mt * 16 + (lane >> 2) + hrow * 8;
#pragma unroll
                for (int nt = 0; nt < 4; ++nt) {
                    int c = wc * 32 + nt * 8 + (lane & 3) * 2;
                    float v0 = acc[mt][nt][hrow * 2 + 0] + bias[c];
                    float v1 = acc[mt][nt][hrow * 2 + 1] + bias[c + 1];
                    acc[mt][nt][hrow * 2 + 0] = v0;
                    acc[mt][nt][hrow * 2 + 1] = v1;
                    s += v0 + v1;
                    q += v0 * v0 + v1 * v1;
                }
                s += __shfl_xor_sync(0xffffffffu, s, 1);
                s += __shfl_xor_sync(0xffffffffu, s, 2);
                q += __shfl_xor_sync(0xffffffffu, q, 1);
                q += __shfl_xor_sync(0xffffffffu, q, 2);
                if ((lane & 3) == 0) { rb1[r * 4 + wc] = s; rb2[r * 4 + wc] = q; }
            }
        }
        __syncthreads();
#pragma unroll
        for (int mt = 0; mt < 4; ++mt) {
#pragma unroll
            for (int hrow = 0; hrow < 2; ++hrow) {
                int r = wr * 64 + mt * 16 + (lane >> 2) + hrow * 8;
                int gr = rowBase + r;
                float s = rb1[r * 4] + rb1[r * 4 + 1] + rb1[r * 4 + 2] + rb1[r * 4 + 3];
                float q = rb2[r * 4] + rb2[r * 4 + 1] + rb2[r * 4 + 2] + rb2[r * 4 + 3];
                float mean = s * (1.f / 128.f);
                float var  = q * (1.f / 128.f) - mean * mean;
                float is = rsqrtf(var + EPS);
                if (gr < M) {
#pragma unroll
                    for (int nt = 0; nt < 4; ++nt) {
                        int c = wc * 32 + nt * 8 + (lane & 3) * 2;
                        float o0 = fmaxf((acc[mt][nt][hrow * 2 + 0] - mean) * is * p1[c]     + p2[c],     0.f);
                        float o1 = fmaxf((acc[mt][nt][hrow * 2 + 1] - mean) * is * p1[c + 1] + p2[c + 1], 0.f);
                        *reinterpret_cast<float2*>(&C[(size_t)gr * 128 + c]) = make_float2(o0, o1);
                    }
                }
            }
        }
    }
}

// ---------------- fused tail: gate + combine + head + LN2 + fc1 + LN3 + fc2 ----------------
__global__ void __launch_bounds__(256, 2)
k_tail(const float* __restrict__ h1, const float* __restrict__ h2,
       const float* __restrict__ Wg,  const float* __restrict__ bg,
       const float* __restrict__ Wh,  const float* __restrict__ bhd,
       const float* __restrict__ g2,  const float* __restrict__ b2,
       const float* __restrict__ Wf1, const float* __restrict__ bf1,
       const float* __restrict__ g3,  const float* __restrict__ b3,
       const float* __restrict__ Wf2, const float* __restrict__ bf2,
       float* __restrict__ out, int M) {
    __shared__ unsigned AsH[128 * KW], AsL[128 * KW];
    __shared__ unsigned BsH[128 * KW], BsL[128 * KW];
    extern __shared__ float dbuf[];

    const int tid  = threadIdx.x;
    const int wid  = tid >> 5;
    const int lane = tid & 31;
    const int rowBase = blockIdx.x * 128;
    const int ar = tid >> 1, ac = (tid & 1) * 16;
    const int am = rowBase + ar;

    float aReg[16], bReg[16];
    float acc[4][4][4];

    auto convertA = [&]() {
#pragma unroll
        for (int j = 0; j < 16; j += 2) {
            unsigned ph, pl;
            split_pair(aReg[j], aReg[j + 1], ph, pl);
            int wi = ar * KW + ((ac + j) >> 1);
            AsH[wi] = ph; AsL[wi] = pl;
        }
    };

    auto mma128 = [&](int wr, int wc) {
#pragma unroll
        for (int ks = 0; ks < 2; ++ks) {
            unsigned bh[4][2], bl[4][2];
#pragma unroll
            for (int nt = 0; nt < 4; ++nt) {
                int n  = wc * 32 + nt * 8 + (lane >> 2);
                int kw = ks * 8 + (lane & 3);
                bh[nt][0] = BsH[n * KW + kw];     bl[nt][0] = BsL[n * KW + kw];
                bh[nt][1] = BsH[n * KW + kw + 4]; bl[nt][1] = BsL[n * KW + kw + 4];
            }
#pragma unroll
            for (int mt = 0; mt < 4; ++mt) {
                int r  = wr * 64 + mt * 16 + (lane >> 2);
                int kw = ks * 8 + (lane & 3);
                unsigned ah[4], al[4];
                ah[0] = AsH[r * KW + kw];           al[0] = AsL[r * KW + kw];
                ah[1] = AsH[(r + 8) * KW + kw];     al[1] = AsL[(r + 8) * KW + kw];
                ah[2] = AsH[r * KW + kw + 4];       al[2] = AsL[r * KW + kw + 4];
                ah[3] = AsH[(r + 8) * KW + kw + 4]; al[3] = AsL[(r + 8) * KW + kw + 4];
#pragma unroll
                for (int nt = 0; nt < 4; ++nt) {
                    mma_bf16(acc[mt][nt], ah, bh[nt]);
                    mma_bf16(acc[mt][nt], ah, bl[nt]);
                    mma_bf16(acc[mt][nt], al, bh[nt]);
                }
            }
        }
    };

    auto zacc = [&]() {
#pragma unroll
        for (int a = 0; a < 4; ++a)
#pragma unroll
            for (int b = 0; b < 4; ++b)
#pragma unroll
                for (int cc = 0; cc < 4; ++cc) acc[a][b][cc] = 0.f;
    };

    // ================= stage 0: gate GEMM (K=256, N=128) =================
    {
        const int wr = wid >> 2, wc = wid & 3;
        const int bn = tid & 127, bk0 = (tid >> 7) * 16;
        zacc();
        auto gload = [&](int t) {
            const int k0 = t * 32;
#pragma unroll
            for (int j4 = 0; j4 < 4; ++j4) {
                int k = k0 + ac + j4 * 4;
                float4 v = make_float4(0.f, 0.f, 0.f, 0.f);
                if (am < M) {
                    const float* p = (k < 128) ? (h1 + (size_t)am * 128 + k)
                                               : (h2 + (size_t)am * 128 + (k - 128));
                    v = *reinterpret_cast<const float4*>(p);
                }
                aReg[j4 * 4 + 0] = v.x; aReg[j4 * 4 + 1] = v.y;
                aReg[j4 * 4 + 2] = v.z; aReg[j4 * 4 + 3] = v.w;
            }
#pragma unroll
            for (int j = 0; j < 16; ++j)
                bReg[j] = Wg[(size_t)(k0 + bk0 + j) * 128 + bn];
        };
        auto convertB = [&]() {
#pragma unroll
            for (int j = 0; j < 16; j += 2) {
                unsigned ph, pl;
                split_pair(bReg[j], bReg[j + 1], ph, pl);
                int wi = bn * KW + ((bk0 + j) >> 1);
                BsH[wi] = ph; BsL[wi] = pl;
            }
        };
        gload(0);
        for (int t = 0; t < 8; ++t) {
            __syncthreads();
            convertA(); convertB();
            __syncthreads();
            mma128(wr, wc);
            if (t + 1 < 8) gload(t + 1);
        }
        // epilogue: sigmoid gate + combine -> dbuf
#pragma unroll
        for (int mt = 0; mt < 4; ++mt) {
            int rl = wr * 64 + mt * 16 + (lane >> 2);
#pragma unroll
            for (int nt = 0; nt < 4; ++nt) {
                int c = wc * 32 + nt * 8 + (lane & 3) * 2;
#pragma unroll
                for (int hrow = 0; hrow < 2; ++hrow) {
                    int r = rl + hrow * 8;
                    int gr = rowBase + r;
                    float o0 = 0.f, o1 = 0.f;
                    if (gr < M) {
                        size_t idx = (size_t)gr * 128 + c;
                        float v0 = acc[mt][nt][hrow * 2 + 0] + bg[c];
                        float v1 = acc[mt][nt][hrow * 2 + 1] + bg[c + 1];
                        float s0 = 1.f / (1.f + __expf(-v0));
                        float s1 = 1.f / (1.f + __expf(-v1));
                        o0 = s0 * h1[idx]     + (1.f - s0) * h2[idx];
                        o1 = s1 * h1[idx + 1] + (1.f - s1) * h2[idx + 1];
                    }
                    dbuf[r * BUF_STRIDE + c]     = o0;
                    dbuf[r * BUF_STRIDE + c + 1] = o1;
                }
            }
        }
    }

    // ================= stage 1: head GEMM (K=128, N=128), A from dbuf =================
    {
        const int wr = wid >> 2, wc = wid & 3;
        const int bn = tid & 127, bk0 = (tid >> 7) * 16;
        zacc();
        for (int t = 0; t < 4; ++t) {
            const int k0 = t * 32;
            __syncthreads();
#pragma unroll
            for (int j = 0; j < 16; ++j) aReg[j] = dbuf[ar * BUF_STRIDE + k0 + ac + j];
            convertA();
#pragma unroll
            for (int j = 0; j < 16; j += 2) {
                float x0 = Wh[(size_t)(k0 + bk0 + j) * 128 + bn];
                float x1 = Wh[(size_t)(k0 + bk0 + j + 1) * 128 + bn];
                unsigned ph, pl;
                split_pair(x0, x1, ph, pl);
                int wi = bn * KW + ((bk0 + j) >> 1);
                BsH[wi] = ph; BsL[wi] = pl;
            }
            __syncthreads();
            mma128(wr, wc);
        }
#pragma unroll
        for (int mt = 0; mt < 4; ++mt) {
            int rl = wr * 64 + mt * 16 + (lane >> 2);
#pragma unroll
            for (int nt = 0; nt < 4; ++nt) {
                int c = wc * 32 + nt * 8 + (lane & 3) * 2;
#pragma unroll
                for (int hrow = 0; hrow < 2; ++hrow) {
                    int r = rl + hrow * 8;
                    dbuf[r * BUF_STRIDE + c]     = acc[mt][nt][hrow * 2 + 0] + bhd[c];
                    dbuf[r * BUF_STRIDE + c + 1] = acc[mt][nt][hrow * 2 + 1] + bhd[c + 1];
                }
            }
        }
    }
    __syncthreads();

    // ================= LN2 + ReLU in place =================
#pragma unroll 1
    for (int i = 0; i < 16; ++i) {
        int r = wid * 16 + i;
        float v[4]; float s = 0.f;
#pragma unroll
        for (int j = 0; j < 4; ++j) { v[j] = dbuf[r * BUF_STRIDE + lane + 32 * j]; s += v[j]; }
        for (int o = 16; o; o >>= 1) s += __shfl_xor_sync(0xffffffffu, s, o);
        float mean = s * (1.f / 128.f);
        float var = 0.f;
#pragma unroll
        for (int j = 0; j < 4; ++j) { float d = v[j] - mean; var += d * d; }
        for (int o = 16; o; o >>= 1) var += __shfl_xor_sync(0xffffffffu, var, o);
        float is = rsqrtf(var * (1.f / 128.f) + EPS);
#pragma unroll
        for (int j = 0; j < 4; ++j) {
            int c = lane + 32 * j;
            dbuf[r * BUF_STRIDE + c] = fmaxf((v[j] - mean) * is * g2[c] + b2[c], 0.f);
        }
    }
    __syncthreads();

    // ================= stage 2: fc1 GEMM (K=128, N=64) =================
    {
        const int wr = wid >> 1, wc = wid & 1;
        const int bn = tid & 63, bk0 = (tid >> 6) * 8;
        zacc();
        for (int t = 0; t < 4; ++t) {
            const int k0 = t * 32;
            __syncthreads();
#pragma unroll
            for (int j = 0; j < 16; ++j) aReg[j] = dbuf[ar * BUF_STRIDE + k0 + ac + j];
            convertA();
#pragma unroll
            for (int j = 0; j < 8; j += 2) {
                float x0 = Wf1[(size_t)(k0 + bk0 + j) * 64 + bn];
                float x1 = Wf1[(size_t)(k0 + bk0 + j + 1) * 64 + bn];
                unsigned ph, pl;
                split_pair(x0, x1, ph, pl);
                int wi = bn * KW + ((bk0 + j) >> 1);
                BsH[wi] = ph; BsL[wi] = pl;
            }
            __syncthreads();
#pragma unroll
            for (int ks = 0; ks < 2; ++ks) {
                unsigned bh[4][2], bl[4][2];
#pragma unroll
                for (int nt = 0; nt < 4; ++nt) {
                    int n  = wc * 32 + nt * 8 + (lane >> 2);
                    int kw = ks * 8 + (lane & 3);
                    bh[nt][0] = BsH[n * KW + kw];     bl[nt][0] = BsL[n * KW + kw];
                    bh[nt][1] = BsH[n * KW + kw + 4]; bl[nt][1] = BsL[n * KW + kw + 4];
                }
#pragma unroll
                for (int mt = 0; mt < 2; ++mt) {
                    int r  = wr * 32 + mt * 16 + (lane >> 2);
                    int kw = ks * 8 + (lane & 3);
                    unsigned ah[4], al[4];
                    ah[0] = AsH[r * KW + kw];           al[0] = AsL[r * KW + kw];
                    ah[1] = AsH[(r + 8) * KW + kw];     al[1] = AsL[(r + 8) * KW + kw];
                    ah[2] = AsH[r * KW + kw + 4];       al[2] = AsL[r * KW + kw + 4];
                    ah[3] = AsH[(r + 8) * KW + kw + 4]; al[3] = AsL[(r + 8) * KW + kw + 4];
#pragma unroll
                    for (int nt = 0; nt < 4; ++nt) {
                        mma_bf16(acc[mt][nt], ah, bh[nt]);
                        mma_bf16(acc[mt][nt], ah, bl[nt]);
                        mma_bf16(acc[mt][nt], al, bh[nt]);
                    }
                }
            }
        }
#pragma unroll
        for (int mt = 0; mt < 2; ++mt) {
            int rl = wr * 32 + mt * 16 + (lane >> 2);
#pragma unroll
            for (int nt = 0; nt < 4; ++nt) {
                int c = wc * 32 + nt * 8 + (lane & 3) * 2;
#pragma unroll
                for (int hrow = 0; hrow < 2; ++hrow) {
                    int r = rl + hrow * 8;
                    dbuf[r * 68 + c]     = acc[mt][nt][hrow * 2 + 0] + bf1[c];
                    dbuf[r * 68 + c + 1] = acc[mt][nt][hrow * 2 + 1] + bf1[c + 1];
                }
            }
        }
    }
    __syncthreads();

    // ================= LN3 + ReLU + fc2 =================
    {
        float w0 = Wf2[lane], w1 = Wf2[lane + 32];
#pragma unroll 1
        for (int i = 0; i < 16; ++i) {
            int r = wid * 16 + i;
            int gr = rowBase + r;
            float x0 = dbuf[r * 68 + lane];
            float x1 = dbuf[r * 68 + lane + 32];
            float s = x0 + x1;
            for (int o = 16; o; o >>= 1) s += __shfl_xor_sync(0xffffffffu, s, o);
            float mean = s * (1.f / 64.f);
            float d0 = x0 - mean, d1 = x1 - mean;
            float var = d0 * d0 + d1 * d1;
            for (int o = 16; o; o >>= 1) var += __shfl_xor_sync(0xffffffffu, var, o);
            float is = rsqrtf(var * (1.f / 64.f) + EPS);
            float n0 = fmaxf(d0 * is * g3[lane]      + b3[lane],      0.f);
            float n1 = fmaxf(d1 * is * g3[lane + 32] + b3[lane + 32], 0.f);
            float dot = n0 * w0 + n1 * w1;
            for (int o = 16; o; o >>= 1) dot += __shfl_xor_sync(0xffffffffu, dot, o);
            if (lane == 0 && gr < M) out[gr] = dot + bf2[0];
        }
    }
}

// ---------------- GAT aggregate (warp per dst node) ----------------
__device__ __forceinline__ float lrelu(float x) { return x > 0.f ? x : 0.2f * x; }

__global__ void k_agg(const int* __restrict__ rowptr, const int* __restrict__ csrc,
                      const float* __restrict__ as_, const float* __restrict__ ad_,
                      const float* __restrict__ xw, const float* __restrict__ bias,
                      float* __restrict__ y) {
    int w = (blockIdx.x * blockDim.x + threadIdx.x) >> 5;
    if (w >= Nn) return;
    int lane = threadIdx.x & 31;
    int s0 = rowptr[w], s1 = rowptr[w + 1];
    float adn = ad_[w];

    float m = -1e30f;
    for (int i = s0 + lane; i < s1; i += 32)
        m = fmaxf(m, lrelu(as_[csrc[i]] + adn));
    for (int o = 16; o; o >>= 1) m = fmaxf(m, __shfl_xor_sync(0xffffffffu, m, o));

    float s = 0.f;
    for (int i = s0 + lane; i < s1; i += 32)
        s += __expf(lrelu(as_[csrc[i]] + adn) - m);
    for (int o = 16; o; o >>= 1) s += __shfl_xor_sync(0xffffffffu, s, o);
    float inv = 1.f / (s + 1e-16f);

    float4 acc = make_float4(0.f, 0.f, 0.f, 0.f);
    for (int i = s0; i < s1; ++i) {
        int src = csrc[i];
        float al = __expf(lrelu(as_[src] + adn) - m) * inv;
        const float4 v = *reinterpret_cast<const float4*>(&xw[(size_t)src * H + lane * 4]);
        acc.x += al * v.x; acc.y += al * v.y; acc.z += al * v.z; acc.w += al * v.w;
    }
    const float4 bv = *reinterpret_cast<const float4*>(&bias[lane * 4]);
    float4 o = make_float4(acc.x + bv.x, acc.y + bv.y, acc.z + bv.z, acc.w + bv.w);
    *reinterpret_cast<float4*>(&y[(size_t)w * H + lane * 4]) = o;
}

// ---------------- GraphNorm: one-pass stats ----------------
__global__ void k_gn_stats(const float* __restrict__ y, const int* __restrict__ batch,
                           float* __restrict__ gsum, float* __restrict__ gsq) {
    int col  = threadIdx.x & (H - 1);
    int half = threadIdx.x >> 7;
    int r0 = blockIdx.x * 64 + half * 32;
    int r1 = min(r0 + 32, Nn);
    float a1 = 0.f, a2 = 0.f; int cur = -1;
    for (int r = r0; r < r1; ++r) {
        int gg = batch[r];
        if (gg != cur) {
            if (cur >= 0) {
                atomicAdd(&gsum[cur * H + col], a1);
                atomicAdd(&gsq [cur * H + col], a2);
            }
            a1 = 0.f; a2 = 0.f; cur = gg;
        }
        float v = y[(size_t)r * H + col];
        a1 += v; a2 += v * v;
    }
    if (cur >= 0) {
        atomicAdd(&gsum[cur * H + col], a1);
        atomicAdd(&gsq [cur * H + col], a2);
    }
}

__global__ void k_gn_fin(const float* __restrict__ gsum, const float* __restrict__ gsq,
                         const int* __restrict__ cnt,
                         const float* __restrict__ w, const float* __restrict__ b,
                         const float* __restrict__ ms,
                         float* __restrict__ kA, float* __restrict__ kB) {
    int i = blockIdx.x * blockDim.x + threadIdx.x;
    if (i >= G * H) return;
    int col = i & (H - 1);
    float c = fmaxf((float)cnt[i >> 7], 1.f);
    float mean = gsum[i] / c;
    float q    = gsq[i] / c;
    float msv  = ms[col];
    float var = q - msv * (2.f - msv) * mean * mean;
    float is = rsqrtf(var + EPS);
    float a = w[col] * is;
    kA[i] = a;
    kB[i] = b[col] - a * msv * mean;
}

__global__ void k_gn_norm(const float* __restrict__ y, const int* __restrict__ batch,
                          const float* __restrict__ kA, const float* __restrict__ kB,
                          const float* __restrict__ res, float* __restrict__ out) {
    int i = blockIdx.x * blockDim.x + threadIdx.x;
    if (i >= Nn * H) return;
    int row = i >> 7;
    int col = i & (H - 1);
    int gi = batch[row] * H + col;
    float v = fmaxf(fmaf(y[i], kA[gi], kB[gi]), 0.f);
    if (res) v += res[i];
    out[i] = v;
}

// =====================================================================
extern "C" void kernel_launch(void* const* d_in, const int* in_sizes, int n_in,
                              void* d_out, int out_size) {
    const float* rna    = (const float*)d_in[0];
    const float* ss     = (const float*)d_in[1];
    const int*   ei     = (const int*)  d_in[2];
    const int*   batch  = (const int*)  d_in[3];
    const float* W_fuse = (const float*)d_in[4];
    const float* b_fuse = (const float*)d_in[5];
    const float* ln1_g  = (const float*)d_in[6];
    const float* ln1_b  = (const float*)d_in[7];
    const float* W_gat  = (const float*)d_in[8];
    const float* attS   = (const float*)d_in[9];
    const float* attD   = (const float*)d_in[10];
    const float* b_gat  = (const float*)d_in[11];
    const float* gn_w   = (const float*)d_in[12];
    const float* gn_b   = (const float*)d_in[13];
    const float* gn_ms  = (const float*)d_in[14];
    const float* W_gate = (const float*)d_in[15];
    const float* b_gate = (const float*)d_in[16];
    const float* W_head = (const float*)d_in[17];
    const float* b_head = (const float*)d_in[18];
    const float* ln2_g  = (const float*)d_in[19];
    const float* ln2_b  = (const float*)d_in[20];
    const float* W_fc1  = (const float*)d_in[21];
    const float* b_fc1  = (const float*)d_in[22];
    const float* ln3_g  = (const float*)d_in[23];
    const float* ln3_b  = (const float*)d_in[24];
    const float* W_fc2  = (const float*)d_in[25];
    const float* b_fc2  = (const float*)d_in[26];
    float* out = (float*)d_out;

    float *h, *xw, *y, *h1, *h2, *as_, *ad_;
    float *gsum, *gsq, *kA, *kB;
    int *deg, *fill, *rowptr, *csrc, *cnt, *bsum;
    cudaGetSymbolAddress((void**)&h,     g_h);
    cudaGetSymbolAddress((void**)&xw,    g_xw);
    cudaGetSymbolAddress((void**)&y,     g_y);
    cudaGetSymbolAddress((void**)&h1,    g_h1);
    cudaGetSymbolAddress((void**)&h2,    g_h2);
    cudaGetSymbolAddress((void**)&as_,   g_as);
    cudaGetSymbolAddress((void**)&ad_,   g_ad);
    cudaGetSymbolAddress((void**)&deg,   g_deg);
    cudaGetSymbolAddress((void**)&fill,  g_fill);
    cudaGetSymbolAddress((void**)&rowptr,g_rowptr);
    cudaGetSymbolAddress((void**)&csrc,  g_csrc);
    cudaGetSymbolAddress((void**)&bsum,  g_bsum);
    cudaGetSymbolAddress((void**)&gsum,  g_gsum);
    cudaGetSymbolAddress((void**)&gsq,   g_gsq);
    cudaGetSymbolAddress((void**)&kA,    g_kA);
    cudaGetSymbolAddress((void**)&kB,    g_kB);
    cudaGetSymbolAddress((void**)&cnt,   g_cnt);

    cudaFuncSetAttribute(k_tail, cudaFuncAttributeMaxDynamicSharedMemorySize, DYN_SMEM);

    const int TPB = 256;
    const int gRowBlocks = (Nn + 127) / 128;
    const int gWarpRows  = (Nn * 32 + TPB - 1) / TPB;
    const int gElems     = (Nn * H + TPB - 1) / TPB;
    const int gEdges     = (ET + TPB - 1) / TPB;
    const int gGN        = (Nn + 63) / 64;
    const int gGH        = (G * H + TPB - 1) / TPB;
    const int nScanBlk   = (Nn + 255) / 256;

    // CSR prologue (slots 1-3)
    k_zero_all<<<(Nn + TPB - 1) / TPB, TPB>>>(deg, fill, cnt);
    k_hist<<<gEdges, TPB>>>(ei, deg);
    k_scan1<<<nScanBlk, 256>>>(deg, rowptr, bsum);
    // slot 4 (profiled): fuse GEMM + fused LN1 + ReLU -> h
    k_mma<3, true><<<gRowBlocks, 256>>>(
        rna, RNA, ss, W_fuse, b_fuse, h, Nn, Fin, H, ln1_g, ln1_b, nullptr, nullptr);
    // CSR rest
    k_scan2<<<1, 256>>>(bsum, nScanBlk);
    k_scan3<<<(Nn + TPB - 1) / TPB, TPB>>>(rowptr, bsum);
    k_scatter<<<gEdges, TPB>>>(ei, rowptr, fill, csrc);
    k_gcount<<<(Nn + TPB - 1) / TPB, TPB>>>(batch, cnt);

    // ---- two GAT + GraphNorm layers ----
    for (int layer = 0; layer < 2; ++layer) {
        const float* xin = (layer == 0) ? h : h1;
        float* dst       = (layer == 0) ? h1 : h2;
        const float* res = (layer == 0) ? nullptr : h;   // h == LN1 output (residual)

        // GAT GEMM with fused attention dot products
        k_mma<2, false><<<gRowBlocks, 256>>>(
            xin, H, nullptr, W_gat, nullptr, xw, Nn, H, H, attS, attD, as_, ad_);
        k_agg<<<gWarpRows, TPB>>>(rowptr, csrc, as_, ad_, xw, b_gat, y);

        k_zero2_f<<<gGH, TPB>>>(gsum, gsq, G * H);
        k_gn_stats<<<gGN, 256>>>(y, batch, gsum, gsq);
        k_gn_fin<<<gGH, TPB>>>(gsum, gsq, cnt, gn_w, gn_b, gn_ms, kA, kB);
        k_gn_norm<<<gElems, TPB>>>(y, batch, kA, kB, res, dst);
    }

    // ---- fused tail ----
    k_tail<<<gRowBlocks, 256, DYN_SMEM>>>(
        h1, h2, W_gate, b_gate, W_head, b_head, ln2_g, ln2_b,
        W_fc1, b_fc1, ln3_g, ln3_b, W_fc2, b_fc2, out, Nn);
}

// round 9
// speedup vs baseline: 1.3775x; 1.3775x over previous
#include <cuda_runtime.h>
#include <cuda_bf16.h>
#include <math.h>

// ---------------- problem constants ----------------
constexpr int Nn  = 50000;
constexpr int Ee  = 800000;
constexpr int ET  = Ee + Nn;      // + self loops
constexpr int RNA = 645;
constexpr int SSd = 6;
constexpr int Fin = RNA + SSd;    // 651
constexpr int H   = 128;
constexpr int G   = 200;
constexpr float EPS = 1e-5f;

constexpr int BUF_STRIDE = 132;
constexpr int DYN_SMEM   = 128 * BUF_STRIDE * 4;   // 67584 B (tail only)

// ---------------- device scratch ----------------
__device__ float g_h    [Nn * H];
__device__ float g_xw   [Nn * H];
__device__ float g_y    [Nn * H];
__device__ float g_h1   [Nn * H];
__device__ float g_h2   [Nn * H];
__device__ float g_as   [Nn];
__device__ float g_ad   [Nn];
__device__ int   g_deg  [Nn];
__device__ int   g_fill [Nn];
__device__ int   g_rowptr[Nn + 1];
__device__ int   g_csrc [ET];
__device__ int   g_bsum [256];
__device__ float g_gsum [G * H];
__device__ float g_gsq  [G * H];
__device__ float g_kA   [G * H];
__device__ float g_kB   [G * H];
__device__ int   g_cnt  [G];

// ---------------- small utility kernels ----------------
__global__ void k_zero2_f(float* p1, float* p2, int n) {
    int i = blockIdx.x * blockDim.x + threadIdx.x;
    if (i < n) { p1[i] = 0.f; p2[i] = 0.f; }
}
__global__ void k_zero_all(int* deg, int* fill, int* cnt) {
    int i = blockIdx.x * blockDim.x + threadIdx.x;
    if (i < Nn) { deg[i] = 0; fill[i] = 0; }
    if (i < G) cnt[i] = 0;
}

// ---------------- CSR build ----------------
__global__ void k_hist(const int* __restrict__ ei, int* __restrict__ deg) {
    int i = blockIdx.x * blockDim.x + threadIdx.x;
    if (i >= ET) return;
    int dst = (i < Ee) ? ei[Ee + i] : (i - Ee);
    atomicAdd(&deg[dst], 1);
}

__global__ void k_scan1(const int* __restrict__ deg, int* __restrict__ rowptr,
                        int* __restrict__ bsum) {
    __shared__ int sm[256];
    int tx = threadIdx.x;
    int i = blockIdx.x * 256 + tx;
    int v = (i < Nn) ? deg[i] : 0;
    sm[tx] = v;
    __syncthreads();
    for (int off = 1; off < 256; off <<= 1) {
        int t = (tx >= off) ? sm[tx - off] : 0;
        __syncthreads();
        sm[tx] += t;
        __syncthreads();
    }
    if (i < Nn) rowptr[i] = sm[tx] - v;
    if (tx == 255) bsum[blockIdx.x] = sm[255];
}

__global__ void k_scan2(int* __restrict__ bsum, int nblk) {
    __shared__ int sm[256];
    int tx = threadIdx.x;
    int v = (tx < nblk) ? bsum[tx] : 0;
    sm[tx] = v;
    __syncthreads();
    for (int off = 1; off < 256; off <<= 1) {
        int t = (tx >= off) ? sm[tx - off] : 0;
        __syncthreads();
        sm[tx] += t;
        __syncthreads();
    }
    if (tx < nblk) bsum[tx] = sm[tx] - v;
}

__global__ void k_scan3(int* __restrict__ rowptr, const int* __restrict__ bsum) {
    int i = blockIdx.x * blockDim.x + threadIdx.x;
    if (i < Nn) rowptr[i] += bsum[i >> 8];
    if (i == 0) rowptr[Nn] = ET;
}

__global__ void k_scatter(const int* __restrict__ ei, const int* __restrict__ rowptr,
                          int* __restrict__ fill, int* __restrict__ csrc) {
    int i = blockIdx.x * blockDim.x + threadIdx.x;
    if (i >= ET) return;
    int src = (i < Ee) ? ei[i]      : (i - Ee);
    int dst = (i < Ee) ? ei[Ee + i] : (i - Ee);
    int pos = rowptr[dst] + atomicAdd(&fill[dst], 1);
    csrc[pos] = src;
}

__global__ void k_gcount(const int* __restrict__ batch, int* __restrict__ cnt) {
    int i = blockIdx.x * blockDim.x + threadIdx.x;
    if (i < Nn) atomicAdd(&cnt[batch[i]], 1);
}

// ---------------- bf16 mma helpers ----------------
__device__ __forceinline__ void mma_bf16(float* c, const unsigned* a, const unsigned* b) {
    asm volatile(
        "mma.sync.aligned.m16n8k16.row.col.f32.bf16.bf16.f32 "
        "{%0,%1,%2,%3}, {%4,%5,%6,%7}, {%8,%9}, {%0,%1,%2,%3};"
        : "+f"(c[0]), "+f"(c[1]), "+f"(c[2]), "+f"(c[3])
        : "r"(a[0]), "r"(a[1]), "r"(a[2]), "r"(a[3]), "r"(b[0]), "r"(b[1]));
}
__device__ __forceinline__ unsigned pack_bf16x2(float x0, float x1) {
    unsigned p;
    asm("cvt.rn.bf16x2.f32 %0, %1, %2;" : "=r"(p) : "f"(x1), "f"(x0));
    return p;
}
__device__ __forceinline__ void split_pair(float x0, float x1, unsigned& ph, unsigned& pl) {
    ph = pack_bf16x2(x0, x1);
    float h0 = __uint_as_float(ph << 16);
    float h1 = __uint_as_float(ph & 0xffff0000u);
    pl = pack_bf16x2(x0 - h0, x1 - h1);
}

constexpr int KW = 20;   // smem plane words per row (16 data + 4 pad)

// ---------------- tensor-core GEMM, BM=64 x BN=128 tile (bf16 x3 split) ----------------
// EPI 2: write C=xw, plus row dots with p1 (att_src) / p2 (att_dst) -> as_/ad_
// EPI 3: bias add, row-LN(p1=g, p2=b) + ReLU in-register -> C
template <int EPI, bool SCALAR_A>
__global__ void __launch_bounds__(256, 2)
k_mma(const float* __restrict__ A0, int K0,
      const float* __restrict__ A1,
      const float* __restrict__ B,
      const float* __restrict__ bias,
      float* __restrict__ C, int M, int Ktot, int Ncols,
      const float* __restrict__ p1, const float* __restrict__ p2,
      float* __restrict__ as_, float* __restrict__ ad_) {
    constexpr int BM = 64, BK = 32;
    constexpr int AELT = 8, BELT = 16;

    __shared__ unsigned AsH[BM * KW], AsL[BM * KW];     // 5 KB each
    __shared__ unsigned BsH[128 * KW], BsL[128 * KW];   // 10 KB each
    __shared__ float rb1[BM * 4], rb2[BM * 4];

    const int tid  = threadIdx.x;
    const int wid  = tid >> 5;
    const int lane = tid & 31;
    const int wr   = wid >> 2;          // 0..1 over M (32 rows each)
    const int wc   = wid & 3;           // 0..3 over N (32 cols each)
    const int rowBase = blockIdx.x * BM;
    const int K1 = Ktot - K0;

    // A load: 64 rows x 32 k = 2048 elems, 8 per thread
    const int ar = tid >> 2, ac = (tid & 3) * 8;
    const int am = rowBase + ar;
    // B load: 32 k x 128 n, 16 per thread
    const int bn  = tid & 127;
    const int bk0 = (tid >> 7) * 16;

    float aReg[AELT], bReg[BELT];
    float acc[2][4][4];
#pragma unroll
    for (int a = 0; a < 2; ++a)
#pragma unroll
        for (int b = 0; b < 4; ++b)
#pragma unroll
            for (int cc = 0; cc < 4; ++cc) acc[a][b][cc] = 0.f;

    const int T = (Ktot + BK - 1) / BK;

    auto gload = [&](int t) {
        const int k0 = t * BK;
        if (SCALAR_A) {
#pragma unroll
            for (int j = 0; j < AELT; ++j) {
                int k = k0 + ac + j;
                float v = 0.f;
                if (am < M && k < Ktot)
                    v = (k < K0) ? A0[(size_t)am * K0 + k]
                                 : A1[(size_t)am * K1 + (k - K0)];
                aReg[j] = v;
            }
        } else {
#pragma unroll
            for (int j4 = 0; j4 < AELT / 4; ++j4) {
                int k = k0 + ac + j4 * 4;
                float4 v = make_float4(0.f, 0.f, 0.f, 0.f);
                if (am < M) {
                    const float* p = (k < K0) ? (A0 + (size_t)am * K0 + k)
                                              : (A1 + (size_t)am * K1 + (k - K0));
                    v = *reinterpret_cast<const float4*>(p);
                }
                aReg[j4 * 4 + 0] = v.x; aReg[j4 * 4 + 1] = v.y;
                aReg[j4 * 4 + 2] = v.z; aReg[j4 * 4 + 3] = v.w;
            }
        }
#pragma unroll
        for (int j = 0; j < BELT; ++j) {
            int k = k0 + bk0 + j;
            bReg[j] = (k < Ktot) ? B[(size_t)k * Ncols + bn] : 0.f;
        }
    };

    auto convert = [&]() {
#pragma unroll
        for (int j = 0; j < AELT; j += 2) {
            unsigned ph, pl;
            split_pair(aReg[j], aReg[j + 1], ph, pl);
            int wi = ar * KW + ((ac + j) >> 1);
            AsH[wi] = ph; AsL[wi] = pl;
        }
#pragma unroll
        for (int j = 0; j < BELT; j += 2) {
            unsigned ph, pl;
            split_pair(bReg[j], bReg[j + 1], ph, pl);
            int wi = bn * KW + ((bk0 + j) >> 1);
            BsH[wi] = ph; BsL[wi] = pl;
        }
    };

    gload(0);
    for (int t = 0; t < T; ++t) {
        __syncthreads();      // planes free (prev mma done)
        convert();
        __syncthreads();      // planes ready
        if (t + 1 < T) gload(t + 1);

#pragma unroll
        for (int ks = 0; ks < 2; ++ks) {
            unsigned bh[4][2], bl[4][2];
#pragma unroll
            for (int nt = 0; nt < 4; ++nt) {
                int n  = wc * 32 + nt * 8 + (lane >> 2);
                int kw = ks * 8 + (lane & 3);
                bh[nt][0] = BsH[n * KW + kw];     bl[nt][0] = BsL[n * KW + kw];
                bh[nt][1] = BsH[n * KW + kw + 4]; bl[nt][1] = BsL[n * KW + kw + 4];
            }
#pragma unroll
            for (int mt = 0; mt < 2; ++mt) {
                int r  = wr * 32 + mt * 16 + (lane >> 2);
                int kw = ks * 8 + (lane & 3);
                unsigned ah[4], al[4];
                ah[0] = AsH[r * KW + kw];           al[0] = AsL[r * KW + kw];
                ah[1] = AsH[(r + 8) * KW + kw];     al[1] = AsL[(r + 8) * KW + kw];
                ah[2] = AsH[r * KW + kw + 4];       al[2] = AsL[r * KW + kw + 4];
                ah[3] = AsH[(r + 8) * KW + kw + 4]; al[3] = AsL[(r + 8) * KW + kw + 4];
#pragma unroll
                for (int nt = 0; nt < 4; ++nt) {
                    mma_bf16(acc[mt][nt], ah, bh[nt]);
                    mma_bf16(acc[mt][nt], ah, bl[nt]);
                    mma_bf16(acc[mt][nt], al, bh[nt]);
                }
            }
        }
    }

    if (EPI == 2) {
        // write xw + fused attention dot products
        float aS[4][2], aD[4][2];
#pragma unroll
        for (int nt = 0; nt < 4; ++nt) {
            int c = wc * 32 + nt * 8 + (lane & 3) * 2;
            aS[nt][0] = p1[c]; aS[nt][1] = p1[c + 1];
            aD[nt][0] = p2[c]; aD[nt][1] = p2[c + 1];
        }
#pragma unroll
        for (int mt = 0; mt < 2; ++mt) {
#pragma unroll
            for (int hrow = 0; hrow < 2; ++hrow) {
                float s1 = 0.f, s2 = 0.f;
                int r = wr * 32 + mt * 16 + (lane >> 2) + hrow * 8;
                int gr = rowBase + r;
#pragma unroll
                for (int nt = 0; nt < 4; ++nt) {
                    int c = wc * 32 + nt * 8 + (lane & 3) * 2;
                    float v0 = acc[mt][nt][hrow * 2 + 0];
                    float v1 = acc[mt][nt][hrow * 2 + 1];
                    s1 += v0 * aS[nt][0] + v1 * aS[nt][1];
                    s2 += v0 * aD[nt][0] + v1 * aD[nt][1];
                    if (gr < M)
                        *reinterpret_cast<float2*>(&C[(size_t)gr * 128 + c]) =
                            make_float2(v0, v1);
                }
                s1 += __shfl_xor_sync(0xffffffffu, s1, 1);
                s1 += __shfl_xor_sync(0xffffffffu, s1, 2);
                s2 += __shfl_xor_sync(0xffffffffu, s2, 1);
                s2 += __shfl_xor_sync(0xffffffffu, s2, 2);
                if ((lane & 3) == 0) { rb1[r * 4 + wc] = s1; rb2[r * 4 + wc] = s2; }
            }
        }
        __syncthreads();
        if (tid < BM) {
            int gr = rowBase + tid;
            if (gr < M) {
                as_[gr] = rb1[tid * 4] + rb1[tid * 4 + 1] + rb1[tid * 4 + 2] + rb1[tid * 4 + 3];
                ad_[gr] = rb2[tid * 4] + rb2[tid * 4 + 1] + rb2[tid * 4 + 2] + rb2[tid * 4 + 3];
            }
        }
    } else {
        // EPI == 3: bias + in-register LayerNorm + ReLU
#pragma unroll
        for (int mt = 0; mt < 2; ++mt) {
#pragma unroll
            for (int hrow = 0; hrow < 2; ++hrow) {
                float s = 0.f, q = 0.f;
                int r = wr * 32 + mt * 16 + (lane >> 2) + hrow * 8;
#pragma unroll
                for (int nt = 0; nt < 4; ++nt) {
                    int c = wc * 32 + nt * 8 + (lane & 3) * 2;
                    float v0 = acc[mt][nt][hrow * 2 + 0] + bias[c];
                    float v1 = acc[mt][nt][hrow * 2 + 1] + bias[c + 1];
                    acc[mt][nt][hrow * 2 + 0] = v0;
                    acc[mt][nt][hrow * 2 + 1] = v1;
                    s += v0 + v1;
                    q += v0 * v0 + v1 * v1;
                }
                s += __shfl_xor_sync(0xffffffffu, s, 1);
                s += __shfl_xor_sync(0xffffffffu, s, 2);
                q += __shfl_xor_sync(0xffffffffu, q, 1);
                q += __shfl_xor_sync(0xffffffffu, q, 2);
                if ((lane & 3) == 0) { rb1[r * 4 + wc] = s; rb2[r * 4 + wc] = q; }
            }
        }
        __syncthreads();
#pragma unroll
        for (int mt = 0; mt < 2; ++mt) {
#pragma unroll
            for (int hrow = 0; hrow < 2; ++hrow) {
                int r = wr * 32 + mt * 16 + (lane >> 2) + hrow * 8;
                int gr = rowBase + r;
                float s = rb1[r * 4] + rb1[r * 4 + 1] + rb1[r * 4 + 2] + rb1[r * 4 + 3];
                float q = rb2[r * 4] + rb2[r * 4 + 1] + rb2[r * 4 + 2] + rb2[r * 4 + 3];
                float mean = s * (1.f / 128.f);
                float var  = q * (1.f / 128.f) - mean * mean;
                float is = rsqrtf(var + EPS);
                if (gr < M) {
#pragma unroll
                    for (int nt = 0; nt < 4; ++nt) {
                        int c = wc * 32 + nt * 8 + (lane & 3) * 2;
                        float o0 = fmaxf((acc[mt][nt][hrow * 2 + 0] - mean) * is * p1[c]     + p2[c],     0.f);
                        float o1 = fmaxf((acc[mt][nt][hrow * 2 + 1] - mean) * is * p1[c + 1] + p2[c + 1], 0.f);
                        *reinterpret_cast<float2*>(&C[(size_t)gr * 128 + c]) = make_float2(o0, o1);
                    }
                }
            }
        }
    }
}

// ---------------- fused tail (R7 version): gate + combine + head + LN2 + fc1 + LN3 + fc2 ----------------
__global__ void __launch_bounds__(256)
k_tail(const float* __restrict__ h1, const float* __restrict__ h2,
       const float* __restrict__ Wg,  const float* __restrict__ bg,
       const float* __restrict__ Wh,  const float* __restrict__ bhd,
       const float* __restrict__ g2,  const float* __restrict__ b2,
       const float* __restrict__ Wf1, const float* __restrict__ bf1,
       const float* __restrict__ g3,  const float* __restrict__ b3,
       const float* __restrict__ Wf2, const float* __restrict__ bf2,
       float* __restrict__ out, int M) {
    __shared__ unsigned AsH[128 * KW], AsL[128 * KW];
    __shared__ unsigned BsH[128 * KW], BsL[128 * KW];
    extern __shared__ float dbuf[];

    const int tid  = threadIdx.x;
    const int wid  = tid >> 5;
    const int lane = tid & 31;
    const int rowBase = blockIdx.x * 128;
    const int ar = tid >> 1, ac = (tid & 1) * 16;
    const int am = rowBase + ar;

    float aReg[16], bReg[16];
    float acc[4][4][4];

    auto convertA = [&]() {
#pragma unroll
        for (int j = 0; j < 16; j += 2) {
            unsigned ph, pl;
            split_pair(aReg[j], aReg[j + 1], ph, pl);
            int wi = ar * KW + ((ac + j) >> 1);
            AsH[wi] = ph; AsL[wi] = pl;
        }
    };

    auto mma128 = [&](int wr, int wc) {
#pragma unroll
        for (int ks = 0; ks < 2; ++ks) {
            unsigned bh[4][2], bl[4][2];
#pragma unroll
            for (int nt = 0; nt < 4; ++nt) {
                int n  = wc * 32 + nt * 8 + (lane >> 2);
                int kw = ks * 8 + (lane & 3);
                bh[nt][0] = BsH[n * KW + kw];     bl[nt][0] = BsL[n * KW + kw];
                bh[nt][1] = BsH[n * KW + kw + 4]; bl[nt][1] = BsL[n * KW + kw + 4];
            }
#pragma unroll
            for (int mt = 0; mt < 4; ++mt) {
                int r  = wr * 64 + mt * 16 + (lane >> 2);
                int kw = ks * 8 + (lane & 3);
                unsigned ah[4], al[4];
                ah[0] = AsH[r * KW + kw];           al[0] = AsL[r * KW + kw];
                ah[1] = AsH[(r + 8) * KW + kw];     al[1] = AsL[(r + 8) * KW + kw];
                ah[2] = AsH[r * KW + kw + 4];       al[2] = AsL[r * KW + kw + 4];
                ah[3] = AsH[(r + 8) * KW + kw + 4]; al[3] = AsL[(r + 8) * KW + kw + 4];
#pragma unroll
                for (int nt = 0; nt < 4; ++nt) {
                    mma_bf16(acc[mt][nt], ah, bh[nt]);
                    mma_bf16(acc[mt][nt], ah, bl[nt]);
                    mma_bf16(acc[mt][nt], al, bh[nt]);
                }
            }
        }
    };

    auto zacc = [&]() {
#pragma unroll
        for (int a = 0; a < 4; ++a)
#pragma unroll
            for (int b = 0; b < 4; ++b)
#pragma unroll
                for (int cc = 0; cc < 4; ++cc) acc[a][b][cc] = 0.f;
    };

    // ================= stage 0: gate GEMM (K=256, N=128) =================
    {
        const int wr = wid >> 2, wc = wid & 3;
        const int bn = tid & 127, bk0 = (tid >> 7) * 16;
        zacc();
        auto gload = [&](int t) {
            const int k0 = t * 32;
#pragma unroll
            for (int j4 = 0; j4 < 4; ++j4) {
                int k = k0 + ac + j4 * 4;
                float4 v = make_float4(0.f, 0.f, 0.f, 0.f);
                if (am < M) {
                    const float* p = (k < 128) ? (h1 + (size_t)am * 128 + k)
                                               : (h2 + (size_t)am * 128 + (k - 128));
                    v = *reinterpret_cast<const float4*>(p);
                }
                aReg[j4 * 4 + 0] = v.x; aReg[j4 * 4 + 1] = v.y;
                aReg[j4 * 4 + 2] = v.z; aReg[j4 * 4 + 3] = v.w;
            }
#pragma unroll
            for (int j = 0; j < 16; ++j)
                bReg[j] = Wg[(size_t)(k0 + bk0 + j) * 128 + bn];
        };
        auto convertB = [&]() {
#pragma unroll
            for (int j = 0; j < 16; j += 2) {
                unsigned ph, pl;
                split_pair(bReg[j], bReg[j + 1], ph, pl);
                int wi = bn * KW + ((bk0 + j) >> 1);
                BsH[wi] = ph; BsL[wi] = pl;
            }
        };
        gload(0);
        for (int t = 0; t < 8; ++t) {
            __syncthreads();
            convertA(); convertB();
            __syncthreads();
            if (t + 1 < 8) gload(t + 1);
            mma128(wr, wc);
        }
        // epilogue: sigmoid gate + combine -> dbuf
#pragma unroll
        for (int mt = 0; mt < 4; ++mt) {
            int rl = wr * 64 + mt * 16 + (lane >> 2);
#pragma unroll
            for (int nt = 0; nt < 4; ++nt) {
                int c = wc * 32 + nt * 8 + (lane & 3) * 2;
#pragma unroll
                for (int hrow = 0; hrow < 2; ++hrow) {
                    int r = rl + hrow * 8;
                    int gr = rowBase + r;
                    float o0 = 0.f, o1 = 0.f;
                    if (gr < M) {
                        size_t idx = (size_t)gr * 128 + c;
                        float v0 = acc[mt][nt][hrow * 2 + 0] + bg[c];
                        float v1 = acc[mt][nt][hrow * 2 + 1] + bg[c + 1];
                        float s0 = 1.f / (1.f + __expf(-v0));
                        float s1 = 1.f / (1.f + __expf(-v1));
                        o0 = s0 * h1[idx]     + (1.f - s0) * h2[idx];
                        o1 = s1 * h1[idx + 1] + (1.f - s1) * h2[idx + 1];
                    }
                    dbuf[r * BUF_STRIDE + c]     = o0;
                    dbuf[r * BUF_STRIDE + c + 1] = o1;
                }
            }
        }
    }

    // ================= stage 1: head GEMM (K=128, N=128), A from dbuf =================
    {
        const int wr = wid >> 2, wc = wid & 3;
        const int bn = tid & 127, bk0 = (tid >> 7) * 16;
        zacc();
        for (int t = 0; t < 4; ++t) {
            const int k0 = t * 32;
            __syncthreads();
#pragma unroll
            for (int j = 0; j < 16; ++j) aReg[j] = dbuf[ar * BUF_STRIDE + k0 + ac + j];
            convertA();
#pragma unroll
            for (int j = 0; j < 16; j += 2) {
                float x0 = Wh[(size_t)(k0 + bk0 + j) * 128 + bn];
                float x1 = Wh[(size_t)(k0 + bk0 + j + 1) * 128 + bn];
                unsigned ph, pl;
                split_pair(x0, x1, ph, pl);
                int wi = bn * KW + ((bk0 + j) >> 1);
                BsH[wi] = ph; BsL[wi] = pl;
            }
            __syncthreads();
            mma128(wr, wc);
        }
#pragma unroll
        for (int mt = 0; mt < 4; ++mt) {
            int rl = wr * 64 + mt * 16 + (lane >> 2);
#pragma unroll
            for (int nt = 0; nt < 4; ++nt) {
                int c = wc * 32 + nt * 8 + (lane & 3) * 2;
#pragma unroll
                for (int hrow = 0; hrow < 2; ++hrow) {
                    int r = rl + hrow * 8;
                    dbuf[r * BUF_STRIDE + c]     = acc[mt][nt][hrow * 2 + 0] + bhd[c];
                    dbuf[r * BUF_STRIDE + c + 1] = acc[mt][nt][hrow * 2 + 1] + bhd[c + 1];
                }
            }
        }
    }
    __syncthreads();

    // ================= LN2 + ReLU in place =================
#pragma unroll 1
    for (int i = 0; i < 16; ++i) {
        int r = wid * 16 + i;
        float v[4]; float s = 0.f;
#pragma unroll
        for (int j = 0; j < 4; ++j) { v[j] = dbuf[r * BUF_STRIDE + lane + 32 * j]; s += v[j]; }
        for (int o = 16; o; o >>= 1) s += __shfl_xor_sync(0xffffffffu, s, o);
        float mean = s * (1.f / 128.f);
        float var = 0.f;
#pragma unroll
        for (int j = 0; j < 4; ++j) { float d = v[j] - mean; var += d * d; }
        for (int o = 16; o; o >>= 1) var += __shfl_xor_sync(0xffffffffu, var, o);
        float is = rsqrtf(var * (1.f / 128.f) + EPS);
#pragma unroll
        for (int j = 0; j < 4; ++j) {
            int c = lane + 32 * j;
            dbuf[r * BUF_STRIDE + c] = fmaxf((v[j] - mean) * is * g2[c] + b2[c], 0.f);
        }
    }
    __syncthreads();

    // ================= stage 2: fc1 GEMM (K=128, N=64) =================
    {
        const int wr = wid >> 1, wc = wid & 1;
        const int bn = tid & 63, bk0 = (tid >> 6) * 8;
        zacc();
        for (int t = 0; t < 4; ++t) {
            const int k0 = t * 32;
            __syncthreads();
#pragma unroll
            for (int j = 0; j < 16; ++j) aReg[j] = dbuf[ar * BUF_STRIDE + k0 + ac + j];
            convertA();
#pragma unroll
            for (int j = 0; j < 8; j += 2) {
                float x0 = Wf1[(size_t)(k0 + bk0 + j) * 64 + bn];
                float x1 = Wf1[(size_t)(k0 + bk0 + j + 1) * 64 + bn];
                unsigned ph, pl;
                split_pair(x0, x1, ph, pl);
                int wi = bn * KW + ((bk0 + j) >> 1);
                BsH[wi] = ph; BsL[wi] = pl;
            }
            __syncthreads();
#pragma unroll
            for (int ks = 0; ks < 2; ++ks) {
                unsigned bh[4][2], bl[4][2];
#pragma unroll
                for (int nt = 0; nt < 4; ++nt) {
                    int n  = wc * 32 + nt * 8 + (lane >> 2);
                    int kw = ks * 8 + (lane & 3);
                    bh[nt][0] = BsH[n * KW + kw];     bl[nt][0] = BsL[n * KW + kw];
                    bh[nt][1] = BsH[n * KW + kw + 4]; bl[nt][1] = BsL[n * KW + kw + 4];
                }
#pragma unroll
                for (int mt = 0; mt < 2; ++mt) {
                    int r  = wr * 32 + mt * 16 + (lane >> 2);
                    int kw = ks * 8 + (lane & 3);
                    unsigned ah[4], al[4];
                    ah[0] = AsH[r * KW + kw];           al[0] = AsL[r * KW + kw];
                    ah[1] = AsH[(r + 8) * KW + kw];     al[1] = AsL[(r + 8) * KW + kw];
                    ah[2] = AsH[r * KW + kw + 4];       al[2] = AsL[r * KW + kw + 4];
                    ah[3] = AsH[(r + 8) * KW + kw + 4]; al[3] = AsL[(r + 8) * KW + kw + 4];
#pragma unroll
                    for (int nt = 0; nt < 4; ++nt) {
                        mma_bf16(acc[mt][nt], ah, bh[nt]);
                        mma_bf16(acc[mt][nt], ah, bl[nt]);
                        mma_bf16(acc[mt][nt], al, bh[nt]);
                    }
                }
            }
        }
#pragma unroll
        for (int mt = 0; mt < 2; ++mt) {
            int rl = wr * 32 + mt * 16 + (lane >> 2);
#pragma unroll
            for (int nt = 0; nt < 4; ++nt) {
                int c = wc * 32 + nt * 8 + (lane & 3) * 2;
#pragma unroll
                for (int hrow = 0; hrow < 2; ++hrow) {
                    int r = rl + hrow * 8;
                    dbuf[r * 68 + c]     = acc[mt][nt][hrow * 2 + 0] + bf1[c];
                    dbuf[r * 68 + c + 1] = acc[mt][nt][hrow * 2 + 1] + bf1[c + 1];
                }
            }
        }
    }
    __syncthreads();

    // ================= LN3 + ReLU + fc2 =================
    {
        float w0 = Wf2[lane], w1 = Wf2[lane + 32];
#pragma unroll 1
        for (int i = 0; i < 16; ++i) {
            int r = wid * 16 + i;
            int gr = rowBase + r;
            float x0 = dbuf[r * 68 + lane];
            float x1 = dbuf[r * 68 + lane + 32];
            float s = x0 + x1;
            for (int o = 16; o; o >>= 1) s += __shfl_xor_sync(0xffffffffu, s, o);
            float mean = s * (1.f / 64.f);
            float d0 = x0 - mean, d1 = x1 - mean;
            float var = d0 * d0 + d1 * d1;
            for (int o = 16; o; o >>= 1) var += __shfl_xor_sync(0xffffffffu, var, o);
            float is = rsqrtf(var * (1.f / 64.f) + EPS);
            float n0 = fmaxf(d0 * is * g3[lane]      + b3[lane],      0.f);
            float n1 = fmaxf(d1 * is * g3[lane + 32] + b3[lane + 32], 0.f);
            float dot = n0 * w0 + n1 * w1;
            for (int o = 16; o; o >>= 1) dot += __shfl_xor_sync(0xffffffffu, dot, o);
            if (lane == 0 && gr < M) out[gr] = dot + bf2[0];
        }
    }
}

// ---------------- GAT aggregate (warp per dst node) ----------------
__device__ __forceinline__ float lrelu(float x) { return x > 0.f ? x : 0.2f * x; }

__global__ void k_agg(const int* __restrict__ rowptr, const int* __restrict__ csrc,
                      const float* __restrict__ as_, const float* __restrict__ ad_,
                      const float* __restrict__ xw, const float* __restrict__ bias,
                      float* __restrict__ y) {
    int w = (blockIdx.x * blockDim.x + threadIdx.x) >> 5;
    if (w >= Nn) return;
    int lane = threadIdx.x & 31;
    int s0 = rowptr[w], s1 = rowptr[w + 1];
    float adn = ad_[w];

    float m = -1e30f;
    for (int i = s0 + lane; i < s1; i += 32)
        m = fmaxf(m, lrelu(as_[csrc[i]] + adn));
    for (int o = 16; o; o >>= 1) m = fmaxf(m, __shfl_xor_sync(0xffffffffu, m, o));

    float s = 0.f;
    for (int i = s0 + lane; i < s1; i += 32)
        s += __expf(lrelu(as_[csrc[i]] + adn) - m);
    for (int o = 16; o; o >>= 1) s += __shfl_xor_sync(0xffffffffu, s, o);
    float inv = 1.f / (s + 1e-16f);

    float4 acc = make_float4(0.f, 0.f, 0.f, 0.f);
    for (int i = s0; i < s1; ++i) {
        int src = csrc[i];
        float al = __expf(lrelu(as_[src] + adn) - m) * inv;
        const float4 v = *reinterpret_cast<const float4*>(&xw[(size_t)src * H + lane * 4]);
        acc.x += al * v.x; acc.y += al * v.y; acc.z += al * v.z; acc.w += al * v.w;
    }
    const float4 bv = *reinterpret_cast<const float4*>(&bias[lane * 4]);
    float4 o = make_float4(acc.x + bv.x, acc.y + bv.y, acc.z + bv.z, acc.w + bv.w);
    *reinterpret_cast<float4*>(&y[(size_t)w * H + lane * 4]) = o;
}

// ---------------- GraphNorm: one-pass stats ----------------
__global__ void k_gn_stats(const float* __restrict__ y, const int* __restrict__ batch,
                           float* __restrict__ gsum, float* __restrict__ gsq) {
    int col  = threadIdx.x & (H - 1);
    int half = threadIdx.x >> 7;
    int r0 = blockIdx.x * 64 + half * 32;
    int r1 = min(r0 + 32, Nn);
    float a1 = 0.f, a2 = 0.f; int cur = -1;
    for (int r = r0; r < r1; ++r) {
        int gg = batch[r];
        if (gg != cur) {
            if (cur >= 0) {
                atomicAdd(&gsum[cur * H + col], a1);
                atomicAdd(&gsq [cur * H + col], a2);
            }
            a1 = 0.f; a2 = 0.f; cur = gg;
        }
        float v = y[(size_t)r * H + col];
        a1 += v; a2 += v * v;
    }
    if (cur >= 0) {
        atomicAdd(&gsum[cur * H + col], a1);
        atomicAdd(&gsq [cur * H + col], a2);
    }
}

__global__ void k_gn_fin(const float* __restrict__ gsum, const float* __restrict__ gsq,
                         const int* __restrict__ cnt,
                         const float* __restrict__ w, const float* __restrict__ b,
                         const float* __restrict__ ms,
                         float* __restrict__ kA, float* __restrict__ kB) {
    int i = blockIdx.x * blockDim.x + threadIdx.x;
    if (i >= G * H) return;
    int col = i & (H - 1);
    float c = fmaxf((float)cnt[i >> 7], 1.f);
    float mean = gsum[i] / c;
    float q    = gsq[i] / c;
    float msv  = ms[col];
    float var = q - msv * (2.f - msv) * mean * mean;
    float is = rsqrtf(var + EPS);
    float a = w[col] * is;
    kA[i] = a;
    kB[i] = b[col] - a * msv * mean;
}

__global__ void k_gn_norm(const float* __restrict__ y, const int* __restrict__ batch,
                          const float* __restrict__ kA, const float* __restrict__ kB,
                          const float* __restrict__ res, float* __restrict__ out) {
    int i = blockIdx.x * blockDim.x + threadIdx.x;
    if (i >= Nn * H) return;
    int row = i >> 7;
    int col = i & (H - 1);
    int gi = batch[row] * H + col;
    float v = fmaxf(fmaf(y[i], kA[gi], kB[gi]), 0.f);
    if (res) v += res[i];
    out[i] = v;
}

// =====================================================================
extern "C" void kernel_launch(void* const* d_in, const int* in_sizes, int n_in,
                              void* d_out, int out_size) {
    const float* rna    = (const float*)d_in[0];
    const float* ss     = (const float*)d_in[1];
    const int*   ei     = (const int*)  d_in[2];
    const int*   batch  = (const int*)  d_in[3];
    const float* W_fuse = (const float*)d_in[4];
    const float* b_fuse = (const float*)d_in[5];
    const float* ln1_g  = (const float*)d_in[6];
    const float* ln1_b  = (const float*)d_in[7];
    const float* W_gat  = (const float*)d_in[8];
    const float* attS   = (const float*)d_in[9];
    const float* attD   = (const float*)d_in[10];
    const float* b_gat  = (const float*)d_in[11];
    const float* gn_w   = (const float*)d_in[12];
    const float* gn_b   = (const float*)d_in[13];
    const float* gn_ms  = (const float*)d_in[14];
    const float* W_gate = (const float*)d_in[15];
    const float* b_gate = (const float*)d_in[16];
    const float* W_head = (const float*)d_in[17];
    const float* b_head = (const float*)d_in[18];
    const float* ln2_g  = (const float*)d_in[19];
    const float* ln2_b  = (const float*)d_in[20];
    const float* W_fc1  = (const float*)d_in[21];
    const float* b_fc1  = (const float*)d_in[22];
    const float* ln3_g  = (const float*)d_in[23];
    const float* ln3_b  = (const float*)d_in[24];
    const float* W_fc2  = (const float*)d_in[25];
    const float* b_fc2  = (const float*)d_in[26];
    float* out = (float*)d_out;

    float *h, *xw, *y, *h1, *h2, *as_, *ad_;
    float *gsum, *gsq, *kA, *kB;
    int *deg, *fill, *rowptr, *csrc, *cnt, *bsum;
    cudaGetSymbolAddress((void**)&h,     g_h);
    cudaGetSymbolAddress((void**)&xw,    g_xw);
    cudaGetSymbolAddress((void**)&y,     g_y);
    cudaGetSymbolAddress((void**)&h1,    g_h1);
    cudaGetSymbolAddress((void**)&h2,    g_h2);
    cudaGetSymbolAddress((void**)&as_,   g_as);
    cudaGetSymbolAddress((void**)&ad_,   g_ad);
    cudaGetSymbolAddress((void**)&deg,   g_deg);
    cudaGetSymbolAddress((void**)&fill,  g_fill);
    cudaGetSymbolAddress((void**)&rowptr,g_rowptr);
    cudaGetSymbolAddress((void**)&csrc,  g_csrc);
    cudaGetSymbolAddress((void**)&bsum,  g_bsum);
    cudaGetSymbolAddress((void**)&gsum,  g_gsum);
    cudaGetSymbolAddress((void**)&gsq,   g_gsq);
    cudaGetSymbolAddress((void**)&kA,    g_kA);
    cudaGetSymbolAddress((void**)&kB,    g_kB);
    cudaGetSymbolAddress((void**)&cnt,   g_cnt);

    cudaFuncSetAttribute(k_tail, cudaFuncAttributeMaxDynamicSharedMemorySize, DYN_SMEM);

    const int TPB = 256;
    const int gRow64     = (Nn + 63) / 64;               // 782 (k_mma tiles)
    const int gRow128    = (Nn + 127) / 128;             // 391 (tail)
    const int gWarpRows  = (Nn * 32 + TPB - 1) / TPB;
    const int gElems     = (Nn * H + TPB - 1) / TPB;
    const int gEdges     = (ET + TPB - 1) / TPB;
    const int gGN        = (Nn + 63) / 64;
    const int gGH        = (G * H + TPB - 1) / TPB;
    const int nScanBlk   = (Nn + 255) / 256;

    // CSR prologue (slots 1-3)
    k_zero_all<<<(Nn + TPB - 1) / TPB, TPB>>>(deg, fill, cnt);
    k_hist<<<gEdges, TPB>>>(ei, deg);
    k_scan1<<<nScanBlk, 256>>>(deg, rowptr, bsum);
    // slot 4 (profiled): fuse GEMM + fused LN1 + ReLU -> h
    k_mma<3, true><<<gRow64, 256>>>(
        rna, RNA, ss, W_fuse, b_fuse, h, Nn, Fin, H, ln1_g, ln1_b, nullptr, nullptr);
    // CSR rest
    k_scan2<<<1, 256>>>(bsum, nScanBlk);
    k_scan3<<<(Nn + TPB - 1) / TPB, TPB>>>(rowptr, bsum);
    k_scatter<<<gEdges, TPB>>>(ei, rowptr, fill, csrc);
    k_gcount<<<(Nn + TPB - 1) / TPB, TPB>>>(batch, cnt);

    // ---- two GAT + GraphNorm layers ----
    for (int layer = 0; layer < 2; ++layer) {
        const float* xin = (layer == 0) ? h : h1;
        float* dst       = (layer == 0) ? h1 : h2;
        const float* res = (layer == 0) ? nullptr : h;   // h == LN1 output (residual)

        // GAT GEMM with fused attention dot products
        k_mma<2, false><<<gRow64, 256>>>(
            xin, H, nullptr, W_gat, nullptr, xw, Nn, H, H, attS, attD, as_, ad_);
        k_agg<<<gWarpRows, TPB>>>(rowptr, csrc, as_, ad_, xw, b_gat, y);

        k_zero2_f<<<gGH, TPB>>>(gsum, gsq, G * H);
        k_gn_stats<<<gGN, 256>>>(y, batch, gsum, gsq);
        k_gn_fin<<<gGH, TPB>>>(gsum, gsq, cnt, gn_w, gn_b, gn_ms, kA, kB);
        k_gn_norm<<<gElems, TPB>>>(y, batch, kA, kB, res, dst);
    }

    // ---- fused tail (R7 version) ----
    k_tail<<<gRow128, 256, DYN_SMEM>>>(
        h1, h2, W_gate, b_gate, W_head, b_head, ln2_g, ln2_b,
        W_fc1, b_fc1, ln3_g, ln3_b, W_fc2, b_fc2, out, Nn);
}

// round 13
// speedup vs baseline: 1.4333x; 1.0405x over previous
#include <cuda_runtime.h>
#include <cuda_bf16.h>
#include <math.h>

// ---------------- problem constants ----------------
constexpr int Nn  = 50000;
constexpr int Ee  = 800000;
constexpr int ET  = Ee + Nn;      // + self loops
constexpr int RNA = 645;
constexpr int SSd = 6;
constexpr int Fin = RNA + SSd;    // 651
constexpr int H   = 128;
constexpr int G   = 200;
constexpr float EPS = 1e-5f;

constexpr int BUF_STRIDE = 132;
constexpr int DYN_SMEM   = 128 * BUF_STRIDE * 4;   // 67584 B (tail only)

// ---------------- device scratch ----------------
__device__ float g_h    [Nn * H];
__device__ float g_xw   [Nn * H];
__device__ float g_y    [Nn * H];
__device__ float g_h1   [Nn * H];
__device__ float g_h2   [Nn * H];
__device__ float g_as   [Nn];
__device__ float g_ad   [Nn];
__device__ int   g_deg  [Nn];
__device__ int   g_fill [Nn];
__device__ int   g_rowptr[Nn + 1];
__device__ int   g_csrc [ET];
__device__ int   g_bsum [256];
__device__ float g_gsum [G * H];
__device__ float g_gsq  [G * H];
__device__ float g_kA   [G * H];
__device__ float g_kB   [G * H];
__device__ int   g_cnt  [G];

// ---------------- small utility kernels ----------------
__global__ void k_zero2_f(float* p1, float* p2, int n) {
    int i = blockIdx.x * blockDim.x + threadIdx.x;
    if (i < n) { p1[i] = 0.f; p2[i] = 0.f; }
}
__global__ void k_zero_all(int* deg, int* fill, int* cnt) {
    int i = blockIdx.x * blockDim.x + threadIdx.x;
    if (i < Nn) { deg[i] = 0; fill[i] = 0; }
    if (i < G) cnt[i] = 0;
}

// ---------------- CSR build ----------------
__global__ void k_hist(const int* __restrict__ ei, int* __restrict__ deg) {
    int i = blockIdx.x * blockDim.x + threadIdx.x;
    if (i >= ET) return;
    int dst = (i < Ee) ? ei[Ee + i] : (i - Ee);
    atomicAdd(&deg[dst], 1);
}

__global__ void k_scan1(const int* __restrict__ deg, int* __restrict__ rowptr,
                        int* __restrict__ bsum) {
    __shared__ int sm[256];
    int tx = threadIdx.x;
    int i = blockIdx.x * 256 + tx;
    int v = (i < Nn) ? deg[i] : 0;
    sm[tx] = v;
    __syncthreads();
    for (int off = 1; off < 256; off <<= 1) {
        int t = (tx >= off) ? sm[tx - off] : 0;
        __syncthreads();
        sm[tx] += t;
        __syncthreads();
    }
    if (i < Nn) rowptr[i] = sm[tx] - v;
    if (tx == 255) bsum[blockIdx.x] = sm[255];
}

__global__ void k_scan2(int* __restrict__ bsum, int nblk) {
    __shared__ int sm[256];
    int tx = threadIdx.x;
    int v = (tx < nblk) ? bsum[tx] : 0;
    sm[tx] = v;
    __syncthreads();
    for (int off = 1; off < 256; off <<= 1) {
        int t = (tx >= off) ? sm[tx - off] : 0;
        __syncthreads();
        sm[tx] += t;
        __syncthreads();
    }
    if (tx < nblk) bsum[tx] = sm[tx] - v;
}

__global__ void k_scan3(int* __restrict__ rowptr, const int* __restrict__ bsum) {
    int i = blockIdx.x * blockDim.x + threadIdx.x;
    if (i < Nn) rowptr[i] += bsum[i >> 8];
    if (i == 0) rowptr[Nn] = ET;
}

__global__ void k_scatter(const int* __restrict__ ei, const int* __restrict__ rowptr,
                          int* __restrict__ fill, int* __restrict__ csrc) {
    int i = blockIdx.x * blockDim.x + threadIdx.x;
    if (i >= ET) return;
    int src = (i < Ee) ? ei[i]      : (i - Ee);
    int dst = (i < Ee) ? ei[Ee + i] : (i - Ee);
    int pos = rowptr[dst] + atomicAdd(&fill[dst], 1);
    csrc[pos] = src;
}

__global__ void k_gcount(const int* __restrict__ batch, int* __restrict__ cnt) {
    int i = blockIdx.x * blockDim.x + threadIdx.x;
    if (i < Nn) atomicAdd(&cnt[batch[i]], 1);
}

// ---------------- bf16 mma helpers ----------------
__device__ __forceinline__ void mma_bf16(float* c, const unsigned* a, const unsigned* b) {
    asm volatile(
        "mma.sync.aligned.m16n8k16.row.col.f32.bf16.bf16.f32 "
        "{%0,%1,%2,%3}, {%4,%5,%6,%7}, {%8,%9}, {%0,%1,%2,%3};"
        : "+f"(c[0]), "+f"(c[1]), "+f"(c[2]), "+f"(c[3])
        : "r"(a[0]), "r"(a[1]), "r"(a[2]), "r"(a[3]), "r"(b[0]), "r"(b[1]));
}
__device__ __forceinline__ unsigned pack_bf16x2(float x0, float x1) {
    unsigned p;
    asm("cvt.rn.bf16x2.f32 %0, %1, %2;" : "=r"(p) : "f"(x1), "f"(x0));
    return p;
}
__device__ __forceinline__ void split_pair(float x0, float x1, unsigned& ph, unsigned& pl) {
    ph = pack_bf16x2(x0, x1);
    float h0 = __uint_as_float(ph << 16);
    float h1 = __uint_as_float(ph & 0xffff0000u);
    pl = pack_bf16x2(x0 - h0, x1 - h1);
}
__device__ __forceinline__ unsigned long long pack_hl(unsigned ph, unsigned pl) {
    return (unsigned long long)pl << 32 | ph;
}

constexpr int KW = 20;   // 32-bit plane stride for k_tail (16 data + 4 pad)

// ---------------- tensor-core GEMM, BM=64 x BN=128, paired-u64 planes ----------------
// A planes: row-major, addr64 = r*20 + kwword       (conflict-free LDS.64)
// B planes: k-major,   addr64 = kwword*132 + n      (conflict-free STS.64 + LDS.64)
// EPI 2: write C=xw, plus row dots with p1 (att_src) / p2 (att_dst) -> as_/ad_
// EPI 3: bias add, row-LN(p1=g, p2=b) + ReLU in-register -> C
template <int EPI, bool SCALAR_A>
__global__ void __launch_bounds__(256, 2)
k_mma(const float* __restrict__ A0, int K0,
      const float* __restrict__ A1,
      const float* __restrict__ B,
      const float* __restrict__ bias,
      float* __restrict__ C, int M, int Ktot, int Ncols,
      const float* __restrict__ p1, const float* __restrict__ p2,
      float* __restrict__ as_, float* __restrict__ ad_) {
    constexpr int BM = 64, BK = 32;
    constexpr int AELT = 8, BELT = 16;
    constexpr int ASTR = 20;          // u64 per A row (16 used)
    constexpr int BSTR = 132;         // u64 per B k-word row (128 used)

    __shared__ unsigned long long As64[BM * ASTR];   // 10.2 KB
    __shared__ unsigned long long Bs64[16 * BSTR];   // 16.9 KB
    __shared__ float rb1[BM * 4], rb2[BM * 4];

    const int tid  = threadIdx.x;
    const int wid  = tid >> 5;
    const int lane = tid & 31;
    const int wr   = wid >> 2;          // 0..1 over M (32 rows each)
    const int wc   = wid & 3;           // 0..3 over N (32 cols each)
    const int rowBase = blockIdx.x * BM;
    const int K1 = Ktot - K0;

    // A load: 64 rows x 32 k, 8 per thread
    const int ar = tid >> 2, ac = (tid & 3) * 8;
    const int am = rowBase + ar;
    // B load: 32 k x 128 n, 16 per thread (one column, 16 k)
    const int bn  = tid & 127;
    const int bk0 = (tid >> 7) * 16;

    float aReg[AELT], bReg[BELT];
    float acc[2][4][4];
#pragma unroll
    for (int a = 0; a < 2; ++a)
#pragma unroll
        for (int b = 0; b < 4; ++b)
#pragma unroll
            for (int cc = 0; cc < 4; ++cc) acc[a][b][cc] = 0.f;

    const int T = (Ktot + BK - 1) / BK;

    auto gload = [&](int t) {
        const int k0 = t * BK;
        if (SCALAR_A) {
#pragma unroll
            for (int j = 0; j < AELT; ++j) {
                int k = k0 + ac + j;
                float v = 0.f;
                if (am < M && k < Ktot)
                    v = (k < K0) ? A0[(size_t)am * K0 + k]
                                 : A1[(size_t)am * K1 + (k - K0)];
                aReg[j] = v;
            }
        } else {
#pragma unroll
            for (int j4 = 0; j4 < AELT / 4; ++j4) {
                int k = k0 + ac + j4 * 4;
                float4 v = make_float4(0.f, 0.f, 0.f, 0.f);
                if (am < M) {
                    const float* p = (k < K0) ? (A0 + (size_t)am * K0 + k)
                                              : (A1 + (size_t)am * K1 + (k - K0));
                    v = *reinterpret_cast<const float4*>(p);
                }
                aReg[j4 * 4 + 0] = v.x; aReg[j4 * 4 + 1] = v.y;
                aReg[j4 * 4 + 2] = v.z; aReg[j4 * 4 + 3] = v.w;
            }
        }
#pragma unroll
        for (int j = 0; j < BELT; ++j) {
            int k = k0 + bk0 + j;
            bReg[j] = (k < Ktot) ? B[(size_t)k * Ncols + bn] : 0.f;
        }
    };

    auto convert = [&]() {
#pragma unroll
        for (int j = 0; j < AELT; j += 2) {
            unsigned ph, pl;
            split_pair(aReg[j], aReg[j + 1], ph, pl);
            As64[ar * ASTR + ((ac + j) >> 1)] = pack_hl(ph, pl);
        }
#pragma unroll
        for (int j = 0; j < BELT; j += 2) {
            unsigned ph, pl;
            split_pair(bReg[j], bReg[j + 1], ph, pl);
            Bs64[((bk0 + j) >> 1) * BSTR + bn] = pack_hl(ph, pl);
        }
    };

    gload(0);
    for (int t = 0; t < T; ++t) {
        __syncthreads();      // planes free (prev mma done)
        convert();
        __syncthreads();      // planes ready
        if (t + 1 < T) gload(t + 1);

#pragma unroll
        for (int ks = 0; ks < 2; ++ks) {
            const int kw = ks * 8 + (lane & 3);
            unsigned bh[4][2], bl[4][2];
#pragma unroll
            for (int nt = 0; nt < 4; ++nt) {
                int n = wc * 32 + nt * 8 + (lane >> 2);
                unsigned long long v0 = Bs64[kw * BSTR + n];
                unsigned long long v1 = Bs64[(kw + 4) * BSTR + n];
                bh[nt][0] = (unsigned)v0; bl[nt][0] = (unsigned)(v0 >> 32);
                bh[nt][1] = (unsigned)v1; bl[nt][1] = (unsigned)(v1 >> 32);
            }
#pragma unroll
            for (int mt = 0; mt < 2; ++mt) {
                int r = wr * 32 + mt * 16 + (lane >> 2);
                unsigned ah[4], al[4];
                unsigned long long a0 = As64[r * ASTR + kw];
                unsigned long long a1 = As64[(r + 8) * ASTR + kw];
                unsigned long long a2 = As64[r * ASTR + kw + 4];
                unsigned long long a3 = As64[(r + 8) * ASTR + kw + 4];
                ah[0] = (unsigned)a0; al[0] = (unsigned)(a0 >> 32);
                ah[1] = (unsigned)a1; al[1] = (unsigned)(a1 >> 32);
                ah[2] = (unsigned)a2; al[2] = (unsigned)(a2 >> 32);
                ah[3] = (unsigned)a3; al[3] = (unsigned)(a3 >> 32);
#pragma unroll
                for (int nt = 0; nt < 4; ++nt) {
                    mma_bf16(acc[mt][nt], ah, bh[nt]);
                    mma_bf16(acc[mt][nt], ah, bl[nt]);
                    mma_bf16(acc[mt][nt], al, bh[nt]);
                }
            }
        }
    }

    if (EPI == 2) {
        // write xw + fused attention dot products
        float aS[4][2], aD[4][2];
#pragma unroll
        for (int nt = 0; nt < 4; ++nt) {
            int c = wc * 32 + nt * 8 + (lane & 3) * 2;
            aS[nt][0] = p1[c]; aS[nt][1] = p1[c + 1];
            aD[nt][0] = p2[c]; aD[nt][1] = p2[c + 1];
        }
#pragma unroll
        for (int mt = 0; mt < 2; ++mt) {
#pragma unroll
            for (int hrow = 0; hrow < 2; ++hrow) {
                float s1 = 0.f, s2 = 0.f;
                int r = wr * 32 + mt * 16 + (lane >> 2) + hrow * 8;
                int gr = rowBase + r;
#pragma unroll
                for (int nt = 0; nt < 4; ++nt) {
                    int c = wc * 32 + nt * 8 + (lane & 3) * 2;
                    float v0 = acc[mt][nt][hrow * 2 + 0];
                    float v1 = acc[mt][nt][hrow * 2 + 1];
                    s1 += v0 * aS[nt][0] + v1 * aS[nt][1];
                    s2 += v0 * aD[nt][0] + v1 * aD[nt][1];
                    if (gr < M)
                        *reinterpret_cast<float2*>(&C[(size_t)gr * 128 + c]) =
                            make_float2(v0, v1);
                }
                s1 += __shfl_xor_sync(0xffffffffu, s1, 1);
                s1 += __shfl_xor_sync(0xffffffffu, s1, 2);
                s2 += __shfl_xor_sync(0xffffffffu, s2, 1);
                s2 += __shfl_xor_sync(0xffffffffu, s2, 2);
                if ((lane & 3) == 0) { rb1[r * 4 + wc] = s1; rb2[r * 4 + wc] = s2; }
            }
        }
        __syncthreads();
        if (tid < BM) {
            int gr = rowBase + tid;
            if (gr < M) {
                as_[gr] = rb1[tid * 4] + rb1[tid * 4 + 1] + rb1[tid * 4 + 2] + rb1[tid * 4 + 3];
                ad_[gr] = rb2[tid * 4] + rb2[tid * 4 + 1] + rb2[tid * 4 + 2] + rb2[tid * 4 + 3];
            }
        }
    } else {
        // EPI == 3: bias + in-register LayerNorm + ReLU
#pragma unroll
        for (int mt = 0; mt < 2; ++mt) {
#pragma unroll
            for (int hrow = 0; hrow < 2; ++hrow) {
                float s = 0.f, q = 0.f;
                int r = wr * 32 + mt * 16 + (lane >> 2) + hrow * 8;
#pragma unroll
                for (int nt = 0; nt < 4; ++nt) {
                    int c = wc * 32 + nt * 8 + (lane & 3) * 2;
                    float v0 = acc[mt][nt][hrow * 2 + 0] + bias[c];
                    float v1 = acc[mt][nt][hrow * 2 + 1] + bias[c + 1];
                    acc[mt][nt][hrow * 2 + 0] = v0;
                    acc[mt][nt][hrow * 2 + 1] = v1;
                    s += v0 + v1;
                    q += v0 * v0 + v1 * v1;
                }
                s += __shfl_xor_sync(0xffffffffu, s, 1);
                s += __shfl_xor_sync(0xffffffffu, s, 2);
                q += __shfl_xor_sync(0xffffffffu, q, 1);
                q += __shfl_xor_sync(0xffffffffu, q, 2);
                if ((lane & 3) == 0) { rb1[r * 4 + wc] = s; rb2[r * 4 + wc] = q; }
            }
        }
        __syncthreads();
#pragma unroll
        for (int mt = 0; mt < 2; ++mt) {
#pragma unroll
            for (int hrow = 0; hrow < 2; ++hrow) {
                int r = wr * 32 + mt * 16 + (lane >> 2) + hrow * 8;
                int gr = rowBase + r;
                float s = rb1[r * 4] + rb1[r * 4 + 1] + rb1[r * 4 + 2] + rb1[r * 4 + 3];
                float q = rb2[r * 4] + rb2[r * 4 + 1] + rb2[r * 4 + 2] + rb2[r * 4 + 3];
                float mean = s * (1.f / 128.f);
                float var  = q * (1.f / 128.f) - mean * mean;
                float is = rsqrtf(var + EPS);
                if (gr < M) {
#pragma unroll
                    for (int nt = 0; nt < 4; ++nt) {
                        int c = wc * 32 + nt * 8 + (lane & 3) * 2;
                        float o0 = fmaxf((acc[mt][nt][hrow * 2 + 0] - mean) * is * p1[c]     + p2[c],     0.f);
                        float o1 = fmaxf((acc[mt][nt][hrow * 2 + 1] - mean) * is * p1[c + 1] + p2[c + 1], 0.f);
                        *reinterpret_cast<float2*>(&C[(size_t)gr * 128 + c]) = make_float2(o0, o1);
                    }
                }
            }
        }
    }
}

// ---------------- fused tail (R7 version): gate + combine + head + LN2 + fc1 + LN3 + fc2 ----------------
__global__ void __launch_bounds__(256)
k_tail(const float* __restrict__ h1, const float* __restrict__ h2,
       const float* __restrict__ Wg,  const float* __restrict__ bg,
       const float* __restrict__ Wh,  const float* __restrict__ bhd,
       const float* __restrict__ g2,  const float* __restrict__ b2,
       const float* __restrict__ Wf1, const float* __restrict__ bf1,
       const float* __restrict__ g3,  const float* __restrict__ b3,
       const float* __restrict__ Wf2, const float* __restrict__ bf2,
       float* __restrict__ out, int M) {
    __shared__ unsigned AsH[128 * KW], AsL[128 * KW];
    __shared__ unsigned BsH[128 * KW], BsL[128 * KW];
    extern __shared__ float dbuf[];

    const int tid  = threadIdx.x;
    const int wid  = tid >> 5;
    const int lane = tid & 31;
    const int rowBase = blockIdx.x * 128;
    const int ar = tid >> 1, ac = (tid & 1) * 16;
    const int am = rowBase + ar;

    float aReg[16], bReg[16];
    float acc[4][4][4];

    auto convertA = [&]() {
#pragma unroll
        for (int j = 0; j < 16; j += 2) {
            unsigned ph, pl;
            split_pair(aReg[j], aReg[j + 1], ph, pl);
            int wi = ar * KW + ((ac + j) >> 1);
            AsH[wi] = ph; AsL[wi] = pl;
        }
    };

    auto mma128 = [&](int wr, int wc) {
#pragma unroll
        for (int ks = 0; ks < 2; ++ks) {
            unsigned bh[4][2], bl[4][2];
#pragma unroll
            for (int nt = 0; nt < 4; ++nt) {
                int n  = wc * 32 + nt * 8 + (lane >> 2);
                int kw = ks * 8 + (lane & 3);
                bh[nt][0] = BsH[n * KW + kw];     bl[nt][0] = BsL[n * KW + kw];
                bh[nt][1] = BsH[n * KW + kw + 4]; bl[nt][1] = BsL[n * KW + kw + 4];
            }
#pragma unroll
            for (int mt = 0; mt < 4; ++mt) {
                int r  = wr * 64 + mt * 16 + (lane >> 2);
                int kw = ks * 8 + (lane & 3);
                unsigned ah[4], al[4];
                ah[0] = AsH[r * KW + kw];           al[0] = AsL[r * KW + kw];
                ah[1] = AsH[(r + 8) * KW + kw];     al[1] = AsL[(r + 8) * KW + kw];
                ah[2] = AsH[r * KW + kw + 4];       al[2] = AsL[r * KW + kw + 4];
                ah[3] = AsH[(r + 8) * KW + kw + 4]; al[3] = AsL[(r + 8) * KW + kw + 4];
#pragma unroll
                for (int nt = 0; nt < 4; ++nt) {
                    mma_bf16(acc[mt][nt], ah, bh[nt]);
                    mma_bf16(acc[mt][nt], ah, bl[nt]);
                    mma_bf16(acc[mt][nt], al, bh[nt]);
                }
            }
        }
    };

    auto zacc = [&]() {
#pragma unroll
        for (int a = 0; a < 4; ++a)
#pragma unroll
            for (int b = 0; b < 4; ++b)
#pragma unroll
                for (int cc = 0; cc < 4; ++cc) acc[a][b][cc] = 0.f;
    };

    // ================= stage 0: gate GEMM (K=256, N=128) =================
    {
        const int wr = wid >> 2, wc = wid & 3;
        const int bn = tid & 127, bk0 = (tid >> 7) * 16;
        zacc();
        auto gload = [&](int t) {
            const int k0 = t * 32;
#pragma unroll
            for (int j4 = 0; j4 < 4; ++j4) {
                int k = k0 + ac + j4 * 4;
                float4 v = make_float4(0.f, 0.f, 0.f, 0.f);
                if (am < M) {
                    const float* p = (k < 128) ? (h1 + (size_t)am * 128 + k)
                                               : (h2 + (size_t)am * 128 + (k - 128));
                    v = *reinterpret_cast<const float4*>(p);
                }
                aReg[j4 * 4 + 0] = v.x; aReg[j4 * 4 + 1] = v.y;
                aReg[j4 * 4 + 2] = v.z; aReg[j4 * 4 + 3] = v.w;
            }
#pragma unroll
            for (int j = 0; j < 16; ++j)
                bReg[j] = Wg[(size_t)(k0 + bk0 + j) * 128 + bn];
        };
        auto convertB = [&]() {
#pragma unroll
            for (int j = 0; j < 16; j += 2) {
                unsigned ph, pl;
                split_pair(bReg[j], bReg[j + 1], ph, pl);
                int wi = bn * KW + ((bk0 + j) >> 1);
                BsH[wi] = ph; BsL[wi] = pl;
            }
        };
        gload(0);
        for (int t = 0; t < 8; ++t) {
            __syncthreads();
            convertA(); convertB();
            __syncthreads();
            if (t + 1 < 8) gload(t + 1);
            mma128(wr, wc);
        }
        // epilogue: sigmoid gate + combine -> dbuf
#pragma unroll
        for (int mt = 0; mt < 4; ++mt) {
            int rl = wr * 64 + mt * 16 + (lane >> 2);
#pragma unroll
            for (int nt = 0; nt < 4; ++nt) {
                int c = wc * 32 + nt * 8 + (lane & 3) * 2;
#pragma unroll
                for (int hrow = 0; hrow < 2; ++hrow) {
                    int r = rl + hrow * 8;
                    int gr = rowBase + r;
                    float o0 = 0.f, o1 = 0.f;
                    if (gr < M) {
                        size_t idx = (size_t)gr * 128 + c;
                        float v0 = acc[mt][nt][hrow * 2 + 0] + bg[c];
                        float v1 = acc[mt][nt][hrow * 2 + 1] + bg[c + 1];
                        float s0 = 1.f / (1.f + __expf(-v0));
                        float s1 = 1.f / (1.f + __expf(-v1));
                        o0 = s0 * h1[idx]     + (1.f - s0) * h2[idx];
                        o1 = s1 * h1[idx + 1] + (1.f - s1) * h2[idx + 1];
                    }
                    dbuf[r * BUF_STRIDE + c]     = o0;
                    dbuf[r * BUF_STRIDE + c + 1] = o1;
                }
            }
        }
    }

    // ================= stage 1: head GEMM (K=128, N=128), A from dbuf =================
    {
        const int wr = wid >> 2, wc = wid & 3;
        const int bn = tid & 127, bk0 = (tid >> 7) * 16;
        zacc();
        for (int t = 0; t < 4; ++t) {
            const int k0 = t * 32;
            __syncthreads();
#pragma unroll
            for (int j = 0; j < 16; ++j) aReg[j] = dbuf[ar * BUF_STRIDE + k0 + ac + j];
            convertA();
#pragma unroll
            for (int j = 0; j < 16; j += 2) {
                float x0 = Wh[(size_t)(k0 + bk0 + j) * 128 + bn];
                float x1 = Wh[(size_t)(k0 + bk0 + j + 1) * 128 + bn];
                unsigned ph, pl;
                split_pair(x0, x1, ph, pl);
                int wi = bn * KW + ((bk0 + j) >> 1);
                BsH[wi] = ph; BsL[wi] = pl;
            }
            __syncthreads();
            mma128(wr, wc);
        }
#pragma unroll
        for (int mt = 0; mt < 4; ++mt) {
            int rl = wr * 64 + mt * 16 + (lane >> 2);
#pragma unroll
            for (int nt = 0; nt < 4; ++nt) {
                int c = wc * 32 + nt * 8 + (lane & 3) * 2;
#pragma unroll
                for (int hrow = 0; hrow < 2; ++hrow) {
                    int r = rl + hrow * 8;
                    dbuf[r * BUF_STRIDE + c]     = acc[mt][nt][hrow * 2 + 0] + bhd[c];
                    dbuf[r * BUF_STRIDE + c + 1] = acc[mt][nt][hrow * 2 + 1] + bhd[c + 1];
                }
            }
        }
    }
    __syncthreads();

    // ================= LN2 + ReLU in place =================
#pragma unroll 1
    for (int i = 0; i < 16; ++i) {
        int r = wid * 16 + i;
        float v[4]; float s = 0.f;
#pragma unroll
        for (int j = 0; j < 4; ++j) { v[j] = dbuf[r * BUF_STRIDE + lane + 32 * j]; s += v[j]; }
        for (int o = 16; o; o >>= 1) s += __shfl_xor_sync(0xffffffffu, s, o);
        float mean = s * (1.f / 128.f);
        float var = 0.f;
#pragma unroll
        for (int j = 0; j < 4; ++j) { float d = v[j] - mean; var += d * d; }
        for (int o = 16; o; o >>= 1) var += __shfl_xor_sync(0xffffffffu, var, o);
        float is = rsqrtf(var * (1.f / 128.f) + EPS);
#pragma unroll
        for (int j = 0; j < 4; ++j) {
            int c = lane + 32 * j;
            dbuf[r * BUF_STRIDE + c] = fmaxf((v[j] - mean) * is * g2[c] + b2[c], 0.f);
        }
    }
    __syncthreads();

    // ================= stage 2: fc1 GEMM (K=128, N=64) =================
    {
        const int wr = wid >> 1, wc = wid & 1;
        const int bn = tid & 63, bk0 = (tid >> 6) * 8;
        zacc();
        for (int t = 0; t < 4; ++t) {
            const int k0 = t * 32;
            __syncthreads();
#pragma unroll
            for (int j = 0; j < 16; ++j) aReg[j] = dbuf[ar * BUF_STRIDE + k0 + ac + j];
            convertA();
#pragma unroll
            for (int j = 0; j < 8; j += 2) {
                float x0 = Wf1[(size_t)(k0 + bk0 + j) * 64 + bn];
                float x1 = Wf1[(size_t)(k0 + bk0 + j + 1) * 64 + bn];
                unsigned ph, pl;
                split_pair(x0, x1, ph, pl);
                int wi = bn * KW + ((bk0 + j) >> 1);
                BsH[wi] = ph; BsL[wi] = pl;
            }
            __syncthreads();
#pragma unroll
            for (int ks = 0; ks < 2; ++ks) {
                unsigned bh[4][2], bl[4][2];
#pragma unroll
                for (int nt = 0; nt < 4; ++nt) {
                    int n  = wc * 32 + nt * 8 + (lane >> 2);
                    int kw = ks * 8 + (lane & 3);
                    bh[nt][0] = BsH[n * KW + kw];     bl[nt][0] = BsL[n * KW + kw];
                    bh[nt][1] = BsH[n * KW + kw + 4]; bl[nt][1] = BsL[n * KW + kw + 4];
                }
#pragma unroll
                for (int mt = 0; mt < 2; ++mt) {
                    int r  = wr * 32 + mt * 16 + (lane >> 2);
                    int kw = ks * 8 + (lane & 3);
                    unsigned ah[4], al[4];
                    ah[0] = AsH[r * KW + kw];           al[0] = AsL[r * KW + kw];
                    ah[1] = AsH[(r + 8) * KW + kw];     al[1] = AsL[(r + 8) * KW + kw];
                    ah[2] = AsH[r * KW + kw + 4];       al[2] = AsL[r * KW + kw + 4];
                    ah[3] = AsH[(r + 8) * KW + kw + 4]; al[3] = AsL[(r + 8) * KW + kw + 4];
#pragma unroll
                    for (int nt = 0; nt < 4; ++nt) {
                        mma_bf16(acc[mt][nt], ah, bh[nt]);
                        mma_bf16(acc[mt][nt], ah, bl[nt]);
                        mma_bf16(acc[mt][nt], al, bh[nt]);
                    }
                }
            }
        }
#pragma unroll
        for (int mt = 0; mt < 2; ++mt) {
            int rl = wr * 32 + mt * 16 + (lane >> 2);
#pragma unroll
            for (int nt = 0; nt < 4; ++nt) {
                int c = wc * 32 + nt * 8 + (lane & 3) * 2;
#pragma unroll
                for (int hrow = 0; hrow < 2; ++hrow) {
                    int r = rl + hrow * 8;
                    dbuf[r * 68 + c]     = acc[mt][nt][hrow * 2 + 0] + bf1[c];
                    dbuf[r * 68 + c + 1] = acc[mt][nt][hrow * 2 + 1] + bf1[c + 1];
                }
            }
        }
    }
    __syncthreads();

    // ================= LN3 + ReLU + fc2 =================
    {
        float w0 = Wf2[lane], w1 = Wf2[lane + 32];
#pragma unroll 1
        for (int i = 0; i < 16; ++i) {
            int r = wid * 16 + i;
            int gr = rowBase + r;
            float x0 = dbuf[r * 68 + lane];
            float x1 = dbuf[r * 68 + lane + 32];
            float s = x0 + x1;
            for (int o = 16; o; o >>= 1) s += __shfl_xor_sync(0xffffffffu, s, o);
            float mean = s * (1.f / 64.f);
            float d0 = x0 - mean, d1 = x1 - mean;
            float var = d0 * d0 + d1 * d1;
            for (int o = 16; o; o >>= 1) var += __shfl_xor_sync(0xffffffffu, var, o);
            float is = rsqrtf(var * (1.f / 64.f) + EPS);
            float n0 = fmaxf(d0 * is * g3[lane]      + b3[lane],      0.f);
            float n1 = fmaxf(d1 * is * g3[lane + 32] + b3[lane + 32], 0.f);
            float dot = n0 * w0 + n1 * w1;
            for (int o = 16; o; o >>= 1) dot += __shfl_xor_sync(0xffffffffu, dot, o);
            if (lane == 0 && gr < M) out[gr] = dot + bf2[0];
        }
    }
}

// ---------------- GAT aggregate (warp per dst node) ----------------
__device__ __forceinline__ float lrelu(float x) { return x > 0.f ? x : 0.2f * x; }

__global__ void k_agg(const int* __restrict__ rowptr, const int* __restrict__ csrc,
                      const float* __restrict__ as_, const float* __restrict__ ad_,
                      const float* __restrict__ xw, const float* __restrict__ bias,
                      float* __restrict__ y) {
    int w = (blockIdx.x * blockDim.x + threadIdx.x) >> 5;
    if (w >= Nn) return;
    int lane = threadIdx.x & 31;
    int s0 = rowptr[w], s1 = rowptr[w + 1];
    float adn = ad_[w];

    float m = -1e30f;
    for (int i = s0 + lane; i < s1; i += 32)
        m = fmaxf(m, lrelu(as_[csrc[i]] + adn));
    for (int o = 16; o; o >>= 1) m = fmaxf(m, __shfl_xor_sync(0xffffffffu, m, o));

    float s = 0.f;
    for (int i = s0 + lane; i < s1; i += 32)
        s += __expf(lrelu(as_[csrc[i]] + adn) - m);
    for (int o = 16; o; o >>= 1) s += __shfl_xor_sync(0xffffffffu, s, o);
    float inv = 1.f / (s + 1e-16f);

    float4 acc = make_float4(0.f, 0.f, 0.f, 0.f);
    for (int i = s0; i < s1; ++i) {
        int src = csrc[i];
        float al = __expf(lrelu(as_[src] + adn) - m) * inv;
        const float4 v = *reinterpret_cast<const float4*>(&xw[(size_t)src * H + lane * 4]);
        acc.x += al * v.x; acc.y += al * v.y; acc.z += al * v.z; acc.w += al * v.w;
    }
    const float4 bv = *reinterpret_cast<const float4*>(&bias[lane * 4]);
    float4 o = make_float4(acc.x + bv.x, acc.y + bv.y, acc.z + bv.z, acc.w + bv.w);
    *reinterpret_cast<float4*>(&y[(size_t)w * H + lane * 4]) = o;
}

// ---------------- GraphNorm: one-pass stats ----------------
__global__ void k_gn_stats(const float* __restrict__ y, const int* __restrict__ batch,
                           float* __restrict__ gsum, float* __restrict__ gsq) {
    int col  = threadIdx.x & (H - 1);
    int half = threadIdx.x >> 7;
    int r0 = blockIdx.x * 64 + half * 32;
    int r1 = min(r0 + 32, Nn);
    float a1 = 0.f, a2 = 0.f; int cur = -1;
    for (int r = r0; r < r1; ++r) {
        int gg = batch[r];
        if (gg != cur) {
            if (cur >= 0) {
                atomicAdd(&gsum[cur * H + col], a1);
                atomicAdd(&gsq [cur * H + col], a2);
            }
            a1 = 0.f; a2 = 0.f; cur = gg;
        }
        float v = y[(size_t)r * H + col];
        a1 += v; a2 += v * v;
    }
    if (cur >= 0) {
        atomicAdd(&gsum[cur * H + col], a1);
        atomicAdd(&gsq [cur * H + col], a2);
    }
}

__global__ void k_gn_fin(const float* __restrict__ gsum, const float* __restrict__ gsq,
                         const int* __restrict__ cnt,
                         const float* __restrict__ w, const float* __restrict__ b,
                         const float* __restrict__ ms,
                         float* __restrict__ kA, float* __restrict__ kB) {
    int i = blockIdx.x * blockDim.x + threadIdx.x;
    if (i >= G * H) return;
    int col = i & (H - 1);
    float c = fmaxf((float)cnt[i >> 7], 1.f);
    float mean = gsum[i] / c;
    float q    = gsq[i] / c;
    float msv  = ms[col];
    float var = q - msv * (2.f - msv) * mean * mean;
    float is = rsqrtf(var + EPS);
    float a = w[col] * is;
    kA[i] = a;
    kB[i] = b[col] - a * msv * mean;
}

__global__ void k_gn_norm(const float* __restrict__ y, const int* __restrict__ batch,
                          const float* __restrict__ kA, const float* __restrict__ kB,
                          const float* __restrict__ res, float* __restrict__ out) {
    int i = blockIdx.x * blockDim.x + threadIdx.x;
    if (i >= Nn * H) return;
    int row = i >> 7;
    int col = i & (H - 1);
    int gi = batch[row] * H + col;
    float v = fmaxf(fmaf(y[i], kA[gi], kB[gi]), 0.f);
    if (res) v += res[i];
    out[i] = v;
}

// =====================================================================
extern "C" void kernel_launch(void* const* d_in, const int* in_sizes, int n_in,
                              void* d_out, int out_size) {
    const float* rna    = (const float*)d_in[0];
    const float* ss     = (const float*)d_in[1];
    const int*   ei     = (const int*)  d_in[2];
    const int*   batch  = (const int*)  d_in[3];
    const float* W_fuse = (const float*)d_in[4];
    const float* b_fuse = (const float*)d_in[5];
    const float* ln1_g  = (const float*)d_in[6];
    const float* ln1_b  = (const float*)d_in[7];
    const float* W_gat  = (const float*)d_in[8];
    const float* attS   = (const float*)d_in[9];
    const float* attD   = (const float*)d_in[10];
    const float* b_gat  = (const float*)d_in[11];
    const float* gn_w   = (const float*)d_in[12];
    const float* gn_b   = (const float*)d_in[13];
    const float* gn_ms  = (const float*)d_in[14];
    const float* W_gate = (const float*)d_in[15];
    const float* b_gate = (const float*)d_in[16];
    const float* W_head = (const float*)d_in[17];
    const float* b_head = (const float*)d_in[18];
    const float* ln2_g  = (const float*)d_in[19];
    const float* ln2_b  = (const float*)d_in[20];
    const float* W_fc1  = (const float*)d_in[21];
    const float* b_fc1  = (const float*)d_in[22];
    const float* ln3_g  = (const float*)d_in[23];
    const float* ln3_b  = (const float*)d_in[24];
    const float* W_fc2  = (const float*)d_in[25];
    const float* b_fc2  = (const float*)d_in[26];
    float* out = (float*)d_out;

    float *h, *xw, *y, *h1, *h2, *as_, *ad_;
    float *gsum, *gsq, *kA, *kB;
    int *deg, *fill, *rowptr, *csrc, *cnt, *bsum;
    cudaGetSymbolAddress((void**)&h,     g_h);
    cudaGetSymbolAddress((void**)&xw,    g_xw);
    cudaGetSymbolAddress((void**)&y,     g_y);
    cudaGetSymbolAddress((void**)&h1,    g_h1);
    cudaGetSymbolAddress((void**)&h2,    g_h2);
    cudaGetSymbolAddress((void**)&as_,   g_as);
    cudaGetSymbolAddress((void**)&ad_,   g_ad);
    cudaGetSymbolAddress((void**)&deg,   g_deg);
    cudaGetSymbolAddress((void**)&fill,  g_fill);
    cudaGetSymbolAddress((void**)&rowptr,g_rowptr);
    cudaGetSymbolAddress((void**)&csrc,  g_csrc);
    cudaGetSymbolAddress((void**)&bsum,  g_bsum);
    cudaGetSymbolAddress((void**)&gsum,  g_gsum);
    cudaGetSymbolAddress((void**)&gsq,   g_gsq);
    cudaGetSymbolAddress((void**)&kA,    g_kA);
    cudaGetSymbolAddress((void**)&kB,    g_kB);
    cudaGetSymbolAddress((void**)&cnt,   g_cnt);

    cudaFuncSetAttribute(k_tail, cudaFuncAttributeMaxDynamicSharedMemorySize, DYN_SMEM);

    const int TPB = 256;
    const int gRow64     = (Nn + 63) / 64;               // 782 (k_mma tiles)
    const int gRow128    = (Nn + 127) / 128;             // 391 (tail)
    const int gWarpRows  = (Nn * 32 + TPB - 1) / TPB;
    const int gElems     = (Nn * H + TPB - 1) / TPB;
    const int gEdges     = (ET + TPB - 1) / TPB;
    const int gGN        = (Nn + 63) / 64;
    const int gGH        = (G * H + TPB - 1) / TPB;
    const int nScanBlk   = (Nn + 255) / 256;

    // CSR prologue (slots 1-3)
    k_zero_all<<<(Nn + TPB - 1) / TPB, TPB>>>(deg, fill, cnt);
    k_hist<<<gEdges, TPB>>>(ei, deg);
    k_scan1<<<nScanBlk, 256>>>(deg, rowptr, bsum);
    // slot 4 (profiled): fuse GEMM + fused LN1 + ReLU -> h
    k_mma<3, true><<<gRow64, 256>>>(
        rna, RNA, ss, W_fuse, b_fuse, h, Nn, Fin, H, ln1_g, ln1_b, nullptr, nullptr);
    // CSR rest
    k_scan2<<<1, 256>>>(bsum, nScanBlk);
    k_scan3<<<(Nn + TPB - 1) / TPB, TPB>>>(rowptr, bsum);
    k_scatter<<<gEdges, TPB>>>(ei, rowptr, fill, csrc);
    k_gcount<<<(Nn + TPB - 1) / TPB, TPB>>>(batch, cnt);

    // ---- two GAT + GraphNorm layers ----
    for (int layer = 0; layer < 2; ++layer) {
        const float* xin = (layer == 0) ? h : h1;
        float* dst       = (layer == 0) ? h1 : h2;
        const float* res = (layer == 0) ? nullptr : h;   // h == LN1 output (residual)

        // GAT GEMM with fused attention dot products
        k_mma<2, false><<<gRow64, 256>>>(
            xin, H, nullptr, W_gat, nullptr, xw, Nn, H, H, attS, attD, as_, ad_);
        k_agg<<<gWarpRows, TPB>>>(rowptr, csrc, as_, ad_, xw, b_gat, y);

        k_zero2_f<<<gGH, TPB>>>(gsum, gsq, G * H);
        k_gn_stats<<<gGN, 256>>>(y, batch, gsum, gsq);
        k_gn_fin<<<gGH, TPB>>>(gsum, gsq, cnt, gn_w, gn_b, gn_ms, kA, kB);
        k_gn_norm<<<gElems, TPB>>>(y, batch, kA, kB, res, dst);
    }

    // ---- fused tail (R7 version) ----
    k_tail<<<gRow128, 256, DYN_SMEM>>>(
        h1, h2, W_gate, b_gate, W_head, b_head, ln2_g, ln2_b,
        W_fc1, b_fc1, ln3_g, ln3_b, W_fc2, b_fc2, out, Nn);
}

// round 16
// speedup vs baseline: 1.4709x; 1.0262x over previous
#include <cuda_runtime.h>
#include <cuda_bf16.h>
#include <math.h>

// ---------------- problem constants ----------------
constexpr int Nn  = 50000;
constexpr int Ee  = 800000;
constexpr int ET  = Ee + Nn;      // + self loops
constexpr int RNA = 645;
constexpr int SSd = 6;
constexpr int Fin = RNA + SSd;    // 651
constexpr int H   = 128;
constexpr int G   = 200;
constexpr float EPS = 1e-5f;

constexpr int BUF_STRIDE = 132;
constexpr int DYN_SMEM   = 128 * BUF_STRIDE * 4;   // 67584 B (tail only)

constexpr int TFUSE = (Fin + 31) / 32;             // 21 k-tiles
constexpr int TGAT  = H / 32;                      // 4 k-tiles

// ---------------- device scratch ----------------
__device__ float g_h    [Nn * H];
__device__ float g_xw   [Nn * H];
__device__ float g_y    [Nn * H];
__device__ float g_h1   [Nn * H];
__device__ float g_h2   [Nn * H];
__device__ float g_as   [Nn];
__device__ float g_ad   [Nn];
__device__ int   g_deg  [Nn];
__device__ int   g_fill [Nn];
__device__ int   g_rowptr[Nn + 1];
__device__ int   g_csrc [ET];
__device__ int   g_bsum [256];
__device__ float g_gsum [G * H];
__device__ float g_gsq  [G * H];
__device__ float g_kA   [G * H];
__device__ float g_kB   [G * H];
__device__ int   g_cnt  [G];
// pre-converted weight planes (u64 = hi bf16x2 | lo bf16x2 << 32), tile-major [kw][n]
__device__ unsigned long long g_Bfuse[TFUSE * 16 * 128];   // 344 KB
__device__ unsigned long long g_Bgat [TGAT  * 16 * 128];   // 64 KB

// ---------------- small utility kernels ----------------
__global__ void k_zero2_f(float* p1, float* p2, int n) {
    int i = blockIdx.x * blockDim.x + threadIdx.x;
    if (i < n) { p1[i] = 0.f; p2[i] = 0.f; }
}
__global__ void k_zero_all(int* deg, int* fill, int* cnt) {
    int i = blockIdx.x * blockDim.x + threadIdx.x;
    if (i < Nn) { deg[i] = 0; fill[i] = 0; }
    if (i < G) cnt[i] = 0;
}

// ---------------- CSR build ----------------
__global__ void k_hist(const int* __restrict__ ei, int* __restrict__ deg) {
    int i = blockIdx.x * blockDim.x + threadIdx.x;
    if (i >= ET) return;
    int dst = (i < Ee) ? ei[Ee + i] : (i - Ee);
    atomicAdd(&deg[dst], 1);
}

__global__ void k_scan1(const int* __restrict__ deg, int* __restrict__ rowptr,
                        int* __restrict__ bsum) {
    __shared__ int sm[256];
    int tx = threadIdx.x;
    int i = blockIdx.x * 256 + tx;
    int v = (i < Nn) ? deg[i] : 0;
    sm[tx] = v;
    __syncthreads();
    for (int off = 1; off < 256; off <<= 1) {
        int t = (tx >= off) ? sm[tx - off] : 0;
        __syncthreads();
        sm[tx] += t;
        __syncthreads();
    }
    if (i < Nn) rowptr[i] = sm[tx] - v;
    if (tx == 255) bsum[blockIdx.x] = sm[255];
}

__global__ void k_scan2(int* __restrict__ bsum, int nblk) {
    __shared__ int sm[256];
    int tx = threadIdx.x;
    int v = (tx < nblk) ? bsum[tx] : 0;
    sm[tx] = v;
    __syncthreads();
    for (int off = 1; off < 256; off <<= 1) {
        int t = (tx >= off) ? sm[tx - off] : 0;
        __syncthreads();
        sm[tx] += t;
        __syncthreads();
    }
    if (tx < nblk) bsum[tx] = sm[tx] - v;
}

__global__ void k_scan3(int* __restrict__ rowptr, const int* __restrict__ bsum) {
    int i = blockIdx.x * blockDim.x + threadIdx.x;
    if (i < Nn) rowptr[i] += bsum[i >> 8];
    if (i == 0) rowptr[Nn] = ET;
}

__global__ void k_scatter(const int* __restrict__ ei, const int* __restrict__ rowptr,
                          int* __restrict__ fill, int* __restrict__ csrc) {
    int i = blockIdx.x * blockDim.x + threadIdx.x;
    if (i >= ET) return;
    int src = (i < Ee) ? ei[i]      : (i - Ee);
    int dst = (i < Ee) ? ei[Ee + i] : (i - Ee);
    int pos = rowptr[dst] + atomicAdd(&fill[dst], 1);
    csrc[pos] = src;
}

__global__ void k_gcount(const int* __restrict__ batch, int* __restrict__ cnt) {
    int i = blockIdx.x * blockDim.x + threadIdx.x;
    if (i < Nn) atomicAdd(&cnt[batch[i]], 1);
}

// ---------------- bf16 mma helpers ----------------
__device__ __forceinline__ void mma_bf16(float* c, const unsigned* a, const unsigned* b) {
    asm volatile(
        "mma.sync.aligned.m16n8k16.row.col.f32.bf16.bf16.f32 "
        "{%0,%1,%2,%3}, {%4,%5,%6,%7}, {%8,%9}, {%0,%1,%2,%3};"
        : "+f"(c[0]), "+f"(c[1]), "+f"(c[2]), "+f"(c[3])
        : "r"(a[0]), "r"(a[1]), "r"(a[2]), "r"(a[3]), "r"(b[0]), "r"(b[1]));
}
__device__ __forceinline__ unsigned pack_bf16x2(float x0, float x1) {
    unsigned p;
    asm("cvt.rn.bf16x2.f32 %0, %1, %2;" : "=r"(p) : "f"(x1), "f"(x0));
    return p;
}
__device__ __forceinline__ void split_pair(float x0, float x1, unsigned& ph, unsigned& pl) {
    ph = pack_bf16x2(x0, x1);
    float h0 = __uint_as_float(ph << 16);
    float h1 = __uint_as_float(ph & 0xffff0000u);
    pl = pack_bf16x2(x0 - h0, x1 - h1);
}
__device__ __forceinline__ unsigned long long pack_hl(unsigned ph, unsigned pl) {
    return (unsigned long long)pl << 32 | ph;
}
__device__ __forceinline__ void cpa16(void* dst, const void* src) {
    unsigned d = (unsigned)__cvta_generic_to_shared(dst);
    asm volatile("cp.async.cg.shared.global [%0], [%1], 16;" :: "r"(d), "l"(src));
}
__device__ __forceinline__ void cpa_commit() {
    asm volatile("cp.async.commit_group;");
}
template <int NN>
__device__ __forceinline__ void cpa_wait() {
    asm volatile("cp.async.wait_group %0;" :: "n"(NN));
}

constexpr int KW = 20;   // 32-bit plane stride for k_tail (16 data + 4 pad)

// ---------------- weight pre-conversion: fp32 [Ktot x 128] -> u64 planes [kw][n] ----------------
__global__ void k_preconv(const float* __restrict__ W, unsigned long long* __restrict__ outp,
                          int Ktot, int nWords) {
    int i = blockIdx.x * blockDim.x + threadIdx.x;
    if (i >= nWords * 128) return;
    int kw = i >> 7, n = i & 127;
    int k0 = kw * 2;
    float x0 = (k0     < Ktot) ? W[(size_t)k0 * 128 + n]       : 0.f;
    float x1 = (k0 + 1 < Ktot) ? W[(size_t)(k0 + 1) * 128 + n] : 0.f;
    unsigned ph, pl;
    split_pair(x0, x1, ph, pl);
    outp[i] = pack_hl(ph, pl);
}

// ---------------- tensor-core GEMM, BM=64 x BN=128, paired-u64 planes ----------------
// B comes PRE-CONVERTED (Bpre, tile-major u64 planes) via cp.async double buffer.
// EPI 2: write C=xw, plus row dots with p1 (att_src) / p2 (att_dst) -> as_/ad_
// EPI 3: bias add, row-LN(p1=g, p2=b) + ReLU in-register -> C
template <int EPI, bool SCALAR_A>
__global__ void __launch_bounds__(256, 2)
k_mma(const float* __restrict__ A0, int K0,
      const float* __restrict__ A1,
      const unsigned long long* __restrict__ Bpre,
      const float* __restrict__ bias,
      float* __restrict__ C, int M, int Ktot,
      const float* __restrict__ p1, const float* __restrict__ p2,
      float* __restrict__ as_, float* __restrict__ ad_) {
    constexpr int BM = 64, BK = 32;
    constexpr int AELT = 8;
    constexpr int ASTR = 20;          // u64 per A row (16 used)
    constexpr int BSTR = 132;         // u64 per B k-word row (128 used)

    __shared__ unsigned long long As64[BM * ASTR];                    // 10.2 KB
    __shared__ __align__(16) unsigned long long Bs64[2][16 * BSTR];   // 33.8 KB
    __shared__ float rb1[BM * 4], rb2[BM * 4];

    const int tid  = threadIdx.x;
    const int wid  = tid >> 5;
    const int lane = tid & 31;
    const int wr   = wid >> 2;          // 0..1 over M (32 rows each)
    const int wc   = wid & 3;           // 0..3 over N (32 cols each)
    const int rowBase = blockIdx.x * BM;
    const int K1 = Ktot - K0;

    // A load: 64 rows x 32 k, 8 per thread
    const int ar = tid >> 2, ac = (tid & 3) * 8;
    const int am = rowBase + ar;
    const bool amv = am < M;

    float aReg[AELT];
    float acc[2][4][4];
#pragma unroll
    for (int a = 0; a < 2; ++a)
#pragma unroll
        for (int b = 0; b < 4; ++b)
#pragma unroll
            for (int cc = 0; cc < 4; ++cc) acc[a][b][cc] = 0.f;

    const int T = (Ktot + BK - 1) / BK;

    auto gload = [&](int t) {
        const int k0 = t * BK;
        if (SCALAR_A) {
            if (k0 + BK <= K0) {
                // full-A0 tile: base + immediate offsets, single thread-level predicate
                const float* base = A0 + (size_t)am * K0 + k0 + ac;
#pragma unroll
                for (int j = 0; j < AELT; ++j) aReg[j] = amv ? base[j] : 0.f;
            } else {
                // boundary tile: general per-element path
#pragma unroll
                for (int j = 0; j < AELT; ++j) {
                    int k = k0 + ac + j;
                    float v = 0.f;
                    if (amv && k < Ktot)
                        v = (k < K0) ? A0[(size_t)am * K0 + k]
                                     : A1[(size_t)am * K1 + (k - K0)];
                    aReg[j] = v;
                }
            }
        } else {
#pragma unroll
            for (int j4 = 0; j4 < AELT / 4; ++j4) {
                int k = k0 + ac + j4 * 4;
                float4 v = make_float4(0.f, 0.f, 0.f, 0.f);
                if (amv) {
                    const float* p = (k < K0) ? (A0 + (size_t)am * K0 + k)
                                              : (A1 + (size_t)am * K1 + (k - K0));
                    v = *reinterpret_cast<const float4*>(p);
                }
                aReg[j4 * 4 + 0] = v.x; aReg[j4 * 4 + 1] = v.y;
                aReg[j4 * 4 + 2] = v.z; aReg[j4 * 4 + 3] = v.w;
            }
        }
    };

    auto convertA = [&]() {
#pragma unroll
        for (int j = 0; j < AELT; j += 2) {
            unsigned ph, pl;
            split_pair(aReg[j], aReg[j + 1], ph, pl);
            As64[ar * ASTR + ((ac + j) >> 1)] = pack_hl(ph, pl);
        }
    };

    // B tile fetch: 16KB via 4x cp.async 16B per thread (contiguous 8 u64 per thread)
    auto bload = [&](int t, int buf) {
        const unsigned long long* src = Bpre + (size_t)t * 2048 + tid * 8;
        unsigned long long* dst = &Bs64[buf][(tid >> 4) * BSTR + (tid & 15) * 8];
        cpa16(dst,     src);
        cpa16(dst + 2, src + 2);
        cpa16(dst + 4, src + 4);
        cpa16(dst + 6, src + 6);
        cpa_commit();
    };

    gload(0);
    bload(0, 0);
    for (int t = 0; t < T; ++t) {
        const int buf = t & 1;
        __syncthreads();                 // mma t-1 done: A planes + B buf^1 free
        if (t + 1 < T) bload(t + 1, buf ^ 1);
        convertA();
        if (t + 1 < T) cpa_wait<1>(); else cpa_wait<0>();
        __syncthreads();                 // A planes + B[buf] ready
        if (t + 1 < T) gload(t + 1);

        const unsigned long long* Bb = Bs64[buf];
#pragma unroll
        for (int ks = 0; ks < 2; ++ks) {
            const int kw = ks * 8 + (lane & 3);
            unsigned bh[4][2], bl[4][2];
#pragma unroll
            for (int nt = 0; nt < 4; ++nt) {
                int n = wc * 32 + nt * 8 + (lane >> 2);
                unsigned long long v0 = Bb[kw * BSTR + n];
                unsigned long long v1 = Bb[(kw + 4) * BSTR + n];
                bh[nt][0] = (unsigned)v0; bl[nt][0] = (unsigned)(v0 >> 32);
                bh[nt][1] = (unsigned)v1; bl[nt][1] = (unsigned)(v1 >> 32);
            }
#pragma unroll
            for (int mt = 0; mt < 2; ++mt) {
                int r = wr * 32 + mt * 16 + (lane >> 2);
                unsigned ah[4], al[4];
                unsigned long long a0 = As64[r * ASTR + kw];
                unsigned long long a1 = As64[(r + 8) * ASTR + kw];
                unsigned long long a2 = As64[r * ASTR + kw + 4];
                unsigned long long a3 = As64[(r + 8) * ASTR + kw + 4];
                ah[0] = (unsigned)a0; al[0] = (unsigned)(a0 >> 32);
                ah[1] = (unsigned)a1; al[1] = (unsigned)(a1 >> 32);
                ah[2] = (unsigned)a2; al[2] = (unsigned)(a2 >> 32);
                ah[3] = (unsigned)a3; al[3] = (unsigned)(a3 >> 32);
#pragma unroll
                for (int nt = 0; nt < 4; ++nt) {
                    mma_bf16(acc[mt][nt], ah, bh[nt]);
                    mma_bf16(acc[mt][nt], ah, bl[nt]);
                    mma_bf16(acc[mt][nt], al, bh[nt]);
                }
            }
        }
    }

    if (EPI == 2) {
        // write xw + fused attention dot products
        float aS[4][2], aD[4][2];
#pragma unroll
        for (int nt = 0; nt < 4; ++nt) {
            int c = wc * 32 + nt * 8 + (lane & 3) * 2;
            aS[nt][0] = p1[c]; aS[nt][1] = p1[c + 1];
            aD[nt][0] = p2[c]; aD[nt][1] = p2[c + 1];
        }
#pragma unroll
        for (int mt = 0; mt < 2; ++mt) {
#pragma unroll
            for (int hrow = 0; hrow < 2; ++hrow) {
                float s1 = 0.f, s2 = 0.f;
                int r = wr * 32 + mt * 16 + (lane >> 2) + hrow * 8;
                int gr = rowBase + r;
#pragma unroll
                for (int nt = 0; nt < 4; ++nt) {
                    int c = wc * 32 + nt * 8 + (lane & 3) * 2;
                    float v0 = acc[mt][nt][hrow * 2 + 0];
                    float v1 = acc[mt][nt][hrow * 2 + 1];
                    s1 += v0 * aS[nt][0] + v1 * aS[nt][1];
                    s2 += v0 * aD[nt][0] + v1 * aD[nt][1];
                    if (gr < M)
                        *reinterpret_cast<float2*>(&C[(size_t)gr * 128 + c]) =
                            make_float2(v0, v1);
                }
                s1 += __shfl_xor_sync(0xffffffffu, s1, 1);
                s1 += __shfl_xor_sync(0xffffffffu, s1, 2);
                s2 += __shfl_xor_sync(0xffffffffu, s2, 1);
                s2 += __shfl_xor_sync(0xffffffffu, s2, 2);
                if ((lane & 3) == 0) { rb1[r * 4 + wc] = s1; rb2[r * 4 + wc] = s2; }
            }
        }
        __syncthreads();
        if (tid < BM) {
            int gr = rowBase + tid;
            if (gr < M) {
                as_[gr] = rb1[tid * 4] + rb1[tid * 4 + 1] + rb1[tid * 4 + 2] + rb1[tid * 4 + 3];
                ad_[gr] = rb2[tid * 4] + rb2[tid * 4 + 1] + rb2[tid * 4 + 2] + rb2[tid * 4 + 3];
            }
        }
    } else {
        // EPI == 3: bias + in-register LayerNorm + ReLU
#pragma unroll
        for (int mt = 0; mt < 2; ++mt) {
#pragma unroll
            for (int hrow = 0; hrow < 2; ++hrow) {
                float s = 0.f, q = 0.f;
                int r = wr * 32 + mt * 16 + (lane >> 2) + hrow * 8;
#pragma unroll
                for (int nt = 0; nt < 4; ++nt) {
                    int c = wc * 32 + nt * 8 + (lane & 3) * 2;
                    float v0 = acc[mt][nt][hrow * 2 + 0] + bias[c];
                    float v1 = acc[mt][nt][hrow * 2 + 1] + bias[c + 1];
                    acc[mt][nt][hrow * 2 + 0] = v0;
                    acc[mt][nt][hrow * 2 + 1] = v1;
                    s += v0 + v1;
                    q += v0 * v0 + v1 * v1;
                }
                s += __shfl_xor_sync(0xffffffffu, s, 1);
                s += __shfl_xor_sync(0xffffffffu, s, 2);
                q += __shfl_xor_sync(0xffffffffu, q, 1);
                q += __shfl_xor_sync(0xffffffffu, q, 2);
                if ((lane & 3) == 0) { rb1[r * 4 + wc] = s; rb2[r * 4 + wc] = q; }
            }
        }
        __syncthreads();
#pragma unroll
        for (int mt = 0; mt < 2; ++mt) {
#pragma unroll
            for (int hrow = 0; hrow < 2; ++hrow) {
                int r = wr * 32 + mt * 16 + (lane >> 2) + hrow * 8;
                int gr = rowBase + r;
                float s = rb1[r * 4] + rb1[r * 4 + 1] + rb1[r * 4 + 2] + rb1[r * 4 + 3];
                float q = rb2[r * 4] + rb2[r * 4 + 1] + rb2[r * 4 + 2] + rb2[r * 4 + 3];
                float mean = s * (1.f / 128.f);
                float var  = q * (1.f / 128.f) - mean * mean;
                float is = rsqrtf(var + EPS);
                if (gr < M) {
#pragma unroll
                    for (int nt = 0; nt < 4; ++nt) {
                        int c = wc * 32 + nt * 8 + (lane & 3) * 2;
                        float o0 = fmaxf((acc[mt][nt][hrow * 2 + 0] - mean) * is * p1[c]     + p2[c],     0.f);
                        float o1 = fmaxf((acc[mt][nt][hrow * 2 + 1] - mean) * is * p1[c + 1] + p2[c + 1], 0.f);
                        *reinterpret_cast<float2*>(&C[(size_t)gr * 128 + c]) = make_float2(o0, o1);
                    }
                }
            }
        }
    }
}

// ---------------- fused tail (unchanged): gate + combine + head + LN2 + fc1 + LN3 + fc2 ----------------
__global__ void __launch_bounds__(256)
k_tail(const float* __restrict__ h1, const float* __restrict__ h2,
       const float* __restrict__ Wg,  const float* __restrict__ bg,
       const float* __restrict__ Wh,  const float* __restrict__ bhd,
       const float* __restrict__ g2,  const float* __restrict__ b2,
       const float* __restrict__ Wf1, const float* __restrict__ bf1,
       const float* __restrict__ g3,  const float* __restrict__ b3,
       const float* __restrict__ Wf2, const float* __restrict__ bf2,
       float* __restrict__ out, int M) {
    __shared__ unsigned AsH[128 * KW], AsL[128 * KW];
    __shared__ unsigned BsH[128 * KW], BsL[128 * KW];
    extern __shared__ float dbuf[];

    const int tid  = threadIdx.x;
    const int wid  = tid >> 5;
    const int lane = tid & 31;
    const int rowBase = blockIdx.x * 128;
    const int ar = tid >> 1, ac = (tid & 1) * 16;
    const int am = rowBase + ar;

    float aReg[16], bReg[16];
    float acc[4][4][4];

    auto convertA = [&]() {
#pragma unroll
        for (int j = 0; j < 16; j += 2) {
            unsigned ph, pl;
            split_pair(aReg[j], aReg[j + 1], ph, pl);
            int wi = ar * KW + ((ac + j) >> 1);
            AsH[wi] = ph; AsL[wi] = pl;
        }
    };

    auto mma128 = [&](int wr, int wc) {
#pragma unroll
        for (int ks = 0; ks < 2; ++ks) {
            unsigned bh[4][2], bl[4][2];
#pragma unroll
            for (int nt = 0; nt < 4; ++nt) {
                int n  = wc * 32 + nt * 8 + (lane >> 2);
                int kw = ks * 8 + (lane & 3);
                bh[nt][0] = BsH[n * KW + kw];     bl[nt][0] = BsL[n * KW + kw];
                bh[nt][1] = BsH[n * KW + kw + 4]; bl[nt][1] = BsL[n * KW + kw + 4];
            }
#pragma unroll
            for (int mt = 0; mt < 4; ++mt) {
                int r  = wr * 64 + mt * 16 + (lane >> 2);
                int kw = ks * 8 + (lane & 3);
                unsigned ah[4], al[4];
                ah[0] = AsH[r * KW + kw];           al[0] = AsL[r * KW + kw];
                ah[1] = AsH[(r + 8) * KW + kw];     al[1] = AsL[(r + 8) * KW + kw];
                ah[2] = AsH[r * KW + kw + 4];       al[2] = AsL[r * KW + kw + 4];
                ah[3] = AsH[(r + 8) * KW + kw + 4]; al[3] = AsL[(r + 8) * KW + kw + 4];
#pragma unroll
                for (int nt = 0; nt < 4; ++nt) {
                    mma_bf16(acc[mt][nt], ah, bh[nt]);
                    mma_bf16(acc[mt][nt], ah, bl[nt]);
                    mma_bf16(acc[mt][nt], al, bh[nt]);
                }
            }
        }
    };

    auto zacc = [&]() {
#pragma unroll
        for (int a = 0; a < 4; ++a)
#pragma unroll
            for (int b = 0; b < 4; ++b)
#pragma unroll
                for (int cc = 0; cc < 4; ++cc) acc[a][b][cc] = 0.f;
    };

    // ================= stage 0: gate GEMM (K=256, N=128) =================
    {
        const int wr = wid >> 2, wc = wid & 3;
        const int bn = tid & 127, bk0 = (tid >> 7) * 16;
        zacc();
        auto gload = [&](int t) {
            const int k0 = t * 32;
#pragma unroll
            for (int j4 = 0; j4 < 4; ++j4) {
                int k = k0 + ac + j4 * 4;
                float4 v = make_float4(0.f, 0.f, 0.f, 0.f);
                if (am < M) {
                    const float* p = (k < 128) ? (h1 + (size_t)am * 128 + k)
                                               : (h2 + (size_t)am * 128 + (k - 128));
                    v = *reinterpret_cast<const float4*>(p);
                }
                aReg[j4 * 4 + 0] = v.x; aReg[j4 * 4 + 1] = v.y;
                aReg[j4 * 4 + 2] = v.z; aReg[j4 * 4 + 3] = v.w;
            }
#pragma unroll
            for (int j = 0; j < 16; ++j)
                bReg[j] = Wg[(size_t)(k0 + bk0 + j) * 128 + bn];
        };
        auto convertB = [&]() {
#pragma unroll
            for (int j = 0; j < 16; j += 2) {
                unsigned ph, pl;
                split_pair(bReg[j], bReg[j + 1], ph, pl);
                int wi = bn * KW + ((bk0 + j) >> 1);
                BsH[wi] = ph; BsL[wi] = pl;
            }
        };
        gload(0);
        for (int t = 0; t < 8; ++t) {
            __syncthreads();
            convertA(); convertB();
            __syncthreads();
            if (t + 1 < 8) gload(t + 1);
            mma128(wr, wc);
        }
        // epilogue: sigmoid gate + combine -> dbuf
#pragma unroll
        for (int mt = 0; mt < 4; ++mt) {
            int rl = wr * 64 + mt * 16 + (lane >> 2);
#pragma unroll
            for (int nt = 0; nt < 4; ++nt) {
                int c = wc * 32 + nt * 8 + (lane & 3) * 2;
#pragma unroll
                for (int hrow = 0; hrow < 2; ++hrow) {
                    int r = rl + hrow * 8;
                    int gr = rowBase + r;
                    float o0 = 0.f, o1 = 0.f;
                    if (gr < M) {
                        size_t idx = (size_t)gr * 128 + c;
                        float v0 = acc[mt][nt][hrow * 2 + 0] + bg[c];
                        float v1 = acc[mt][nt][hrow * 2 + 1] + bg[c + 1];
                        float s0 = 1.f / (1.f + __expf(-v0));
                        float s1 = 1.f / (1.f + __expf(-v1));
                        o0 = s0 * h1[idx]     + (1.f - s0) * h2[idx];
                        o1 = s1 * h1[idx + 1] + (1.f - s1) * h2[idx + 1];
                    }
                    dbuf[r * BUF_STRIDE + c]     = o0;
                    dbuf[r * BUF_STRIDE + c + 1] = o1;
                }
            }
        }
    }

    // ================= stage 1: head GEMM (K=128, N=128), A from dbuf =================
    {
        const int wr = wid >> 2, wc = wid & 3;
        const int bn = tid & 127, bk0 = (tid >> 7) * 16;
        zacc();
        for (int t = 0; t < 4; ++t) {
            const int k0 = t * 32;
            __syncthreads();
#pragma unroll
            for (int j = 0; j < 16; ++j) aReg[j] = dbuf[ar * BUF_STRIDE + k0 + ac + j];
            convertA();
#pragma unroll
            for (int j = 0; j < 16; j += 2) {
                float x0 = Wh[(size_t)(k0 + bk0 + j) * 128 + bn];
                float x1 = Wh[(size_t)(k0 + bk0 + j + 1) * 128 + bn];
                unsigned ph, pl;
                split_pair(x0, x1, ph, pl);
                int wi = bn * KW + ((bk0 + j) >> 1);
                BsH[wi] = ph; BsL[wi] = pl;
            }
            __syncthreads();
            mma128(wr, wc);
        }
#pragma unroll
        for (int mt = 0; mt < 4; ++mt) {
            int rl = wr * 64 + mt * 16 + (lane >> 2);
#pragma unroll
            for (int nt = 0; nt < 4; ++nt) {
                int c = wc * 32 + nt * 8 + (lane & 3) * 2;
#pragma unroll
                for (int hrow = 0; hrow < 2; ++hrow) {
                    int r = rl + hrow * 8;
                    dbuf[r * BUF_STRIDE + c]     = acc[mt][nt][hrow * 2 + 0] + bhd[c];
                    dbuf[r * BUF_STRIDE + c + 1] = acc[mt][nt][hrow * 2 + 1] + bhd[c + 1];
                }
            }
        }
    }
    __syncthreads();

    // ================= LN2 + ReLU in place =================
#pragma unroll 1
    for (int i = 0; i < 16; ++i) {
        int r = wid * 16 + i;
        float v[4]; float s = 0.f;
#pragma unroll
        for (int j = 0; j < 4; ++j) { v[j] = dbuf[r * BUF_STRIDE + lane + 32 * j]; s += v[j]; }
        for (int o = 16; o; o >>= 1) s += __shfl_xor_sync(0xffffffffu, s, o);
        float mean = s * (1.f / 128.f);
        float var = 0.f;
#pragma unroll
        for (int j = 0; j < 4; ++j) { float d = v[j] - mean; var += d * d; }
        for (int o = 16; o; o >>= 1) var += __shfl_xor_sync(0xffffffffu, var, o);
        float is = rsqrtf(var * (1.f / 128.f) + EPS);
#pragma unroll
        for (int j = 0; j < 4; ++j) {
            int c = lane + 32 * j;
            dbuf[r * BUF_STRIDE + c] = fmaxf((v[j] - mean) * is * g2[c] + b2[c], 0.f);
        }
    }
    __syncthreads();

    // ================= stage 2: fc1 GEMM (K=128, N=64) =================
    {
        const int wr = wid >> 1, wc = wid & 1;
        const int bn = tid & 63, bk0 = (tid >> 6) * 8;
        zacc();
        for (int t = 0; t < 4; ++t) {
            const int k0 = t * 32;
            __syncthreads();
#pragma unroll
            for (int j = 0; j < 16; ++j) aReg[j] = dbuf[ar * BUF_STRIDE + k0 + ac + j];
            convertA();
#pragma unroll
            for (int j = 0; j < 8; j += 2) {
                float x0 = Wf1[(size_t)(k0 + bk0 + j) * 64 + bn];
                float x1 = Wf1[(size_t)(k0 + bk0 + j + 1) * 64 + bn];
                unsigned ph, pl;
                split_pair(x0, x1, ph, pl);
                int wi = bn * KW + ((bk0 + j) >> 1);
                BsH[wi] = ph; BsL[wi] = pl;
            }
            __syncthreads();
#pragma unroll
            for (int ks = 0; ks < 2; ++ks) {
                unsigned bh[4][2], bl[4][2];
#pragma unroll
                for (int nt = 0; nt < 4; ++nt) {
                    int n  = wc * 32 + nt * 8 + (lane >> 2);
                    int kw = ks * 8 + (lane & 3);
                    bh[nt][0] = BsH[n * KW + kw];     bl[nt][0] = BsL[n * KW + kw];
                    bh[nt][1] = BsH[n * KW + kw + 4]; bl[nt][1] = BsL[n * KW + kw + 4];
                }
#pragma unroll
                for (int mt = 0; mt < 2; ++mt) {
                    int r  = wr * 32 + mt * 16 + (lane >> 2);
                    int kw = ks * 8 + (lane & 3);
                    unsigned ah[4], al[4];
                    ah[0] = AsH[r * KW + kw];           al[0] = AsL[r * KW + kw];
                    ah[1] = AsH[(r + 8) * KW + kw];     al[1] = AsL[(r + 8) * KW + kw];
                    ah[2] = AsH[r * KW + kw + 4];       al[2] = AsL[r * KW + kw + 4];
                    ah[3] = AsH[(r + 8) * KW + kw + 4]; al[3] = AsL[(r + 8) * KW + kw + 4];
#pragma unroll
                    for (int nt = 0; nt < 4; ++nt) {
                        mma_bf16(acc[mt][nt], ah, bh[nt]);
                        mma_bf16(acc[mt][nt], ah, bl[nt]);
                        mma_bf16(acc[mt][nt], al, bh[nt]);
                    }
                }
            }
        }
#pragma unroll
        for (int mt = 0; mt < 2; ++mt) {
            int rl = wr * 32 + mt * 16 + (lane >> 2);
#pragma unroll
            for (int nt = 0; nt < 4; ++nt) {
                int c = wc * 32 + nt * 8 + (lane & 3) * 2;
#pragma unroll
                for (int hrow = 0; hrow < 2; ++hrow) {
                    int r = rl + hrow * 8;
                    dbuf[r * 68 + c]     = acc[mt][nt][hrow * 2 + 0] + bf1[c];
                    dbuf[r * 68 + c + 1] = acc[mt][nt][hrow * 2 + 1] + bf1[c + 1];
                }
            }
        }
    }
    __syncthreads();

    // ================= LN3 + ReLU + fc2 =================
    {
        float w0 = Wf2[lane], w1 = Wf2[lane + 32];
#pragma unroll 1
        for (int i = 0; i < 16; ++i) {
            int r = wid * 16 + i;
            int gr = rowBase + r;
            float x0 = dbuf[r * 68 + lane];
            float x1 = dbuf[r * 68 + lane + 32];
            float s = x0 + x1;
            for (int o = 16; o; o >>= 1) s += __shfl_xor_sync(0xffffffffu, s, o);
            float mean = s * (1.f / 64.f);
            float d0 = x0 - mean, d1 = x1 - mean;
            float var = d0 * d0 + d1 * d1;
            for (int o = 16; o; o >>= 1) var += __shfl_xor_sync(0xffffffffu, var, o);
            float is = rsqrtf(var * (1.f / 64.f) + EPS);
            float n0 = fmaxf(d0 * is * g3[lane]      + b3[lane],      0.f);
            float n1 = fmaxf(d1 * is * g3[lane + 32] + b3[lane + 32], 0.f);
            float dot = n0 * w0 + n1 * w1;
            for (int o = 16; o; o >>= 1) dot += __shfl_xor_sync(0xffffffffu, dot, o);
            if (lane == 0 && gr < M) out[gr] = dot + bf2[0];
        }
    }
}

// ---------------- GAT aggregate (warp per dst node) ----------------
__device__ __forceinline__ float lrelu(float x) { return x > 0.f ? x : 0.2f * x; }

__global__ void k_agg(const int* __restrict__ rowptr, const int* __restrict__ csrc,
                      const float* __restrict__ as_, const float* __restrict__ ad_,
                      const float* __restrict__ xw, const float* __restrict__ bias,
                      float* __restrict__ y) {
    int w = (blockIdx.x * blockDim.x + threadIdx.x) >> 5;
    if (w >= Nn) return;
    int lane = threadIdx.x & 31;
    int s0 = rowptr[w], s1 = rowptr[w + 1];
    float adn = ad_[w];

    float m = -1e30f;
    for (int i = s0 + lane; i < s1; i += 32)
        m = fmaxf(m, lrelu(as_[csrc[i]] + adn));
    for (int o = 16; o; o >>= 1) m = fmaxf(m, __shfl_xor_sync(0xffffffffu, m, o));

    float s = 0.f;
    for (int i = s0 + lane; i < s1; i += 32)
        s += __expf(lrelu(as_[csrc[i]] + adn) - m);
    for (int o = 16; o; o >>= 1) s += __shfl_xor_sync(0xffffffffu, s, o);
    float inv = 1.f / (s + 1e-16f);

    float4 acc = make_float4(0.f, 0.f, 0.f, 0.f);
    for (int i = s0; i < s1; ++i) {
        int src = csrc[i];
        float al = __expf(lrelu(as_[src] + adn) - m) * inv;
        const float4 v = *reinterpret_cast<const float4*>(&xw[(size_t)src * H + lane * 4]);
        acc.x += al * v.x; acc.y += al * v.y; acc.z += al * v.z; acc.w += al * v.w;
    }
    const float4 bv = *reinterpret_cast<const float4*>(&bias[lane * 4]);
    float4 o = make_float4(acc.x + bv.x, acc.y + bv.y, acc.z + bv.z, acc.w + bv.w);
    *reinterpret_cast<float4*>(&y[(size_t)w * H + lane * 4]) = o;
}

// ---------------- GraphNorm: one-pass stats ----------------
__global__ void k_gn_stats(const float* __restrict__ y, const int* __restrict__ batch,
                           float* __restrict__ gsum, float* __restrict__ gsq) {
    int col  = threadIdx.x & (H - 1);
    int half = threadIdx.x >> 7;
    int r0 = blockIdx.x * 64 + half * 32;
    int r1 = min(r0 + 32, Nn);
    float a1 = 0.f, a2 = 0.f; int cur = -1;
    for (int r = r0; r < r1; ++r) {
        int gg = batch[r];
        if (gg != cur) {
            if (cur >= 0) {
                atomicAdd(&gsum[cur * H + col], a1);
                atomicAdd(&gsq [cur * H + col], a2);
            }
            a1 = 0.f; a2 = 0.f; cur = gg;
        }
        float v = y[(size_t)r * H + col];
        a1 += v; a2 += v * v;
    }
    if (cur >= 0) {
        atomicAdd(&gsum[cur * H + col], a1);
        atomicAdd(&gsq [cur * H + col], a2);
    }
}

__global__ void k_gn_fin(const float* __restrict__ gsum, const float* __restrict__ gsq,
                         const int* __restrict__ cnt,
                         const float* __restrict__ w, const float* __restrict__ b,
                         const float* __restrict__ ms,
                         float* __restrict__ kA, float* __restrict__ kB) {
    int i = blockIdx.x * blockDim.x + threadIdx.x;
    if (i >= G * H) return;
    int col = i & (H - 1);
    float c = fmaxf((float)cnt[i >> 7], 1.f);
    float mean = gsum[i] / c;
    float q    = gsq[i] / c;
    float msv  = ms[col];
    float var = q - msv * (2.f - msv) * mean * mean;
    float is = rsqrtf(var + EPS);
    float a = w[col] * is;
    kA[i] = a;
    kB[i] = b[col] - a * msv * mean;
}

__global__ void k_gn_norm(const float* __restrict__ y, const int* __restrict__ batch,
                          const float* __restrict__ kA, const float* __restrict__ kB,
                          const float* __restrict__ res, float* __restrict__ out) {
    int i = blockIdx.x * blockDim.x + threadIdx.x;
    if (i >= Nn * H) return;
    int row = i >> 7;
    int col = i & (H - 1);
    int gi = batch[row] * H + col;
    float v = fmaxf(fmaf(y[i], kA[gi], kB[gi]), 0.f);
    if (res) v += res[i];
    out[i] = v;
}

// =====================================================================
extern "C" void kernel_launch(void* const* d_in, const int* in_sizes, int n_in,
                              void* d_out, int out_size) {
    const float* rna    = (const float*)d_in[0];
    const float* ss     = (const float*)d_in[1];
    const int*   ei     = (const int*)  d_in[2];
    const int*   batch  = (const int*)  d_in[3];
    const float* W_fuse = (const float*)d_in[4];
    const float* b_fuse = (const float*)d_in[5];
    const float* ln1_g  = (const float*)d_in[6];
    const float* ln1_b  = (const float*)d_in[7];
    const float* W_gat  = (const float*)d_in[8];
    const float* attS   = (const float*)d_in[9];
    const float* attD   = (const float*)d_in[10];
    const float* b_gat  = (const float*)d_in[11];
    const float* gn_w   = (const float*)d_in[12];
    const float* gn_b   = (const float*)d_in[13];
    const float* gn_ms  = (const float*)d_in[14];
    const float* W_gate = (const float*)d_in[15];
    const float* b_gate = (const float*)d_in[16];
    const float* W_head = (const float*)d_in[17];
    const float* b_head = (const float*)d_in[18];
    const float* ln2_g  = (const float*)d_in[19];
    const float* ln2_b  = (const float*)d_in[20];
    const float* W_fc1  = (const float*)d_in[21];
    const float* b_fc1  = (const float*)d_in[22];
    const float* ln3_g  = (const float*)d_in[23];
    const float* ln3_b  = (const float*)d_in[24];
    const float* W_fc2  = (const float*)d_in[25];
    const float* b_fc2  = (const float*)d_in[26];
    float* out = (float*)d_out;

    float *h, *xw, *y, *h1, *h2, *as_, *ad_;
    float *gsum, *gsq, *kA, *kB;
    int *deg, *fill, *rowptr, *csrc, *cnt, *bsum;
    unsigned long long *Bfuse, *Bgat;
    cudaGetSymbolAddress((void**)&h,     g_h);
    cudaGetSymbolAddress((void**)&xw,    g_xw);
    cudaGetSymbolAddress((void**)&y,     g_y);
    cudaGetSymbolAddress((void**)&h1,    g_h1);
    cudaGetSymbolAddress((void**)&h2,    g_h2);
    cudaGetSymbolAddress((void**)&as_,   g_as);
    cudaGetSymbolAddress((void**)&ad_,   g_ad);
    cudaGetSymbolAddress((void**)&deg,   g_deg);
    cudaGetSymbolAddress((void**)&fill,  g_fill);
    cudaGetSymbolAddress((void**)&rowptr,g_rowptr);
    cudaGetSymbolAddress((void**)&csrc,  g_csrc);
    cudaGetSymbolAddress((void**)&bsum,  g_bsum);
    cudaGetSymbolAddress((void**)&gsum,  g_gsum);
    cudaGetSymbolAddress((void**)&gsq,   g_gsq);
    cudaGetSymbolAddress((void**)&kA,    g_kA);
    cudaGetSymbolAddress((void**)&kB,    g_kB);
    cudaGetSymbolAddress((void**)&cnt,   g_cnt);
    cudaGetSymbolAddress((void**)&Bfuse, g_Bfuse);
    cudaGetSymbolAddress((void**)&Bgat,  g_Bgat);

    cudaFuncSetAttribute(k_tail, cudaFuncAttributeMaxDynamicSharedMemorySize, DYN_SMEM);

    const int TPB = 256;
    const int gRow64     = (Nn + 63) / 64;               // 782 (k_mma tiles)
    const int gRow128    = (Nn + 127) / 128;             // 391 (tail)
    const int gWarpRows  = (Nn * 32 + TPB - 1) / TPB;
    const int gElems     = (Nn * H + TPB - 1) / TPB;
    const int gEdges     = (ET + TPB - 1) / TPB;
    const int gGN        = (Nn + 63) / 64;
    const int gGH        = (G * H + TPB - 1) / TPB;
    const int nScanBlk   = (Nn + 255) / 256;

    // slots 1-3: zero + weight pre-conversion
    k_zero_all<<<(Nn + TPB - 1) / TPB, TPB>>>(deg, fill, cnt);
    k_preconv<<<(TFUSE * 16 * 128 + TPB - 1) / TPB, TPB>>>(W_fuse, Bfuse, Fin, TFUSE * 16);
    k_preconv<<<(TGAT * 16 * 128 + TPB - 1) / TPB, TPB>>>(W_gat, Bgat, H, TGAT * 16);
    // slot 4 (profiled): fuse GEMM + fused LN1 + ReLU -> h
    k_mma<3, true><<<gRow64, 256>>>(
        rna, RNA, ss, Bfuse, b_fuse, h, Nn, Fin, ln1_g, ln1_b, nullptr, nullptr);
    // CSR build
    k_hist<<<gEdges, TPB>>>(ei, deg);
    k_scan1<<<nScanBlk, 256>>>(deg, rowptr, bsum);
    k_scan2<<<1, 256>>>(bsum, nScanBlk);
    k_scan3<<<(Nn + TPB - 1) / TPB, TPB>>>(rowptr, bsum);
    k_scatter<<<gEdges, TPB>>>(ei, rowptr, fill, csrc);
    k_gcount<<<(Nn + TPB - 1) / TPB, TPB>>>(batch, cnt);

    // ---- two GAT + GraphNorm layers ----
    for (int layer = 0; layer < 2; ++layer) {
        const float* xin = (layer == 0) ? h : h1;
        float* dst       = (layer == 0) ? h1 : h2;
        const float* res = (layer == 0) ? nullptr : h;   // h == LN1 output (residual)

        // GAT GEMM with fused attention dot products
        k_mma<2, false><<<gRow64, 256>>>(
            xin, H, nullptr, Bgat, nullptr, xw, Nn, H, attS, attD, as_, ad_);
        k_agg<<<gWarpRows, TPB>>>(rowptr, csrc, as_, ad_, xw, b_gat, y);

        k_zero2_f<<<gGH, TPB>>>(gsum, gsq, G * H);
        k_gn_stats<<<gGN, 256>>>(y, batch, gsum, gsq);
        k_gn_fin<<<gGH, TPB>>>(gsum, gsq, cnt, gn_w, gn_b, gn_ms, kA, kB);
        k_gn_norm<<<gElems, TPB>>>(y, batch, kA, kB, res, dst);
    }

    // ---- fused tail (unchanged) ----
    k_tail<<<gRow128, 256, DYN_SMEM>>>(
        h1, h2, W_gate, b_gate, W_head, b_head, ln2_g, ln2_b,
        W_fc1, b_fc1, ln3_g, ln3_b, W_fc2, b_fc2, out, Nn);
}

// round 17
// speedup vs baseline: 1.4815x; 1.0072x over previous
#include <cuda_runtime.h>
#include <cuda_bf16.h>
#include <math.h>

// ---------------- problem constants ----------------
constexpr int Nn  = 50000;
constexpr int Ee  = 800000;
constexpr int ET  = Ee + Nn;      // + self loops
constexpr int RNA = 645;
constexpr int SSd = 6;
constexpr int Fin = RNA + SSd;    // 651
constexpr int H   = 128;
constexpr int G   = 200;
constexpr float EPS = 1e-5f;

constexpr int BUF_STRIDE = 132;
constexpr int DYN_SMEM   = 128 * BUF_STRIDE * 4;   // 67584 B (tail only)

constexpr int TFUSE = (Fin + 31) / 32;             // 21 k-tiles
constexpr int TGAT  = H / 32;                      // 4 k-tiles

// ---------------- device scratch ----------------
__device__ float g_h    [Nn * H];
__device__ float g_xw   [Nn * H];
__device__ float g_y    [Nn * H];
__device__ float g_h1   [Nn * H];
__device__ float g_h2   [Nn * H];
__device__ float g_as   [Nn];
__device__ float g_ad   [Nn];
__device__ int   g_deg  [Nn];
__device__ int   g_fill [Nn];
__device__ int   g_rowptr[Nn + 1];
__device__ int   g_csrc [ET];
__device__ int   g_bsum [256];
__device__ float g_gsum [G * H];
__device__ float g_gsq  [G * H];
__device__ float g_kA   [G * H];
__device__ float g_kB   [G * H];
__device__ int   g_cnt  [G];
// pre-converted weight planes (u64 = hi bf16x2 | lo bf16x2 << 32), tile-major [kw][n]
__device__ unsigned long long g_Bfuse[TFUSE * 16 * 128];   // 344 KB
__device__ unsigned long long g_Bgat [TGAT  * 16 * 128];   // 64 KB

// ---------------- small utility kernels ----------------
__global__ void k_zero2_f(float* p1, float* p2, int n) {
    int i = blockIdx.x * blockDim.x + threadIdx.x;
    if (i < n) { p1[i] = 0.f; p2[i] = 0.f; }
}
__global__ void k_zero_all(int* deg, int* fill, int* cnt) {
    int i = blockIdx.x * blockDim.x + threadIdx.x;
    if (i < Nn) { deg[i] = 0; fill[i] = 0; }
    if (i < G) cnt[i] = 0;
}

// ---------------- CSR build ----------------
__global__ void k_hist(const int* __restrict__ ei, int* __restrict__ deg) {
    int i = blockIdx.x * blockDim.x + threadIdx.x;
    if (i >= ET) return;
    int dst = (i < Ee) ? ei[Ee + i] : (i - Ee);
    atomicAdd(&deg[dst], 1);
}

__global__ void k_scan1(const int* __restrict__ deg, int* __restrict__ rowptr,
                        int* __restrict__ bsum) {
    __shared__ int sm[256];
    int tx = threadIdx.x;
    int i = blockIdx.x * 256 + tx;
    int v = (i < Nn) ? deg[i] : 0;
    sm[tx] = v;
    __syncthreads();
    for (int off = 1; off < 256; off <<= 1) {
        int t = (tx >= off) ? sm[tx - off] : 0;
        __syncthreads();
        sm[tx] += t;
        __syncthreads();
    }
    if (i < Nn) rowptr[i] = sm[tx] - v;
    if (tx == 255) bsum[blockIdx.x] = sm[255];
}

__global__ void k_scan2(int* __restrict__ bsum, int nblk) {
    __shared__ int sm[256];
    int tx = threadIdx.x;
    int v = (tx < nblk) ? bsum[tx] : 0;
    sm[tx] = v;
    __syncthreads();
    for (int off = 1; off < 256; off <<= 1) {
        int t = (tx >= off) ? sm[tx - off] : 0;
        __syncthreads();
        sm[tx] += t;
        __syncthreads();
    }
    if (tx < nblk) bsum[tx] = sm[tx] - v;
}

__global__ void k_scan3(int* __restrict__ rowptr, const int* __restrict__ bsum) {
    int i = blockIdx.x * blockDim.x + threadIdx.x;
    if (i < Nn) rowptr[i] += bsum[i >> 8];
    if (i == 0) rowptr[Nn] = ET;
}

__global__ void k_scatter(const int* __restrict__ ei, const int* __restrict__ rowptr,
                          int* __restrict__ fill, int* __restrict__ csrc) {
    int i = blockIdx.x * blockDim.x + threadIdx.x;
    if (i >= ET) return;
    int src = (i < Ee) ? ei[i]      : (i - Ee);
    int dst = (i < Ee) ? ei[Ee + i] : (i - Ee);
    int pos = rowptr[dst] + atomicAdd(&fill[dst], 1);
    csrc[pos] = src;
}

__global__ void k_gcount(const int* __restrict__ batch, int* __restrict__ cnt) {
    int i = blockIdx.x * blockDim.x + threadIdx.x;
    if (i < Nn) atomicAdd(&cnt[batch[i]], 1);
}

// ---------------- bf16 mma helpers ----------------
__device__ __forceinline__ void mma_bf16(float* c, const unsigned* a, const unsigned* b) {
    asm volatile(
        "mma.sync.aligned.m16n8k16.row.col.f32.bf16.bf16.f32 "
        "{%0,%1,%2,%3}, {%4,%5,%6,%7}, {%8,%9}, {%0,%1,%2,%3};"
        : "+f"(c[0]), "+f"(c[1]), "+f"(c[2]), "+f"(c[3])
        : "r"(a[0]), "r"(a[1]), "r"(a[2]), "r"(a[3]), "r"(b[0]), "r"(b[1]));
}
__device__ __forceinline__ unsigned pack_bf16x2(float x0, float x1) {
    unsigned p;
    asm("cvt.rn.bf16x2.f32 %0, %1, %2;" : "=r"(p) : "f"(x1), "f"(x0));
    return p;
}
__device__ __forceinline__ void split_pair(float x0, float x1, unsigned& ph, unsigned& pl) {
    ph = pack_bf16x2(x0, x1);
    float h0 = __uint_as_float(ph << 16);
    float h1 = __uint_as_float(ph & 0xffff0000u);
    pl = pack_bf16x2(x0 - h0, x1 - h1);
}
__device__ __forceinline__ unsigned long long pack_hl(unsigned ph, unsigned pl) {
    return (unsigned long long)pl << 32 | ph;
}
__device__ __forceinline__ void cpa16(void* dst, const void* src) {
    unsigned d = (unsigned)__cvta_generic_to_shared(dst);
    asm volatile("cp.async.cg.shared.global [%0], [%1], 16;" :: "r"(d), "l"(src));
}
__device__ __forceinline__ void cpa_commit() {
    asm volatile("cp.async.commit_group;");
}
template <int NN>
__device__ __forceinline__ void cpa_wait() {
    asm volatile("cp.async.wait_group %0;" :: "n"(NN));
}

constexpr int KW = 20;   // 32-bit plane stride for k_tail (16 data + 4 pad)

// ---------------- weight pre-conversion: fp32 [Ktot x 128] -> u64 planes [kw][n] ----------------
__global__ void k_preconv(const float* __restrict__ W, unsigned long long* __restrict__ outp,
                          int Ktot, int nWords) {
    int i = blockIdx.x * blockDim.x + threadIdx.x;
    if (i >= nWords * 128) return;
    int kw = i >> 7, n = i & 127;
    int k0 = kw * 2;
    float x0 = (k0     < Ktot) ? W[(size_t)k0 * 128 + n]       : 0.f;
    float x1 = (k0 + 1 < Ktot) ? W[(size_t)(k0 + 1) * 128 + n] : 0.f;
    unsigned ph, pl;
    split_pair(x0, x1, ph, pl);
    outp[i] = pack_hl(ph, pl);
}

// ---------------- tensor-core GEMM, BM=64 x BN=128, paired-u64 planes ----------------
// Single-barrier pipeline: A planes and B tiles both double-buffered.
// EPI 2: write C=xw, plus row dots with p1 (att_src) / p2 (att_dst) -> as_/ad_
// EPI 3: bias add, row-LN(p1=g, p2=b) + ReLU in-register -> C
template <int EPI, bool SCALAR_A>
__global__ void __launch_bounds__(256, 2)
k_mma(const float* __restrict__ A0, int K0,
      const float* __restrict__ A1,
      const unsigned long long* __restrict__ Bpre,
      const float* __restrict__ bias,
      float* __restrict__ C, int M, int Ktot,
      const float* __restrict__ p1, const float* __restrict__ p2,
      float* __restrict__ as_, float* __restrict__ ad_) {
    constexpr int BM = 64, BK = 32;
    constexpr int AELT = 8;
    constexpr int ASTR = 20;          // u64 per A row (16 used)
    constexpr int BSTR = 132;         // u64 per B k-word row (128 used)

    __shared__ unsigned long long As64[2][BM * ASTR];                 // 20.5 KB
    __shared__ __align__(16) unsigned long long Bs64[2][16 * BSTR];   // 33.8 KB
    __shared__ float rb1[BM * 4], rb2[BM * 4];

    const int tid  = threadIdx.x;
    const int wid  = tid >> 5;
    const int lane = tid & 31;
    const int wr   = wid >> 2;          // 0..1 over M (32 rows each)
    const int wc   = wid & 3;           // 0..3 over N (32 cols each)
    const int rowBase = blockIdx.x * BM;
    const int K1 = Ktot - K0;

    // A load: 64 rows x 32 k, 8 per thread
    const int ar = tid >> 2, ac = (tid & 3) * 8;
    const int am = rowBase + ar;
    const bool amv = am < M;

    float aReg[AELT];
    float acc[2][4][4];
#pragma unroll
    for (int a = 0; a < 2; ++a)
#pragma unroll
        for (int b = 0; b < 4; ++b)
#pragma unroll
            for (int cc = 0; cc < 4; ++cc) acc[a][b][cc] = 0.f;

    const int T = (Ktot + BK - 1) / BK;

    auto gload = [&](int t) {
        const int k0 = t * BK;
        if (SCALAR_A) {
            if (k0 + BK <= K0) {
                const float* base = A0 + (size_t)am * K0 + k0 + ac;
#pragma unroll
                for (int j = 0; j < AELT; ++j) aReg[j] = amv ? base[j] : 0.f;
            } else {
#pragma unroll
                for (int j = 0; j < AELT; ++j) {
                    int k = k0 + ac + j;
                    float v = 0.f;
                    if (amv && k < Ktot)
                        v = (k < K0) ? A0[(size_t)am * K0 + k]
                                     : A1[(size_t)am * K1 + (k - K0)];
                    aReg[j] = v;
                }
            }
        } else {
#pragma unroll
            for (int j4 = 0; j4 < AELT / 4; ++j4) {
                int k = k0 + ac + j4 * 4;
                float4 v = make_float4(0.f, 0.f, 0.f, 0.f);
                if (amv) {
                    const float* p = (k < K0) ? (A0 + (size_t)am * K0 + k)
                                              : (A1 + (size_t)am * K1 + (k - K0));
                    v = *reinterpret_cast<const float4*>(p);
                }
                aReg[j4 * 4 + 0] = v.x; aReg[j4 * 4 + 1] = v.y;
                aReg[j4 * 4 + 2] = v.z; aReg[j4 * 4 + 3] = v.w;
            }
        }
    };

    auto convertA = [&](int ab) {
#pragma unroll
        for (int j = 0; j < AELT; j += 2) {
            unsigned ph, pl;
            split_pair(aReg[j], aReg[j + 1], ph, pl);
            As64[ab][ar * ASTR + ((ac + j) >> 1)] = pack_hl(ph, pl);
        }
    };

    // B tile fetch: 16KB via 4x cp.async 16B per thread
    auto bload = [&](int t, int buf) {
        const unsigned long long* src = Bpre + (size_t)t * 2048 + tid * 8;
        unsigned long long* dst = &Bs64[buf][(tid >> 4) * BSTR + (tid & 15) * 8];
        cpa16(dst,     src);
        cpa16(dst + 2, src + 2);
        cpa16(dst + 4, src + 4);
        cpa16(dst + 6, src + 6);
        cpa_commit();
    };

    // pipeline preamble
    gload(0);
    bload(0, 0);
    convertA(0);
    if (1 < T) gload(1);

    for (int t = 0; t < T; ++t) {
        const int buf = t & 1;
        cpa_wait<0>();            // B[buf] landed
        __syncthreads();          // A[buf] convert visible; mma(t-1) done everywhere
        if (t + 1 < T) bload(t + 1, buf ^ 1);

        const unsigned long long* Bb = Bs64[buf];
        const unsigned long long* Ab = As64[buf];
#pragma unroll
        for (int ks = 0; ks < 2; ++ks) {
            const int kw = ks * 8 + (lane & 3);
            unsigned bh[4][2], bl[4][2];
#pragma unroll
            for (int nt = 0; nt < 4; ++nt) {
                int n = wc * 32 + nt * 8 + (lane >> 2);
                unsigned long long v0 = Bb[kw * BSTR + n];
                unsigned long long v1 = Bb[(kw + 4) * BSTR + n];
                bh[nt][0] = (unsigned)v0; bl[nt][0] = (unsigned)(v0 >> 32);
                bh[nt][1] = (unsigned)v1; bl[nt][1] = (unsigned)(v1 >> 32);
            }
#pragma unroll
            for (int mt = 0; mt < 2; ++mt) {
                int r = wr * 32 + mt * 16 + (lane >> 2);
                unsigned ah[4], al[4];
                unsigned long long a0 = Ab[r * ASTR + kw];
                unsigned long long a1 = Ab[(r + 8) * ASTR + kw];
                unsigned long long a2 = Ab[r * ASTR + kw + 4];
                unsigned long long a3 = Ab[(r + 8) * ASTR + kw + 4];
                ah[0] = (unsigned)a0; al[0] = (unsigned)(a0 >> 32);
                ah[1] = (unsigned)a1; al[1] = (unsigned)(a1 >> 32);
                ah[2] = (unsigned)a2; al[2] = (unsigned)(a2 >> 32);
                ah[3] = (unsigned)a3; al[3] = (unsigned)(a3 >> 32);
#pragma unroll
                for (int nt = 0; nt < 4; ++nt) {
                    mma_bf16(acc[mt][nt], ah, bh[nt]);
                    mma_bf16(acc[mt][nt], ah, bl[nt]);
                    mma_bf16(acc[mt][nt], al, bh[nt]);
                }
            }
        }
        if (t + 1 < T) {
            convertA(buf ^ 1);    // overlaps other warps' mma(t)
            if (t + 2 < T) gload(t + 2);
        }
    }

    if (EPI == 2) {
        // write xw + fused attention dot products
        float aS[4][2], aD[4][2];
#pragma unroll
        for (int nt = 0; nt < 4; ++nt) {
            int c = wc * 32 + nt * 8 + (lane & 3) * 2;
            aS[nt][0] = p1[c]; aS[nt][1] = p1[c + 1];
            aD[nt][0] = p2[c]; aD[nt][1] = p2[c + 1];
        }
#pragma unroll
        for (int mt = 0; mt < 2; ++mt) {
#pragma unroll
            for (int hrow = 0; hrow < 2; ++hrow) {
                float s1 = 0.f, s2 = 0.f;
                int r = wr * 32 + mt * 16 + (lane >> 2) + hrow * 8;
                int gr = rowBase + r;
#pragma unroll
                for (int nt = 0; nt < 4; ++nt) {
                    int c = wc * 32 + nt * 8 + (lane & 3) * 2;
                    float v0 = acc[mt][nt][hrow * 2 + 0];
                    float v1 = acc[mt][nt][hrow * 2 + 1];
                    s1 += v0 * aS[nt][0] + v1 * aS[nt][1];
                    s2 += v0 * aD[nt][0] + v1 * aD[nt][1];
                    if (gr < M)
                        *reinterpret_cast<float2*>(&C[(size_t)gr * 128 + c]) =
                            make_float2(v0, v1);
                }
                s1 += __shfl_xor_sync(0xffffffffu, s1, 1);
                s1 += __shfl_xor_sync(0xffffffffu, s1, 2);
                s2 += __shfl_xor_sync(0xffffffffu, s2, 1);
                s2 += __shfl_xor_sync(0xffffffffu, s2, 2);
                if ((lane & 3) == 0) { rb1[r * 4 + wc] = s1; rb2[r * 4 + wc] = s2; }
            }
        }
        __syncthreads();
        if (tid < BM) {
            int gr = rowBase + tid;
            if (gr < M) {
                as_[gr] = rb1[tid * 4] + rb1[tid * 4 + 1] + rb1[tid * 4 + 2] + rb1[tid * 4 + 3];
                ad_[gr] = rb2[tid * 4] + rb2[tid * 4 + 1] + rb2[tid * 4 + 2] + rb2[tid * 4 + 3];
            }
        }
    } else {
        // EPI == 3: bias + in-register LayerNorm + ReLU
#pragma unroll
        for (int mt = 0; mt < 2; ++mt) {
#pragma unroll
            for (int hrow = 0; hrow < 2; ++hrow) {
                float s = 0.f, q = 0.f;
                int r = wr * 32 + mt * 16 + (lane >> 2) + hrow * 8;
#pragma unroll
                for (int nt = 0; nt < 4; ++nt) {
                    int c = wc * 32 + nt * 8 + (lane & 3) * 2;
                    float v0 = acc[mt][nt][hrow * 2 + 0] + bias[c];
                    float v1 = acc[mt][nt][hrow * 2 + 1] + bias[c + 1];
                    acc[mt][nt][hrow * 2 + 0] = v0;
                    acc[mt][nt][hrow * 2 + 1] = v1;
                    s += v0 + v1;
                    q += v0 * v0 + v1 * v1;
                }
                s += __shfl_xor_sync(0xffffffffu, s, 1);
                s += __shfl_xor_sync(0xffffffffu, s, 2);
                q += __shfl_xor_sync(0xffffffffu, q, 1);
                q += __shfl_xor_sync(0xffffffffu, q, 2);
                if ((lane & 3) == 0) { rb1[r * 4 + wc] = s; rb2[r * 4 + wc] = q; }
            }
        }
        __syncthreads();
#pragma unroll
        for (int mt = 0; mt < 2; ++mt) {
#pragma unroll
            for (int hrow = 0; hrow < 2; ++hrow) {
                int r = wr * 32 + mt * 16 + (lane >> 2) + hrow * 8;
                int gr = rowBase + r;
                float s = rb1[r * 4] + rb1[r * 4 + 1] + rb1[r * 4 + 2] + rb1[r * 4 + 3];
                float q = rb2[r * 4] + rb2[r * 4 + 1] + rb2[r * 4 + 2] + rb2[r * 4 + 3];
                float mean = s * (1.f / 128.f);
                float var  = q * (1.f / 128.f) - mean * mean;
                float is = rsqrtf(var + EPS);
                if (gr < M) {
#pragma unroll
                    for (int nt = 0; nt < 4; ++nt) {
                        int c = wc * 32 + nt * 8 + (lane & 3) * 2;
                        float o0 = fmaxf((acc[mt][nt][hrow * 2 + 0] - mean) * is * p1[c]     + p2[c],     0.f);
                        float o1 = fmaxf((acc[mt][nt][hrow * 2 + 1] - mean) * is * p1[c + 1] + p2[c + 1], 0.f);
                        *reinterpret_cast<float2*>(&C[(size_t)gr * 128 + c]) = make_float2(o0, o1);
                    }
                }
            }
        }
    }
}

// ---------------- fused tail (unchanged): gate + combine + head + LN2 + fc1 + LN3 + fc2 ----------------
__global__ void __launch_bounds__(256)
k_tail(const float* __restrict__ h1, const float* __restrict__ h2,
       const float* __restrict__ Wg,  const float* __restrict__ bg,
       const float* __restrict__ Wh,  const float* __restrict__ bhd,
       const float* __restrict__ g2,  const float* __restrict__ b2,
       const float* __restrict__ Wf1, const float* __restrict__ bf1,
       const float* __restrict__ g3,  const float* __restrict__ b3,
       const float* __restrict__ Wf2, const float* __restrict__ bf2,
       float* __restrict__ out, int M) {
    __shared__ unsigned AsH[128 * KW], AsL[128 * KW];
    __shared__ unsigned BsH[128 * KW], BsL[128 * KW];
    extern __shared__ float dbuf[];

    const int tid  = threadIdx.x;
    const int wid  = tid >> 5;
    const int lane = tid & 31;
    const int rowBase = blockIdx.x * 128;
    const int ar = tid >> 1, ac = (tid & 1) * 16;
    const int am = rowBase + ar;

    float aReg[16], bReg[16];
    float acc[4][4][4];

    auto convertA = [&]() {
#pragma unroll
        for (int j = 0; j < 16; j += 2) {
            unsigned ph, pl;
            split_pair(aReg[j], aReg[j + 1], ph, pl);
            int wi = ar * KW + ((ac + j) >> 1);
            AsH[wi] = ph; AsL[wi] = pl;
        }
    };

    auto mma128 = [&](int wr, int wc) {
#pragma unroll
        for (int ks = 0; ks < 2; ++ks) {
            unsigned bh[4][2], bl[4][2];
#pragma unroll
            for (int nt = 0; nt < 4; ++nt) {
                int n  = wc * 32 + nt * 8 + (lane >> 2);
                int kw = ks * 8 + (lane & 3);
                bh[nt][0] = BsH[n * KW + kw];     bl[nt][0] = BsL[n * KW + kw];
                bh[nt][1] = BsH[n * KW + kw + 4]; bl[nt][1] = BsL[n * KW + kw + 4];
            }
#pragma unroll
            for (int mt = 0; mt < 4; ++mt) {
                int r  = wr * 64 + mt * 16 + (lane >> 2);
                int kw = ks * 8 + (lane & 3);
                unsigned ah[4], al[4];
                ah[0] = AsH[r * KW + kw];           al[0] = AsL[r * KW + kw];
                ah[1] = AsH[(r + 8) * KW + kw];     al[1] = AsL[(r + 8) * KW + kw];
                ah[2] = AsH[r * KW + kw + 4];       al[2] = AsL[r * KW + kw + 4];
                ah[3] = AsH[(r + 8) * KW + kw + 4]; al[3] = AsL[(r + 8) * KW + kw + 4];
#pragma unroll
                for (int nt = 0; nt < 4; ++nt) {
                    mma_bf16(acc[mt][nt], ah, bh[nt]);
                    mma_bf16(acc[mt][nt], ah, bl[nt]);
                    mma_bf16(acc[mt][nt], al, bh[nt]);
                }
            }
        }
    };

    auto zacc = [&]() {
#pragma unroll
        for (int a = 0; a < 4; ++a)
#pragma unroll
            for (int b = 0; b < 4; ++b)
#pragma unroll
                for (int cc = 0; cc < 4; ++cc) acc[a][b][cc] = 0.f;
    };

    // ================= stage 0: gate GEMM (K=256, N=128) =================
    {
        const int wr = wid >> 2, wc = wid & 3;
        const int bn = tid & 127, bk0 = (tid >> 7) * 16;
        zacc();
        auto gload = [&](int t) {
            const int k0 = t * 32;
#pragma unroll
            for (int j4 = 0; j4 < 4; ++j4) {
                int k = k0 + ac + j4 * 4;
                float4 v = make_float4(0.f, 0.f, 0.f, 0.f);
                if (am < M) {
                    const float* p = (k < 128) ? (h1 + (size_t)am * 128 + k)
                                               : (h2 + (size_t)am * 128 + (k - 128));
                    v = *reinterpret_cast<const float4*>(p);
                }
                aReg[j4 * 4 + 0] = v.x; aReg[j4 * 4 + 1] = v.y;
                aReg[j4 * 4 + 2] = v.z; aReg[j4 * 4 + 3] = v.w;
            }
#pragma unroll
            for (int j = 0; j < 16; ++j)
                bReg[j] = Wg[(size_t)(k0 + bk0 + j) * 128 + bn];
        };
        auto convertB = [&]() {
#pragma unroll
            for (int j = 0; j < 16; j += 2) {
                unsigned ph, pl;
                split_pair(bReg[j], bReg[j + 1], ph, pl);
                int wi = bn * KW + ((bk0 + j) >> 1);
                BsH[wi] = ph; BsL[wi] = pl;
            }
        };
        gload(0);
        for (int t = 0; t < 8; ++t) {
            __syncthreads();
            convertA(); convertB();
            __syncthreads();
            if (t + 1 < 8) gload(t + 1);
            mma128(wr, wc);
        }
        // epilogue: sigmoid gate + combine -> dbuf
#pragma unroll
        for (int mt = 0; mt < 4; ++mt) {
            int rl = wr * 64 + mt * 16 + (lane >> 2);
#pragma unroll
            for (int nt = 0; nt < 4; ++nt) {
                int c = wc * 32 + nt * 8 + (lane & 3) * 2;
#pragma unroll
                for (int hrow = 0; hrow < 2; ++hrow) {
                    int r = rl + hrow * 8;
                    int gr = rowBase + r;
                    float o0 = 0.f, o1 = 0.f;
                    if (gr < M) {
                        size_t idx = (size_t)gr * 128 + c;
                        float v0 = acc[mt][nt][hrow * 2 + 0] + bg[c];
                        float v1 = acc[mt][nt][hrow * 2 + 1] + bg[c + 1];
                        float s0 = 1.f / (1.f + __expf(-v0));
                        float s1 = 1.f / (1.f + __expf(-v1));
                        o0 = s0 * h1[idx]     + (1.f - s0) * h2[idx];
                        o1 = s1 * h1[idx + 1] + (1.f - s1) * h2[idx + 1];
                    }
                    dbuf[r * BUF_STRIDE + c]     = o0;
                    dbuf[r * BUF_STRIDE + c + 1] = o1;
                }
            }
        }
    }

    // ================= stage 1: head GEMM (K=128, N=128), A from dbuf =================
    {
        const int wr = wid >> 2, wc = wid & 3;
        const int bn = tid & 127, bk0 = (tid >> 7) * 16;
        zacc();
        for (int t = 0; t < 4; ++t) {
            const int k0 = t * 32;
            __syncthreads();
#pragma unroll
            for (int j = 0; j < 16; ++j) aReg[j] = dbuf[ar * BUF_STRIDE + k0 + ac + j];
            convertA();
#pragma unroll
            for (int j = 0; j < 16; j += 2) {
                float x0 = Wh[(size_t)(k0 + bk0 + j) * 128 + bn];
                float x1 = Wh[(size_t)(k0 + bk0 + j + 1) * 128 + bn];
                unsigned ph, pl;
                split_pair(x0, x1, ph, pl);
                int wi = bn * KW + ((bk0 + j) >> 1);
                BsH[wi] = ph; BsL[wi] = pl;
            }
            __syncthreads();
            mma128(wr, wc);
        }
#pragma unroll
        for (int mt = 0; mt < 4; ++mt) {
            int rl = wr * 64 + mt * 16 + (lane >> 2);
#pragma unroll
            for (int nt = 0; nt < 4; ++nt) {
                int c = wc * 32 + nt * 8 + (lane & 3) * 2;
#pragma unroll
                for (int hrow = 0; hrow < 2; ++hrow) {
                    int r = rl + hrow * 8;
                    dbuf[r * BUF_STRIDE + c]     = acc[mt][nt][hrow * 2 + 0] + bhd[c];
                    dbuf[r * BUF_STRIDE + c + 1] = acc[mt][nt][hrow * 2 + 1] + bhd[c + 1];
                }
            }
        }
    }
    __syncthreads();

    // ================= LN2 + ReLU in place =================
#pragma unroll 1
    for (int i = 0; i < 16; ++i) {
        int r = wid * 16 + i;
        float v[4]; float s = 0.f;
#pragma unroll
        for (int j = 0; j < 4; ++j) { v[j] = dbuf[r * BUF_STRIDE + lane + 32 * j]; s += v[j]; }
        for (int o = 16; o; o >>= 1) s += __shfl_xor_sync(0xffffffffu, s, o);
        float mean = s * (1.f / 128.f);
        float var = 0.f;
#pragma unroll
        for (int j = 0; j < 4; ++j) { float d = v[j] - mean; var += d * d; }
        for (int o = 16; o; o >>= 1) var += __shfl_xor_sync(0xffffffffu, var, o);
        float is = rsqrtf(var * (1.f / 128.f) + EPS);
#pragma unroll
        for (int j = 0; j < 4; ++j) {
            int c = lane + 32 * j;
            dbuf[r * BUF_STRIDE + c] = fmaxf((v[j] - mean) * is * g2[c] + b2[c], 0.f);
        }
    }
    __syncthreads();

    // ================= stage 2: fc1 GEMM (K=128, N=64) =================
    {
        const int wr = wid >> 1, wc = wid & 1;
        const int bn = tid & 63, bk0 = (tid >> 6) * 8;
        zacc();
        for (int t = 0; t < 4; ++t) {
            const int k0 = t * 32;
            __syncthreads();
#pragma unroll
            for (int j = 0; j < 16; ++j) aReg[j] = dbuf[ar * BUF_STRIDE + k0 + ac + j];
            convertA();
#pragma unroll
            for (int j = 0; j < 8; j += 2) {
                float x0 = Wf1[(size_t)(k0 + bk0 + j) * 64 + bn];
                float x1 = Wf1[(size_t)(k0 + bk0 + j + 1) * 64 + bn];
                unsigned ph, pl;
                split_pair(x0, x1, ph, pl);
                int wi = bn * KW + ((bk0 + j) >> 1);
                BsH[wi] = ph; BsL[wi] = pl;
            }
            __syncthreads();
#pragma unroll
            for (int ks = 0; ks < 2; ++ks) {
                unsigned bh[4][2], bl[4][2];
#pragma unroll
                for (int nt = 0; nt < 4; ++nt) {
                    int n  = wc * 32 + nt * 8 + (lane >> 2);
                    int kw = ks * 8 + (lane & 3);
                    bh[nt][0] = BsH[n * KW + kw];     bl[nt][0] = BsL[n * KW + kw];
                    bh[nt][1] = BsH[n * KW + kw + 4]; bl[nt][1] = BsL[n * KW + kw + 4];
                }
#pragma unroll
                for (int mt = 0; mt < 2; ++mt) {
                    int r  = wr * 32 + mt * 16 + (lane >> 2);
                    int kw = ks * 8 + (lane & 3);
                    unsigned ah[4], al[4];
                    ah[0] = AsH[r * KW + kw];           al[0] = AsL[r * KW + kw];
                    ah[1] = AsH[(r + 8) * KW + kw];     al[1] = AsL[(r + 8) * KW + kw];
                    ah[2] = AsH[r * KW + kw + 4];       al[2] = AsL[r * KW + kw + 4];
                    ah[3] = AsH[(r + 8) * KW + kw + 4]; al[3] = AsL[(r + 8) * KW + kw + 4];
#pragma unroll
                    for (int nt = 0; nt < 4; ++nt) {
                        mma_bf16(acc[mt][nt], ah, bh[nt]);
                        mma_bf16(acc[mt][nt], ah, bl[nt]);
                        mma_bf16(acc[mt][nt], al, bh[nt]);
                    }
                }
            }
        }
#pragma unroll
        for (int mt = 0; mt < 2; ++mt) {
            int rl = wr * 32 + mt * 16 + (lane >> 2);
#pragma unroll
            for (int nt = 0; nt < 4; ++nt) {
                int c = wc * 32 + nt * 8 + (lane & 3) * 2;
#pragma unroll
                for (int hrow = 0; hrow < 2; ++hrow) {
                    int r = rl + hrow * 8;
                    dbuf[r * 68 + c]     = acc[mt][nt][hrow * 2 + 0] + bf1[c];
                    dbuf[r * 68 + c + 1] = acc[mt][nt][hrow * 2 + 1] + bf1[c + 1];
                }
            }
        }
    }
    __syncthreads();

    // ================= LN3 + ReLU + fc2 =================
    {
        float w0 = Wf2[lane], w1 = Wf2[lane + 32];
#pragma unroll 1
        for (int i = 0; i < 16; ++i) {
            int r = wid * 16 + i;
            int gr = rowBase + r;
            float x0 = dbuf[r * 68 + lane];
            float x1 = dbuf[r * 68 + lane + 32];
            float s = x0 + x1;
            for (int o = 16; o; o >>= 1) s += __shfl_xor_sync(0xffffffffu, s, o);
            float mean = s * (1.f / 64.f);
            float d0 = x0 - mean, d1 = x1 - mean;
            float var = d0 * d0 + d1 * d1;
            for (int o = 16; o; o >>= 1) var += __shfl_xor_sync(0xffffffffu, var, o);
            float is = rsqrtf(var * (1.f / 64.f) + EPS);
            float n0 = fmaxf(d0 * is * g3[lane]      + b3[lane],      0.f);
            float n1 = fmaxf(d1 * is * g3[lane + 32] + b3[lane + 32], 0.f);
            float dot = n0 * w0 + n1 * w1;
            for (int o = 16; o; o >>= 1) dot += __shfl_xor_sync(0xffffffffu, dot, o);
            if (lane == 0 && gr < M) out[gr] = dot + bf2[0];
        }
    }
}

// ---------------- GAT aggregate (warp per dst node, online softmax) ----------------
__device__ __forceinline__ float lrelu(float x) { return x > 0.f ? x : 0.2f * x; }

__global__ void k_agg(const int* __restrict__ rowptr, const int* __restrict__ csrc,
                      const float* __restrict__ as_, const float* __restrict__ ad_,
                      const float* __restrict__ xw, const float* __restrict__ bias,
                      float* __restrict__ y) {
    int w = (blockIdx.x * blockDim.x + threadIdx.x) >> 5;
    if (w >= Nn) return;
    int lane = threadIdx.x & 31;
    int s0 = rowptr[w], s1 = rowptr[w + 1];
    float adn = ad_[w];

    // one-pass online softmax stats (m, s) per lane
    float m = -1e30f, s = 0.f;
    for (int i = s0 + lane; i < s1; i += 32) {
        float e = lrelu(as_[csrc[i]] + adn);
        if (e > m) { s *= __expf(m - e); m = e; }
        s += __expf(e - m);
    }
    // cross-lane merge
    for (int o = 16; o; o >>= 1) {
        float mo = __shfl_xor_sync(0xffffffffu, m, o);
        float so = __shfl_xor_sync(0xffffffffu, s, o);
        float mn = fmaxf(m, mo);
        s = s * __expf(m - mn) + so * __expf(mo - mn);
        m = mn;
    }
    float inv = 1.f / (s + 1e-16f);

    float4 acc = make_float4(0.f, 0.f, 0.f, 0.f);
    for (int i = s0; i < s1; ++i) {
        int src = csrc[i];
        float al = __expf(lrelu(as_[src] + adn) - m) * inv;
        const float4 v = *reinterpret_cast<const float4*>(&xw[(size_t)src * H + lane * 4]);
        acc.x += al * v.x; acc.y += al * v.y; acc.z += al * v.z; acc.w += al * v.w;
    }
    const float4 bv = *reinterpret_cast<const float4*>(&bias[lane * 4]);
    float4 o = make_float4(acc.x + bv.x, acc.y + bv.y, acc.z + bv.z, acc.w + bv.w);
    *reinterpret_cast<float4*>(&y[(size_t)w * H + lane * 4]) = o;
}

// ---------------- GraphNorm: one-pass stats ----------------
__global__ void k_gn_stats(const float* __restrict__ y, const int* __restrict__ batch,
                           float* __restrict__ gsum, float* __restrict__ gsq) {
    int col  = threadIdx.x & (H - 1);
    int half = threadIdx.x >> 7;
    int r0 = blockIdx.x * 64 + half * 32;
    int r1 = min(r0 + 32, Nn);
    float a1 = 0.f, a2 = 0.f; int cur = -1;
    for (int r = r0; r < r1; ++r) {
        int gg = batch[r];
        if (gg != cur) {
            if (cur >= 0) {
                atomicAdd(&gsum[cur * H + col], a1);
                atomicAdd(&gsq [cur * H + col], a2);
            }
            a1 = 0.f; a2 = 0.f; cur = gg;
        }
        float v = y[(size_t)r * H + col];
        a1 += v; a2 += v * v;
    }
    if (cur >= 0) {
        atomicAdd(&gsum[cur * H + col], a1);
        atomicAdd(&gsq [cur * H + col], a2);
    }
}

__global__ void k_gn_fin(const float* __restrict__ gsum, const float* __restrict__ gsq,
                         const int* __restrict__ cnt,
                         const float* __restrict__ w, const float* __restrict__ b,
                         const float* __restrict__ ms,
                         float* __restrict__ kA, float* __restrict__ kB) {
    int i = blockIdx.x * blockDim.x + threadIdx.x;
    if (i >= G * H) return;
    int col = i & (H - 1);
    float c = fmaxf((float)cnt[i >> 7], 1.f);
    float mean = gsum[i] / c;
    float q    = gsq[i] / c;
    float msv  = ms[col];
    float var = q - msv * (2.f - msv) * mean * mean;
    float is = rsqrtf(var + EPS);
    float a = w[col] * is;
    kA[i] = a;
    kB[i] = b[col] - a * msv * mean;
}

__global__ void k_gn_norm(const float* __restrict__ y, const int* __restrict__ batch,
                          const float* __restrict__ kA, const float* __restrict__ kB,
                          const float* __restrict__ res, float* __restrict__ out) {
    int i = blockIdx.x * blockDim.x + threadIdx.x;
    if (i >= Nn * H) return;
    int row = i >> 7;
    int col = i & (H - 1);
    int gi = batch[row] * H + col;
    float v = fmaxf(fmaf(y[i], kA[gi], kB[gi]), 0.f);
    if (res) v += res[i];
    out[i] = v;
}

// =====================================================================
extern "C" void kernel_launch(void* const* d_in, const int* in_sizes, int n_in,
                              void* d_out, int out_size) {
    const float* rna    = (const float*)d_in[0];
    const float* ss     = (const float*)d_in[1];
    const int*   ei     = (const int*)  d_in[2];
    const int*   batch  = (const int*)  d_in[3];
    const float* W_fuse = (const float*)d_in[4];
    const float* b_fuse = (const float*)d_in[5];
    const float* ln1_g  = (const float*)d_in[6];
    const float* ln1_b  = (const float*)d_in[7];
    const float* W_gat  = (const float*)d_in[8];
    const float* attS   = (const float*)d_in[9];
    const float* attD   = (const float*)d_in[10];
    const float* b_gat  = (const float*)d_in[11];
    const float* gn_w   = (const float*)d_in[12];
    const float* gn_b   = (const float*)d_in[13];
    const float* gn_ms  = (const float*)d_in[14];
    const float* W_gate = (const float*)d_in[15];
    const float* b_gate = (const float*)d_in[16];
    const float* W_head = (const float*)d_in[17];
    const float* b_head = (const float*)d_in[18];
    const float* ln2_g  = (const float*)d_in[19];
    const float* ln2_b  = (const float*)d_in[20];
    const float* W_fc1  = (const float*)d_in[21];
    const float* b_fc1  = (const float*)d_in[22];
    const float* ln3_g  = (const float*)d_in[23];
    const float* ln3_b  = (const float*)d_in[24];
    const float* W_fc2  = (const float*)d_in[25];
    const float* b_fc2  = (const float*)d_in[26];
    float* out = (float*)d_out;

    float *h, *xw, *y, *h1, *h2, *as_, *ad_;
    float *gsum, *gsq, *kA, *kB;
    int *deg, *fill, *rowptr, *csrc, *cnt, *bsum;
    unsigned long long *Bfuse, *Bgat;
    cudaGetSymbolAddress((void**)&h,     g_h);
    cudaGetSymbolAddress((void**)&xw,    g_xw);
    cudaGetSymbolAddress((void**)&y,     g_y);
    cudaGetSymbolAddress((void**)&h1,    g_h1);
    cudaGetSymbolAddress((void**)&h2,    g_h2);
    cudaGetSymbolAddress((void**)&as_,   g_as);
    cudaGetSymbolAddress((void**)&ad_,   g_ad);
    cudaGetSymbolAddress((void**)&deg,   g_deg);
    cudaGetSymbolAddress((void**)&fill,  g_fill);
    cudaGetSymbolAddress((void**)&rowptr,g_rowptr);
    cudaGetSymbolAddress((void**)&csrc,  g_csrc);
    cudaGetSymbolAddress((void**)&bsum,  g_bsum);
    cudaGetSymbolAddress((void**)&gsum,  g_gsum);
    cudaGetSymbolAddress((void**)&gsq,   g_gsq);
    cudaGetSymbolAddress((void**)&kA,    g_kA);
    cudaGetSymbolAddress((void**)&kB,    g_kB);
    cudaGetSymbolAddress((void**)&cnt,   g_cnt);
    cudaGetSymbolAddress((void**)&Bfuse, g_Bfuse);
    cudaGetSymbolAddress((void**)&Bgat,  g_Bgat);

    cudaFuncSetAttribute(k_tail, cudaFuncAttributeMaxDynamicSharedMemorySize, DYN_SMEM);

    const int TPB = 256;
    const int gRow64     = (Nn + 63) / 64;               // 782 (k_mma tiles)
    const int gRow128    = (Nn + 127) / 128;             // 391 (tail)
    const int gWarpRows  = (Nn * 32 + TPB - 1) / TPB;
    const int gElems     = (Nn * H + TPB - 1) / TPB;
    const int gEdges     = (ET + TPB - 1) / TPB;
    const int gGN        = (Nn + 63) / 64;
    const int gGH        = (G * H + TPB - 1) / TPB;
    const int nScanBlk   = (Nn + 255) / 256;

    // slots 1-3: zero + weight pre-conversion
    k_zero_all<<<(Nn + TPB - 1) / TPB, TPB>>>(deg, fill, cnt);
    k_preconv<<<(TFUSE * 16 * 128 + TPB - 1) / TPB, TPB>>>(W_fuse, Bfuse, Fin, TFUSE * 16);
    k_preconv<<<(TGAT * 16 * 128 + TPB - 1) / TPB, TPB>>>(W_gat, Bgat, H, TGAT * 16);
    // slot 4 (profiled): fuse GEMM + fused LN1 + ReLU -> h
    k_mma<3, true><<<gRow64, 256>>>(
        rna, RNA, ss, Bfuse, b_fuse, h, Nn, Fin, ln1_g, ln1_b, nullptr, nullptr);
    // CSR build
    k_hist<<<gEdges, TPB>>>(ei, deg);
    k_scan1<<<nScanBlk, 256>>>(deg, rowptr, bsum);
    k_scan2<<<1, 256>>>(bsum, nScanBlk);
    k_scan3<<<(Nn + TPB - 1) / TPB, TPB>>>(rowptr, bsum);
    k_scatter<<<gEdges, TPB>>>(ei, rowptr, fill, csrc);
    k_gcount<<<(Nn + TPB - 1) / TPB, TPB>>>(batch, cnt);

    // ---- two GAT + GraphNorm layers ----
    for (int layer = 0; layer < 2; ++layer) {
        const float* xin = (layer == 0) ? h : h1;
        float* dst       = (layer == 0) ? h1 : h2;
        const float* res = (layer == 0) ? nullptr : h;   // h == LN1 output (residual)

        // GAT GEMM with fused attention dot products
        k_mma<2, false><<<gRow64, 256>>>(
            xin, H, nullptr, Bgat, nullptr, xw, Nn, H, attS, attD, as_, ad_);
        k_agg<<<gWarpRows, TPB>>>(rowptr, csrc, as_, ad_, xw, b_gat, y);

        k_zero2_f<<<gGH, TPB>>>(gsum, gsq, G * H);
        k_gn_stats<<<gGN, 256>>>(y, batch, gsum, gsq);
        k_gn_fin<<<gGH, TPB>>>(gsum, gsq, cnt, gn_w, gn_b, gn_ms, kA, kB);
        k_gn_norm<<<gElems, TPB>>>(y, batch, kA, kB, res, dst);
    }

    // ---- fused tail (unchanged) ----
    k_tail<<<gRow128, 256, DYN_SMEM>>>(
        h1, h2, W_gate, b_gate, W_head, b_head, ln2_g, ln2_b,
        W_fc1, b_fc1, ln3_g, ln3_b, W_fc2, b_fc2, out, Nn);
}